// round 1
// baseline (speedup 1.0000x reference)
#include <cuda_runtime.h>
#include <math.h>
#include <stdint.h>

// ---------------------------------------------------------------------------
// Problem constants
// ---------------------------------------------------------------------------
#define BB   8
#define SS   512
#define HH   768
#define NHH  12
#define DHH  64
#define FFF  3072
#define MM   (BB * SS)          // 4096 rows of (B,S) flattened
#define LN_EPS 1e-3f

// ---------------------------------------------------------------------------
// Scratch (static device memory -- allocation-free per harness rules)
// ---------------------------------------------------------------------------
__device__ float g_q  [MM * HH];
__device__ float g_k  [MM * HH];
__device__ float g_v  [MM * HH];
__device__ float g_ctx[MM * HH];
__device__ float g_t1 [MM * HH];
__device__ float g_h1 [MM * HH];
__device__ float g_ff [MM * FFF];
__device__ float g_t2 [MM * HH];

// ---------------------------------------------------------------------------
// GEMM: C[M,N] = A[M,K] @ W[K,N] + bias, with optional epilogue
//   EPI = 0: none, 1: exact GELU, 2: += residual
// Tiles: BM=BN=128, BK=16, 256 threads, 8x8 microtile (2x2 of 4-wide halves).
// All shapes divide the tiles exactly (M=4096, N in {768,3072}, K in {768,3072}).
// ---------------------------------------------------------------------------
__device__ __forceinline__ float gelu_f(float x) {
    return 0.5f * x * (1.0f + erff(x * 0.70710678118654752f));
}

template <int EPI>
__global__ void __launch_bounds__(256) gemm_kernel(
    const float* __restrict__ A, const float* __restrict__ W,
    const float* __restrict__ bias, const float* __restrict__ resid,
    float* __restrict__ C, int M, int N, int K)
{
    __shared__ float As[16][132];   // A tile stored transposed: As[k][m]
    __shared__ float Bs[16][128];   // Bs[k][n]

    const int bn = blockIdx.x;
    const int bm = blockIdx.y;
    const int t  = threadIdx.x;
    const int tx = t & 15;          // 0..15  -> N microtile
    const int ty = t >> 4;          // 0..15  -> M microtile

    const float* Ablk = A + (size_t)bm * 128 * K;
    const float* Wblk = W + (size_t)bn * 128;

    float acc[8][8];
#pragma unroll
    for (int i = 0; i < 8; i++)
#pragma unroll
        for (int j = 0; j < 8; j++) acc[i][j] = 0.f;

    const int arow = t >> 2;        // 0..63
    const int aq   = t & 3;         // which float4 in the 16-wide k slice

    for (int kt = 0; kt < K; kt += 16) {
        // --- load A tile (128 x 16), store transposed ---
#pragma unroll
        for (int v = 0; v < 2; v++) {
            const int r = arow + v * 64;
            float4 a4 = *(const float4*)(Ablk + (size_t)r * K + kt + aq * 4);
            As[aq * 4 + 0][r] = a4.x;
            As[aq * 4 + 1][r] = a4.y;
            As[aq * 4 + 2][r] = a4.z;
            As[aq * 4 + 3][r] = a4.w;
        }
        // --- load B tile (16 x 128) ---
#pragma unroll
        for (int v = 0; v < 2; v++) {
            const int fidx = t + v * 256;
            const int r  = fidx >> 5;       // 0..15
            const int c4 = fidx & 31;       // 0..31
            *(float4*)&Bs[r][c4 * 4] =
                *(const float4*)(Wblk + (size_t)(kt + r) * N + c4 * 4);
        }
        __syncthreads();

#pragma unroll
        for (int kk = 0; kk < 16; kk++) {
            float af[8], bf[8];
            *(float4*)&af[0] = *(float4*)&As[kk][ty * 4];
            *(float4*)&af[4] = *(float4*)&As[kk][64 + ty * 4];
            *(float4*)&bf[0] = *(float4*)&Bs[kk][tx * 4];
            *(float4*)&bf[4] = *(float4*)&Bs[kk][64 + tx * 4];
#pragma unroll
            for (int i = 0; i < 8; i++)
#pragma unroll
                for (int j = 0; j < 8; j++)
                    acc[i][j] = fmaf(af[i], bf[j], acc[i][j]);
        }
        __syncthreads();
    }

    // --- epilogue ---
#pragma unroll
    for (int ih = 0; ih < 2; ih++) {
#pragma unroll
        for (int ii = 0; ii < 4; ii++) {
            const int r = bm * 128 + ih * 64 + ty * 4 + ii;
            const size_t rowoff = (size_t)r * N;
#pragma unroll
            for (int jh = 0; jh < 2; jh++) {
                const int c = bn * 128 + jh * 64 + tx * 4;
                float o[4];
#pragma unroll
                for (int jj = 0; jj < 4; jj++) {
                    float vv = acc[ih * 4 + ii][jh * 4 + jj] + bias[c + jj];
                    if (EPI == 1) vv = gelu_f(vv);
                    if (EPI == 2) vv += resid[rowoff + c + jj];
                    o[jj] = vv;
                }
                *(float4*)&C[rowoff + c] = *(const float4*)o;
            }
        }
    }
}

// ---------------------------------------------------------------------------
// Flash-style attention.
// grid: (S/64, B*NH). block: 256. Each block: 64 query rows of one head.
// Q/K/V stored as [B*S, H] row-major; head h occupies cols [h*64, h*64+64).
// Dynamic smem: Qs,Ks,Vs,Ps each 64x65 + 3 stat arrays of 64.
// ---------------------------------------------------------------------------
#define ALD 65
#define ATT_SMEM_BYTES ((4 * 64 * ALD + 3 * 64) * (int)sizeof(float))

__global__ void __launch_bounds__(256) attn_kernel(
    const float* __restrict__ Q, const float* __restrict__ Kx,
    const float* __restrict__ V, const int* __restrict__ mask,
    float* __restrict__ O)
{
    extern __shared__ float sm[];
    float* Qs  = sm;
    float* Ks  = Qs + 64 * ALD;
    float* Vs  = Ks + 64 * ALD;
    float* Ps  = Vs + 64 * ALD;
    float* m_s = Ps + 64 * ALD;
    float* l_s = m_s + 64;
    float* scl = l_s + 64;

    const int qt = blockIdx.x;          // query tile 0..7
    const int bh = blockIdx.y;          // 0..95
    const int b  = bh / NHH;
    const int h  = bh % NHH;

    const int t  = threadIdx.x;
    const int tx = t & 15;
    const int ty = t >> 4;

    const size_t base = (size_t)b * SS * HH + (size_t)h * DHH;

    // load Q tile
#pragma unroll
    for (int v = 0; v < 4; v++) {
        const int fidx = t + v * 256;       // 0..1023
        const int r  = fidx >> 4;           // 0..63
        const int c4 = fidx & 15;           // 0..15
        float4 q4 = *(const float4*)(Q + base + (size_t)(qt * 64 + r) * HH + c4 * 4);
        Qs[r * ALD + c4 * 4 + 0] = q4.x;
        Qs[r * ALD + c4 * 4 + 1] = q4.y;
        Qs[r * ALD + c4 * 4 + 2] = q4.z;
        Qs[r * ALD + c4 * 4 + 3] = q4.w;
    }
    if (t < 64) { m_s[t] = -1e30f; l_s[t] = 0.f; }

    float oacc[4][4];
#pragma unroll
    for (int i = 0; i < 4; i++)
#pragma unroll
        for (int j = 0; j < 4; j++) oacc[i][j] = 0.f;

    __syncthreads();

    for (int ktile = 0; ktile < SS / 64; ktile++) {
        // load K and V tiles
#pragma unroll
        for (int v = 0; v < 4; v++) {
            const int fidx = t + v * 256;
            const int r  = fidx >> 4;
            const int c4 = fidx & 15;
            const size_t gidx = base + (size_t)(ktile * 64 + r) * HH + c4 * 4;
            float4 k4 = *(const float4*)(Kx + gidx);
            Ks[r * ALD + c4 * 4 + 0] = k4.x;
            Ks[r * ALD + c4 * 4 + 1] = k4.y;
            Ks[r * ALD + c4 * 4 + 2] = k4.z;
            Ks[r * ALD + c4 * 4 + 3] = k4.w;
            float4 v4 = *(const float4*)(V + gidx);
            Vs[r * ALD + c4 * 4 + 0] = v4.x;
            Vs[r * ALD + c4 * 4 + 1] = v4.y;
            Vs[r * ALD + c4 * 4 + 2] = v4.z;
            Vs[r * ALD + c4 * 4 + 3] = v4.w;
        }
        __syncthreads();

        // scores: S = Qs @ Ks^T  (each thread 4x4)
        float sacc[4][4];
#pragma unroll
        for (int i = 0; i < 4; i++)
#pragma unroll
            for (int j = 0; j < 4; j++) sacc[i][j] = 0.f;

#pragma unroll 8
        for (int d = 0; d < 64; d++) {
            float qv[4], kv[4];
#pragma unroll
            for (int ii = 0; ii < 4; ii++) qv[ii] = Qs[(ty * 4 + ii) * ALD + d];
#pragma unroll
            for (int jj = 0; jj < 4; jj++) kv[jj] = Ks[(tx * 4 + jj) * ALD + d];
#pragma unroll
            for (int ii = 0; ii < 4; ii++)
#pragma unroll
                for (int jj = 0; jj < 4; jj++)
                    sacc[ii][jj] = fmaf(qv[ii], kv[jj], sacc[ii][jj]);
        }
        // scale + additive mask, write to Ps
#pragma unroll
        for (int jj = 0; jj < 4; jj++) {
            const int col = ktile * 64 + tx * 4 + jj;
            const float mk = (float)mask[b * SS + col];
            const float addm = (1.0f - mk) * -10000.0f;
#pragma unroll
            for (int ii = 0; ii < 4; ii++)
                Ps[(ty * 4 + ii) * ALD + tx * 4 + jj] = sacc[ii][jj] * 0.125f + addm;
        }
        __syncthreads();

        // online softmax per row (threads 0..63)
        if (t < 64) {
            const int r = t;
            float tm = -1e30f;
#pragma unroll 8
            for (int j = 0; j < 64; j++) tm = fmaxf(tm, Ps[r * ALD + j]);
            const float nm = fmaxf(m_s[r], tm);
            const float sc = __expf(m_s[r] - nm);
            float rs = 0.f;
#pragma unroll 8
            for (int j = 0; j < 64; j++) {
                const float p = __expf(Ps[r * ALD + j] - nm);
                Ps[r * ALD + j] = p;
                rs += p;
            }
            m_s[r] = nm;
            scl[r] = sc;
            l_s[r] = l_s[r] * sc + rs;
        }
        __syncthreads();

        // O = O*scale + P @ V
        float f[4];
#pragma unroll
        for (int ii = 0; ii < 4; ii++) f[ii] = scl[ty * 4 + ii];
#pragma unroll
        for (int ii = 0; ii < 4; ii++)
#pragma unroll
            for (int jj = 0; jj < 4; jj++) oacc[ii][jj] *= f[ii];

#pragma unroll 8
        for (int j = 0; j < 64; j++) {
            float pv[4], vv[4];
#pragma unroll
            for (int ii = 0; ii < 4; ii++) pv[ii] = Ps[(ty * 4 + ii) * ALD + j];
#pragma unroll
            for (int jj = 0; jj < 4; jj++) vv[jj] = Vs[j * ALD + tx * 4 + jj];
#pragma unroll
            for (int ii = 0; ii < 4; ii++)
#pragma unroll
                for (int jj = 0; jj < 4; jj++)
                    oacc[ii][jj] = fmaf(pv[ii], vv[jj], oacc[ii][jj]);
        }
        __syncthreads();
    }

    // normalize and write ctx (layout [B*S, H])
#pragma unroll
    for (int ii = 0; ii < 4; ii++) {
        const float inv = 1.0f / l_s[ty * 4 + ii];
        const int row = qt * 64 + ty * 4 + ii;
        float* op = O + (size_t)(b * SS + row) * HH + h * DHH + tx * 4;
        float o4[4];
#pragma unroll
        for (int jj = 0; jj < 4; jj++) o4[jj] = oacc[ii][jj] * inv;
        *(float4*)op = *(const float4*)o4;
    }
}

// ---------------------------------------------------------------------------
// Row-wise LayerNorm (H=768): one block / row, 256 threads (3 cols/thread).
// ---------------------------------------------------------------------------
__global__ void __launch_bounds__(256) ln_kernel(
    const float* __restrict__ X, const float* __restrict__ gg,
    const float* __restrict__ bb, float* __restrict__ Y)
{
    const int row = blockIdx.x;
    const float* x = X + (size_t)row * HH;
    const int c = threadIdx.x;

    const float v0 = x[c];
    const float v1 = x[c + 256];
    const float v2 = x[c + 512];
    float s  = v0 + v1 + v2;
    float s2 = v0 * v0 + v1 * v1 + v2 * v2;

    __shared__ float sa[8], sb[8];
    __shared__ float stats[2];
    const int lane = threadIdx.x & 31, w = threadIdx.x >> 5;
#pragma unroll
    for (int o = 16; o > 0; o >>= 1) {
        s  += __shfl_down_sync(0xffffffffu, s, o);
        s2 += __shfl_down_sync(0xffffffffu, s2, o);
    }
    if (lane == 0) { sa[w] = s; sb[w] = s2; }
    __syncthreads();
    if (threadIdx.x == 0) {
        float ts = 0.f, ts2 = 0.f;
#pragma unroll
        for (int i = 0; i < 8; i++) { ts += sa[i]; ts2 += sb[i]; }
        const float mu  = ts * (1.0f / HH);
        const float var = ts2 * (1.0f / HH) - mu * mu;
        stats[0] = mu;
        stats[1] = rsqrtf(var + LN_EPS);
    }
    __syncthreads();
    const float mu = stats[0], rstd = stats[1];
    float* y = Y + (size_t)row * HH;
    y[c]       = (v0 - mu) * rstd * gg[c]       + bb[c];
    y[c + 256] = (v1 - mu) * rstd * gg[c + 256] + bb[c + 256];
    y[c + 512] = (v2 - mu) * rstd * gg[c + 512] + bb[c + 512];
}

// ---------------------------------------------------------------------------
// Launch
// ---------------------------------------------------------------------------
extern "C" void kernel_launch(void* const* d_in, const int* in_sizes, int n_in,
                              void* d_out, int out_size)
{
    const float* x    = (const float*)d_in[0];
    const int*   mask = (const int*)  d_in[1];
    const float* Wq   = (const float*)d_in[2];
    const float* bq   = (const float*)d_in[3];
    const float* Wk   = (const float*)d_in[4];
    const float* bk   = (const float*)d_in[5];
    const float* Wv   = (const float*)d_in[6];
    const float* bv   = (const float*)d_in[7];
    const float* Wo   = (const float*)d_in[8];
    const float* bo   = (const float*)d_in[9];
    const float* ln1g = (const float*)d_in[10];
    const float* ln1b = (const float*)d_in[11];
    const float* W1   = (const float*)d_in[12];
    const float* b1   = (const float*)d_in[13];
    const float* W2   = (const float*)d_in[14];
    const float* b2   = (const float*)d_in[15];
    const float* ln2g = (const float*)d_in[16];
    const float* ln2b = (const float*)d_in[17];
    float* out = (float*)d_out;

    float *gq, *gk, *gv, *gctx, *gt1, *gh1, *gff, *gt2;
    cudaGetSymbolAddress((void**)&gq,   g_q);
    cudaGetSymbolAddress((void**)&gk,   g_k);
    cudaGetSymbolAddress((void**)&gv,   g_v);
    cudaGetSymbolAddress((void**)&gctx, g_ctx);
    cudaGetSymbolAddress((void**)&gt1,  g_t1);
    cudaGetSymbolAddress((void**)&gh1,  g_h1);
    cudaGetSymbolAddress((void**)&gff,  g_ff);
    cudaGetSymbolAddress((void**)&gt2,  g_t2);

    cudaFuncSetAttribute(attn_kernel,
                         cudaFuncAttributeMaxDynamicSharedMemorySize,
                         ATT_SMEM_BYTES);

    const dim3 blk(256);

    // QKV projections: [4096,768] @ [768,768]
    {
        dim3 grid(HH / 128, MM / 128);
        gemm_kernel<0><<<grid, blk>>>(x, Wq, bq, nullptr, gq, MM, HH, HH);
        gemm_kernel<0><<<grid, blk>>>(x, Wk, bk, nullptr, gk, MM, HH, HH);
        gemm_kernel<0><<<grid, blk>>>(x, Wv, bv, nullptr, gv, MM, HH, HH);
    }

    // attention -> ctx
    {
        dim3 grid(SS / 64, BB * NHH);
        attn_kernel<<<grid, blk, ATT_SMEM_BYTES>>>(gq, gk, gv, mask, gctx);
    }

    // attn_out = ctx @ Wo + bo + x
    {
        dim3 grid(HH / 128, MM / 128);
        gemm_kernel<2><<<grid, blk>>>(gctx, Wo, bo, x, gt1, MM, HH, HH);
    }
    // h1 = LN(t1)
    ln_kernel<<<MM, blk>>>(gt1, ln1g, ln1b, gh1);

    // ff = gelu(h1 @ W1 + b1)
    {
        dim3 grid(FFF / 128, MM / 128);
        gemm_kernel<1><<<grid, blk>>>(gh1, W1, b1, nullptr, gff, MM, FFF, HH);
    }
    // t2 = ff @ W2 + b2 + h1
    {
        dim3 grid(HH / 128, MM / 128);
        gemm_kernel<2><<<grid, blk>>>(gff, W2, b2, gh1, gt2, MM, HH, FFF);
    }
    // out = LN(t2)
    ln_kernel<<<MM, blk>>>(gt2, ln2g, ln2b, out);
}

// round 3
// speedup vs baseline: 2.0132x; 2.0132x over previous
#include <cuda_runtime.h>
#include <cuda_bf16.h>
#include <math.h>
#include <stdint.h>

// ---------------------------------------------------------------------------
// Problem constants
// ---------------------------------------------------------------------------
#define BB   8
#define SS   512
#define HH   768
#define NHH  12
#define DHH  64
#define FFF  3072
#define MM   (BB * SS)
#define LN_EPS 1e-3f

// ---------------------------------------------------------------------------
// Scratch (static device memory)
// ---------------------------------------------------------------------------
__device__ __align__(16) float g_qkv [MM * 3 * HH];   // fused Q|K|V, row stride 2304
__device__ __align__(16) float g_ctx [MM * HH];
__device__ __align__(16) float g_t1  [MM * HH];
__device__ __align__(16) float g_h1  [MM * HH];
__device__ __align__(16) float g_t2  [MM * HH];
__device__ __align__(16) __nv_bfloat16 g_ff_hi[MM * FFF];
__device__ __align__(16) __nv_bfloat16 g_ff_lo[MM * FFF];
__device__ __align__(16) float g_wqkv[3 * HH * HH];   // [2304][768] = (Wq|Wk|Wv)^T
__device__ __align__(16) float g_bqkv[3 * HH];
__device__ __align__(16) float g_wto [HH * HH];
__device__ __align__(16) float g_wt1 [FFF * HH];      // W1^T [3072][768]
__device__ __align__(16) float g_wt2 [HH * FFF];      // W2^T [768][3072]

// ---------------------------------------------------------------------------
// PTX wrappers: ldmatrix + bf16 mma.sync (arch-stable, works on sm_103 target)
// ---------------------------------------------------------------------------
__device__ __forceinline__ uint32_t smem_u32(const void* p) {
    uint32_t a;
    asm("{ .reg .u64 t; cvta.to.shared.u64 t, %1; cvt.u32.u64 %0, t; }"
        : "=r"(a) : "l"(p));
    return a;
}
#define LDM4(R, ADDR) \
    asm volatile("ldmatrix.sync.aligned.m8n8.x4.shared.b16 {%0,%1,%2,%3}, [%4];" \
        : "=r"((R)[0]), "=r"((R)[1]), "=r"((R)[2]), "=r"((R)[3]) : "r"(ADDR))
#define MMA16816(D, A, B0, B1) \
    asm volatile("mma.sync.aligned.m16n8k16.row.col.f32.bf16.bf16.f32 " \
        "{%0,%1,%2,%3}, {%4,%5,%6,%7}, {%8,%9}, {%0,%1,%2,%3};" \
        : "+f"((D)[0]), "+f"((D)[1]), "+f"((D)[2]), "+f"((D)[3]) \
        : "r"((A)[0]), "r"((A)[1]), "r"((A)[2]), "r"((A)[3]), "r"(B0), "r"(B1))

// ---------------------------------------------------------------------------
// Helpers
// ---------------------------------------------------------------------------
__device__ __forceinline__ float gelu_f(float x) {
    return 0.5f * x * (1.0f + erff(x * 0.70710678118654752f));
}
__device__ __forceinline__ void split_f4(float4 a, uint2& uh, uint2& ul) {
    __nv_bfloat162 h0 = __floats2bfloat162_rn(a.x, a.y);
    __nv_bfloat162 h1 = __floats2bfloat162_rn(a.z, a.w);
    float lx = a.x - __bfloat162float(h0.x);
    float ly = a.y - __bfloat162float(h0.y);
    float lz = a.z - __bfloat162float(h1.x);
    float lw = a.w - __bfloat162float(h1.y);
    __nv_bfloat162 l0 = __floats2bfloat162_rn(lx, ly);
    __nv_bfloat162 l1 = __floats2bfloat162_rn(lz, lw);
    uh.x = *(uint32_t*)&h0; uh.y = *(uint32_t*)&h1;
    ul.x = *(uint32_t*)&l0; ul.y = *(uint32_t*)&l1;
}

// ---------------------------------------------------------------------------
// Transpose: in [K,N] fp32 -> out [N,K] fp32
// ---------------------------------------------------------------------------
__global__ void __launch_bounds__(256) transpose_kernel(
    const float* __restrict__ in, float* __restrict__ out, int K, int N)
{
    __shared__ float tile[32][33];
    const int n0 = blockIdx.x * 32, k0 = blockIdx.y * 32;
    const int tx = threadIdx.x, ty = threadIdx.y;
#pragma unroll
    for (int j = 0; j < 32; j += 8)
        tile[ty + j][tx] = in[(size_t)(k0 + ty + j) * N + n0 + tx];
    __syncthreads();
#pragma unroll
    for (int j = 0; j < 32; j += 8)
        out[(size_t)(n0 + ty + j) * K + k0 + tx] = tile[tx][ty + j];
}

__global__ void concat3_kernel(const float* __restrict__ a, const float* __restrict__ b,
                               const float* __restrict__ c, float* __restrict__ o)
{
    const int i = blockIdx.x * 256 + threadIdx.x;
    if (i < HH) { o[i] = a[i]; o[HH + i] = b[i]; o[2 * HH + i] = c[i]; }
}

// ---------------------------------------------------------------------------
// Tensor-core GEMM via mma.sync bf16 hi/lo 3-term split.
//   C[M,Ntot] = A[M,K] @ Wt[Ntot,K]^T (+bias, epilogue)
//   EPI: 0 bias only (fp32), 1 bias+GELU -> bf16 hi/lo, 2 bias+resid (fp32)
//   ASRC: 0 A fp32 (split in kernel), 1 A pre-split bf16 hi/lo
// CTA 128x128, KC=32, 8 warps (warp 64x32), double-buffered smem,
// row stride 80B (conflict-free ldmatrix, no xor swizzle).
// ---------------------------------------------------------------------------
#define KC 32
#define ROWB 80                        // bytes per row (32 bf16 data + pad)
#define MATB (128 * ROWB)              // 10240 per matrix
#define STAGEB (4 * MATB)              // A_hi, A_lo, B_hi, B_lo
#define GSMEM_BYTES (2 * STAGEB)       // 81920

template <int EPI, int ASRC>
__global__ void __launch_bounds__(256) tc_gemm(
    const float* __restrict__ A,
    const __nv_bfloat16* __restrict__ Ahi, const __nv_bfloat16* __restrict__ Alo,
    const float* __restrict__ Wt, const float* __restrict__ bias,
    const float* __restrict__ resid,
    float* __restrict__ C,
    __nv_bfloat16* __restrict__ Chi, __nv_bfloat16* __restrict__ Clo,
    int K, int Ntot)
{
    extern __shared__ char sm[];
    const uint32_t sb = smem_u32(sm);

    const int t    = threadIdx.x;
    const int wid  = t >> 5, lane = t & 31;
    const int wm   = wid >> 2;          // 0..1
    const int wn   = wid & 3;           // 0..3
    const int bn   = blockIdx.x, bm = blockIdx.y;
    const int rbase = bm * 128, cbase = bn * 128;
    const int nch  = K / KC;

    // prefetch registers
    float4 pfa[4], pfb[4];
    uint4  pah[2], pal[2];

    // ldg indices (A fp32 / B fp32): idx = t + j*256 -> r = idx>>3, c4 = idx&7
    auto ldgA = [&](int ci) {
        const int kt = ci * KC;
        if (ASRC == 0) {
#pragma unroll
            for (int j = 0; j < 4; j++) {
                const int idx = t + j * 256;
                const int r = idx >> 3, c4 = idx & 7;
                pfa[j] = *(const float4*)(A + (size_t)(rbase + r) * K + kt + c4 * 4);
            }
        } else {
#pragma unroll
            for (int j = 0; j < 2; j++) {
                const int idx = t + j * 256;
                const int r = idx >> 2, c8 = idx & 3;
                const size_t g = (size_t)(rbase + r) * K + kt + c8 * 8;
                pah[j] = *(const uint4*)(Ahi + g);
                pal[j] = *(const uint4*)(Alo + g);
            }
        }
    };
    auto ldgB = [&](int ci) {
        const int kt = ci * KC;
#pragma unroll
        for (int j = 0; j < 4; j++) {
            const int idx = t + j * 256;
            const int r = idx >> 3, c4 = idx & 7;
            pfb[j] = *(const float4*)(Wt + (size_t)(cbase + r) * K + kt + c4 * 4);
        }
    };
    auto stsAB = [&](int s) {
        char* st = sm + s * STAGEB;
        if (ASRC == 0) {
#pragma unroll
            for (int j = 0; j < 4; j++) {
                const int idx = t + j * 256;
                const int r = idx >> 3, c4 = idx & 7;
                uint2 uh, ul;
                split_f4(pfa[j], uh, ul);
                *(uint2*)(st + r * ROWB + c4 * 8)        = uh;
                *(uint2*)(st + MATB + r * ROWB + c4 * 8) = ul;
            }
        } else {
#pragma unroll
            for (int j = 0; j < 2; j++) {
                const int idx = t + j * 256;
                const int r = idx >> 2, c8 = idx & 3;
                *(uint4*)(st + r * ROWB + c8 * 16)        = pah[j];
                *(uint4*)(st + MATB + r * ROWB + c8 * 16) = pal[j];
            }
        }
#pragma unroll
        for (int j = 0; j < 4; j++) {
            const int idx = t + j * 256;
            const int r = idx >> 3, c4 = idx & 7;
            uint2 uh, ul;
            split_f4(pfb[j], uh, ul);
            *(uint2*)(st + 2 * MATB + r * ROWB + c4 * 8) = uh;
            *(uint2*)(st + 3 * MATB + r * ROWB + c4 * 8) = ul;
        }
    };

    float acc[4][4][4];
#pragma unroll
    for (int i = 0; i < 4; i++)
#pragma unroll
        for (int j = 0; j < 4; j++)
#pragma unroll
            for (int q = 0; q < 4; q++) acc[i][j][q] = 0.f;

    // ldmatrix lane offsets
    const uint32_t a_off = (uint32_t)((wm * 64 + (lane & 15)) * ROWB + ((lane >> 4) << 4));
    const uint32_t b_off = (uint32_t)((wn * 32 + ((lane & 7) | ((lane & 16) >> 1))) * ROWB
                                      + (((lane >> 3) & 1) << 4));

    auto mma_chunk = [&](int s) {
        const uint32_t sA  = sb + s * STAGEB;
        const uint32_t sAl = sA + MATB;
        const uint32_t sBh = sA + 2 * MATB;
        const uint32_t sBl = sA + 3 * MATB;
#pragma unroll
        for (int ks = 0; ks < 2; ks++) {
            const uint32_t ko = ks * 32;
            uint32_t AH[4][4], AL[4][4], BH[2][4], BL[2][4];
#pragma unroll
            for (int mt = 0; mt < 4; mt++) {
                LDM4(AH[mt], sA  + a_off + mt * (16 * ROWB) + ko);
                LDM4(AL[mt], sAl + a_off + mt * (16 * ROWB) + ko);
            }
#pragma unroll
            for (int n2 = 0; n2 < 2; n2++) {
                LDM4(BH[n2], sBh + b_off + n2 * (16 * ROWB) + ko);
                LDM4(BL[n2], sBl + b_off + n2 * (16 * ROWB) + ko);
            }
#pragma unroll
            for (int mt = 0; mt < 4; mt++) {
#pragma unroll
                for (int nt = 0; nt < 4; nt++) {
                    const uint32_t bh0 = BH[nt >> 1][(nt & 1) * 2];
                    const uint32_t bh1 = BH[nt >> 1][(nt & 1) * 2 + 1];
                    const uint32_t bl0 = BL[nt >> 1][(nt & 1) * 2];
                    const uint32_t bl1 = BL[nt >> 1][(nt & 1) * 2 + 1];
                    MMA16816(acc[mt][nt], AH[mt], bh0, bh1);
                    MMA16816(acc[mt][nt], AH[mt], bl0, bl1);
                    MMA16816(acc[mt][nt], AL[mt], bh0, bh1);
                }
            }
        }
    };

    // pipeline
    ldgA(0); ldgB(0);
    stsAB(0);
    __syncthreads();
    for (int ci = 0; ci < nch; ci++) {
        const int s = ci & 1;
        if (ci + 1 < nch) { ldgA(ci + 1); ldgB(ci + 1); }
        mma_chunk(s);
        __syncthreads();
        if (ci + 1 < nch) { stsAB(s ^ 1); __syncthreads(); }
    }

    // epilogue: acc[mt][nt]: rows m = rbase+wm*64+mt*16+(lane>>2)(+8),
    //           cols n = cbase+wn*32+nt*8+(lane&3)*2
    const int mrow0 = rbase + wm * 64 + (lane >> 2);
    const int ncol0 = cbase + wn * 32 + (lane & 3) * 2;
#pragma unroll
    for (int mt = 0; mt < 4; mt++) {
#pragma unroll
        for (int half = 0; half < 2; half++) {
            const int m = mrow0 + mt * 16 + half * 8;
            const size_t rowoff = (size_t)m * Ntot;
#pragma unroll
            for (int nt = 0; nt < 4; nt++) {
                const int n = ncol0 + nt * 8;
                float v0 = acc[mt][nt][half * 2 + 0];
                float v1 = acc[mt][nt][half * 2 + 1];
                const float2 bv = *(const float2*)(bias + n);
                v0 += bv.x; v1 += bv.y;
                if (EPI == 2) {
                    const float2 rv = *(const float2*)(resid + rowoff + n);
                    v0 += rv.x; v1 += rv.y;
                }
                if (EPI == 1) {
                    v0 = gelu_f(v0); v1 = gelu_f(v1);
                    __nv_bfloat162 h = __floats2bfloat162_rn(v0, v1);
                    float l0 = v0 - __bfloat162float(h.x);
                    float l1 = v1 - __bfloat162float(h.y);
                    __nv_bfloat162 l = __floats2bfloat162_rn(l0, l1);
                    *(__nv_bfloat162*)(Chi + rowoff + n) = h;
                    *(__nv_bfloat162*)(Clo + rowoff + n) = l;
                } else {
                    *(float2*)(C + rowoff + n) = make_float2(v0, v1);
                }
            }
        }
    }
}

// ---------------------------------------------------------------------------
// Flash-style attention (fp32 SIMT), QKV read with row stride ST
// ---------------------------------------------------------------------------
#define ALD 65
#define ATT_SMEM_BYTES ((4 * 64 * ALD + 3 * 64) * (int)sizeof(float))

__global__ void __launch_bounds__(256) attn_kernel(
    const float* __restrict__ Q, const float* __restrict__ Kx,
    const float* __restrict__ V, const int* __restrict__ mask,
    float* __restrict__ O, int ST)
{
    extern __shared__ float smf[];
    float* Qs  = smf;
    float* Ks  = Qs + 64 * ALD;
    float* Vs  = Ks + 64 * ALD;
    float* Ps  = Vs + 64 * ALD;
    float* m_s = Ps + 64 * ALD;
    float* l_s = m_s + 64;
    float* scl = l_s + 64;

    const int qt = blockIdx.x;
    const int bh = blockIdx.y;
    const int b  = bh / NHH;
    const int h  = bh % NHH;

    const int t  = threadIdx.x;
    const int tx = t & 15;
    const int ty = t >> 4;

    const size_t base = (size_t)b * SS * ST + (size_t)h * DHH;

#pragma unroll
    for (int v = 0; v < 4; v++) {
        const int fidx = t + v * 256;
        const int r  = fidx >> 4;
        const int c4 = fidx & 15;
        float4 q4 = *(const float4*)(Q + base + (size_t)(qt * 64 + r) * ST + c4 * 4);
        Qs[r * ALD + c4 * 4 + 0] = q4.x;
        Qs[r * ALD + c4 * 4 + 1] = q4.y;
        Qs[r * ALD + c4 * 4 + 2] = q4.z;
        Qs[r * ALD + c4 * 4 + 3] = q4.w;
    }
    if (t < 64) { m_s[t] = -1e30f; l_s[t] = 0.f; }

    float oacc[4][4];
#pragma unroll
    for (int i = 0; i < 4; i++)
#pragma unroll
        for (int j = 0; j < 4; j++) oacc[i][j] = 0.f;

    __syncthreads();

    for (int ktile = 0; ktile < SS / 64; ktile++) {
#pragma unroll
        for (int v = 0; v < 4; v++) {
            const int fidx = t + v * 256;
            const int r  = fidx >> 4;
            const int c4 = fidx & 15;
            const size_t gidx = base + (size_t)(ktile * 64 + r) * ST + c4 * 4;
            float4 k4 = *(const float4*)(Kx + gidx);
            Ks[r * ALD + c4 * 4 + 0] = k4.x;
            Ks[r * ALD + c4 * 4 + 1] = k4.y;
            Ks[r * ALD + c4 * 4 + 2] = k4.z;
            Ks[r * ALD + c4 * 4 + 3] = k4.w;
            float4 v4 = *(const float4*)(V + gidx);
            Vs[r * ALD + c4 * 4 + 0] = v4.x;
            Vs[r * ALD + c4 * 4 + 1] = v4.y;
            Vs[r * ALD + c4 * 4 + 2] = v4.z;
            Vs[r * ALD + c4 * 4 + 3] = v4.w;
        }
        __syncthreads();

        float sacc[4][4];
#pragma unroll
        for (int i = 0; i < 4; i++)
#pragma unroll
            for (int j = 0; j < 4; j++) sacc[i][j] = 0.f;

#pragma unroll 8
        for (int d = 0; d < 64; d++) {
            float qv[4], kv[4];
#pragma unroll
            for (int ii = 0; ii < 4; ii++) qv[ii] = Qs[(ty * 4 + ii) * ALD + d];
#pragma unroll
            for (int jj = 0; jj < 4; jj++) kv[jj] = Ks[(tx * 4 + jj) * ALD + d];
#pragma unroll
            for (int ii = 0; ii < 4; ii++)
#pragma unroll
                for (int jj = 0; jj < 4; jj++)
                    sacc[ii][jj] = fmaf(qv[ii], kv[jj], sacc[ii][jj]);
        }
#pragma unroll
        for (int jj = 0; jj < 4; jj++) {
            const int col = ktile * 64 + tx * 4 + jj;
            const float mk = (float)mask[b * SS + col];
            const float addm = (1.0f - mk) * -10000.0f;
#pragma unroll
            for (int ii = 0; ii < 4; ii++)
                Ps[(ty * 4 + ii) * ALD + tx * 4 + jj] = sacc[ii][jj] * 0.125f + addm;
        }
        __syncthreads();

        if (t < 64) {
            const int r = t;
            float tm = -1e30f;
#pragma unroll 8
            for (int j = 0; j < 64; j++) tm = fmaxf(tm, Ps[r * ALD + j]);
            const float nm = fmaxf(m_s[r], tm);
            const float sc = __expf(m_s[r] - nm);
            float rs = 0.f;
#pragma unroll 8
            for (int j = 0; j < 64; j++) {
                const float p = __expf(Ps[r * ALD + j] - nm);
                Ps[r * ALD + j] = p;
                rs += p;
            }
            m_s[r] = nm;
            scl[r] = sc;
            l_s[r] = l_s[r] * sc + rs;
        }
        __syncthreads();

        float f[4];
#pragma unroll
        for (int ii = 0; ii < 4; ii++) f[ii] = scl[ty * 4 + ii];
#pragma unroll
        for (int ii = 0; ii < 4; ii++)
#pragma unroll
            for (int jj = 0; jj < 4; jj++) oacc[ii][jj] *= f[ii];

#pragma unroll 8
        for (int j = 0; j < 64; j++) {
            float pv[4], vv[4];
#pragma unroll
            for (int ii = 0; ii < 4; ii++) pv[ii] = Ps[(ty * 4 + ii) * ALD + j];
#pragma unroll
            for (int jj = 0; jj < 4; jj++) vv[jj] = Vs[j * ALD + tx * 4 + jj];
#pragma unroll
            for (int ii = 0; ii < 4; ii++)
#pragma unroll
                for (int jj = 0; jj < 4; jj++)
                    oacc[ii][jj] = fmaf(pv[ii], vv[jj], oacc[ii][jj]);
        }
        __syncthreads();
    }

#pragma unroll
    for (int ii = 0; ii < 4; ii++) {
        const float inv = 1.0f / l_s[ty * 4 + ii];
        const int row = qt * 64 + ty * 4 + ii;
        float* op = O + (size_t)(b * SS + row) * HH + h * DHH + tx * 4;
        float o4[4];
#pragma unroll
        for (int jj = 0; jj < 4; jj++) o4[jj] = oacc[ii][jj] * inv;
        *(float4*)op = *(const float4*)o4;
    }
}

// ---------------------------------------------------------------------------
// Row-wise LayerNorm
// ---------------------------------------------------------------------------
__global__ void __launch_bounds__(256) ln_kernel(
    const float* __restrict__ X, const float* __restrict__ gg,
    const float* __restrict__ bb, float* __restrict__ Y)
{
    const int row = blockIdx.x;
    const float* x = X + (size_t)row * HH;
    const int c = threadIdx.x;

    const float v0 = x[c];
    const float v1 = x[c + 256];
    const float v2 = x[c + 512];
    float s  = v0 + v1 + v2;
    float s2 = v0 * v0 + v1 * v1 + v2 * v2;

    __shared__ float sa[8], sb2[8];
    __shared__ float stats[2];
    const int lane = threadIdx.x & 31, w = threadIdx.x >> 5;
#pragma unroll
    for (int o = 16; o > 0; o >>= 1) {
        s  += __shfl_down_sync(0xffffffffu, s, o);
        s2 += __shfl_down_sync(0xffffffffu, s2, o);
    }
    if (lane == 0) { sa[w] = s; sb2[w] = s2; }
    __syncthreads();
    if (threadIdx.x == 0) {
        float ts = 0.f, ts2 = 0.f;
#pragma unroll
        for (int i = 0; i < 8; i++) { ts += sa[i]; ts2 += sb2[i]; }
        const float mu  = ts * (1.0f / HH);
        const float var = ts2 * (1.0f / HH) - mu * mu;
        stats[0] = mu;
        stats[1] = rsqrtf(var + LN_EPS);
    }
    __syncthreads();
    const float mu = stats[0], rstd = stats[1];
    float* y = Y + (size_t)row * HH;
    y[c]       = (v0 - mu) * rstd * gg[c]       + bb[c];
    y[c + 256] = (v1 - mu) * rstd * gg[c + 256] + bb[c + 256];
    y[c + 512] = (v2 - mu) * rstd * gg[c + 512] + bb[c + 512];
}

// ---------------------------------------------------------------------------
// Launch
// ---------------------------------------------------------------------------
extern "C" void kernel_launch(void* const* d_in, const int* in_sizes, int n_in,
                              void* d_out, int out_size)
{
    (void)in_sizes; (void)n_in; (void)out_size;
    const float* x    = (const float*)d_in[0];
    const int*   mask = (const int*)  d_in[1];
    const float* Wq   = (const float*)d_in[2];
    const float* bq   = (const float*)d_in[3];
    const float* Wk   = (const float*)d_in[4];
    const float* bk   = (const float*)d_in[5];
    const float* Wv   = (const float*)d_in[6];
    const float* bv   = (const float*)d_in[7];
    const float* Wo   = (const float*)d_in[8];
    const float* bo   = (const float*)d_in[9];
    const float* ln1g = (const float*)d_in[10];
    const float* ln1b = (const float*)d_in[11];
    const float* W1   = (const float*)d_in[12];
    const float* b1   = (const float*)d_in[13];
    const float* W2   = (const float*)d_in[14];
    const float* b2   = (const float*)d_in[15];
    const float* ln2g = (const float*)d_in[16];
    const float* ln2b = (const float*)d_in[17];
    float* out = (float*)d_out;

    float *gqkv, *gctx, *gt1, *gh1, *gt2;
    float *gwqkv, *gbqkv, *gwto, *gwt1, *gwt2;
    __nv_bfloat16 *gffh, *gffl;
    cudaGetSymbolAddress((void**)&gqkv,  g_qkv);
    cudaGetSymbolAddress((void**)&gctx,  g_ctx);
    cudaGetSymbolAddress((void**)&gt1,   g_t1);
    cudaGetSymbolAddress((void**)&gh1,   g_h1);
    cudaGetSymbolAddress((void**)&gt2,   g_t2);
    cudaGetSymbolAddress((void**)&gffh,  g_ff_hi);
    cudaGetSymbolAddress((void**)&gffl,  g_ff_lo);
    cudaGetSymbolAddress((void**)&gwqkv, g_wqkv);
    cudaGetSymbolAddress((void**)&gbqkv, g_bqkv);
    cudaGetSymbolAddress((void**)&gwto,  g_wto);
    cudaGetSymbolAddress((void**)&gwt1,  g_wt1);
    cudaGetSymbolAddress((void**)&gwt2,  g_wt2);

    cudaFuncSetAttribute(attn_kernel,
                         cudaFuncAttributeMaxDynamicSharedMemorySize, ATT_SMEM_BYTES);
    cudaFuncSetAttribute(tc_gemm<0, 0>,
                         cudaFuncAttributeMaxDynamicSharedMemorySize, GSMEM_BYTES);
    cudaFuncSetAttribute(tc_gemm<1, 0>,
                         cudaFuncAttributeMaxDynamicSharedMemorySize, GSMEM_BYTES);
    cudaFuncSetAttribute(tc_gemm<2, 0>,
                         cudaFuncAttributeMaxDynamicSharedMemorySize, GSMEM_BYTES);
    cudaFuncSetAttribute(tc_gemm<2, 1>,
                         cudaFuncAttributeMaxDynamicSharedMemorySize, GSMEM_BYTES);

    const dim3 tb(32, 8);

    // Weight prep: (Wq|Wk|Wv)^T fused, Wo^T, W1^T, W2^T, bias concat
    transpose_kernel<<<dim3(HH / 32,  HH / 32),  tb>>>(Wq, gwqkv,                gwto ? HH : HH, HH);
    transpose_kernel<<<dim3(HH / 32,  HH / 32),  tb>>>(Wk, gwqkv + HH * HH,      HH, HH);
    transpose_kernel<<<dim3(HH / 32,  HH / 32),  tb>>>(Wv, gwqkv + 2 * HH * HH,  HH, HH);
    transpose_kernel<<<dim3(HH / 32,  HH / 32),  tb>>>(Wo, gwto, HH, HH);
    transpose_kernel<<<dim3(FFF / 32, HH / 32),  tb>>>(W1, gwt1, HH, FFF);
    transpose_kernel<<<dim3(HH / 32,  FFF / 32), tb>>>(W2, gwt2, FFF, HH);
    concat3_kernel<<<3, 256>>>(bq, bk, bv, gbqkv);

    // Fused QKV: [4096,768] @ [768,2304]
    tc_gemm<0, 0><<<dim3(3 * HH / 128, MM / 128), 256, GSMEM_BYTES>>>(
        x, nullptr, nullptr, gwqkv, gbqkv, nullptr, gqkv, nullptr, nullptr, HH, 3 * HH);

    // attention (reads fused buffer with stride 2304)
    attn_kernel<<<dim3(SS / 64, BB * NHH), 256, ATT_SMEM_BYTES>>>(
        gqkv, gqkv + HH, gqkv + 2 * HH, mask, gctx, 3 * HH);

    // t1 = ctx @ Wo + bo + x
    tc_gemm<2, 0><<<dim3(HH / 128, MM / 128), 256, GSMEM_BYTES>>>(
        gctx, nullptr, nullptr, gwto, bo, x, gt1, nullptr, nullptr, HH, HH);
    ln_kernel<<<MM, 256>>>(gt1, ln1g, ln1b, gh1);

    // ff = gelu(h1 @ W1 + b1) -> bf16 hi/lo
    tc_gemm<1, 0><<<dim3(FFF / 128, MM / 128), 256, GSMEM_BYTES>>>(
        gh1, nullptr, nullptr, gwt1, b1, nullptr, nullptr, gffh, gffl, HH, FFF);

    // t2 = ff @ W2 + b2 + h1
    tc_gemm<2, 1><<<dim3(HH / 128, MM / 128), 256, GSMEM_BYTES>>>(
        nullptr, gffh, gffl, gwt2, b2, gh1, gt2, nullptr, nullptr, FFF, HH);
    ln_kernel<<<MM, 256>>>(gt2, ln2g, ln2b, out);
}

// round 5
// speedup vs baseline: 2.3956x; 1.1900x over previous
#include <cuda_runtime.h>
#include <cuda_bf16.h>
#include <math.h>
#include <stdint.h>

#define BB   8
#define SS   512
#define HH   768
#define NHH  12
#define DHH  64
#define FFF  3072
#define MM   (BB * SS)
#define LN_EPS 1e-3f

// ---------------------------------------------------------------------------
// Scratch
// ---------------------------------------------------------------------------
__device__ __align__(16) __nv_bfloat16 g_xh  [MM * HH];
__device__ __align__(16) __nv_bfloat16 g_xl  [MM * HH];
__device__ __align__(16) __nv_bfloat16 g_qkvh[MM * 3 * HH];
__device__ __align__(16) __nv_bfloat16 g_qkvl[MM * 3 * HH];
__device__ __align__(16) __nv_bfloat16 g_ctxh[MM * HH];
__device__ __align__(16) __nv_bfloat16 g_ctxl[MM * HH];
__device__ __align__(16) float g_t1 [MM * HH];
__device__ __align__(16) float g_h1 [MM * HH];
__device__ __align__(16) __nv_bfloat16 g_h1h[MM * HH];
__device__ __align__(16) __nv_bfloat16 g_h1l[MM * HH];
__device__ __align__(16) __nv_bfloat16 g_ffh[MM * FFF];
__device__ __align__(16) __nv_bfloat16 g_ffl[MM * FFF];
__device__ __align__(16) float g_t2 [MM * HH];
__device__ __align__(16) __nv_bfloat16 g_wqkvh[3 * HH * HH];
__device__ __align__(16) __nv_bfloat16 g_wqkvl[3 * HH * HH];
__device__ __align__(16) float g_bqkv[3 * HH];
__device__ __align__(16) __nv_bfloat16 g_woh[HH * HH];
__device__ __align__(16) __nv_bfloat16 g_wol[HH * HH];
__device__ __align__(16) __nv_bfloat16 g_w1h[FFF * HH];
__device__ __align__(16) __nv_bfloat16 g_w1l[FFF * HH];
__device__ __align__(16) __nv_bfloat16 g_w2h[HH * FFF];
__device__ __align__(16) __nv_bfloat16 g_w2l[HH * FFF];

// ---------------------------------------------------------------------------
// PTX wrappers
// ---------------------------------------------------------------------------
__device__ __forceinline__ uint32_t smem_u32(const void* p) {
    uint32_t a;
    asm("{ .reg .u64 t; cvta.to.shared.u64 t, %1; cvt.u32.u64 %0, t; }"
        : "=r"(a) : "l"(p));
    return a;
}
#define LDM4(R, ADDR) \
    asm volatile("ldmatrix.sync.aligned.m8n8.x4.shared.b16 {%0,%1,%2,%3}, [%4];" \
        : "=r"((R)[0]), "=r"((R)[1]), "=r"((R)[2]), "=r"((R)[3]) : "r"(ADDR))
#define LDM4T(R, ADDR) \
    asm volatile("ldmatrix.sync.aligned.m8n8.x4.trans.shared.b16 {%0,%1,%2,%3}, [%4];" \
        : "=r"((R)[0]), "=r"((R)[1]), "=r"((R)[2]), "=r"((R)[3]) : "r"(ADDR))
#define MMA16816(D, A, B0, B1) \
    asm volatile("mma.sync.aligned.m16n8k16.row.col.f32.bf16.bf16.f32 " \
        "{%0,%1,%2,%3}, {%4,%5,%6,%7}, {%8,%9}, {%0,%1,%2,%3};" \
        : "+f"((D)[0]), "+f"((D)[1]), "+f"((D)[2]), "+f"((D)[3]) \
        : "r"((A)[0]), "r"((A)[1]), "r"((A)[2]), "r"((A)[3]), "r"(B0), "r"(B1))
#define CP16(SADDR, GPTR) \
    asm volatile("cp.async.cg.shared.global [%0], [%1], 16;" \
        :: "r"(SADDR), "l"(GPTR))
#define CP_COMMIT() asm volatile("cp.async.commit_group;" ::: "memory")
#define CP_WAIT(N)  asm volatile("cp.async.wait_group %0;" :: "n"(N) : "memory")

__device__ __forceinline__ float gelu_f(float x) {
    return 0.5f * x * (1.0f + erff(x * 0.70710678118654752f));
}
__device__ __forceinline__ void split2(float v0, float v1, uint32_t& uh, uint32_t& ul) {
    __nv_bfloat162 h = __floats2bfloat162_rn(v0, v1);
    float l0 = v0 - __bfloat162float(h.x);
    float l1 = v1 - __bfloat162float(h.y);
    __nv_bfloat162 l = __floats2bfloat162_rn(l0, l1);
    uh = *(uint32_t*)&h; ul = *(uint32_t*)&l;
}

// ---------------------------------------------------------------------------
// Prep kernels
// ---------------------------------------------------------------------------
__global__ void __launch_bounds__(256) trans_split_kernel(
    const float* __restrict__ in, __nv_bfloat16* __restrict__ oh,
    __nv_bfloat16* __restrict__ ol, int K, int N)
{
    __shared__ float tile[32][33];
    const int n0 = blockIdx.x * 32, k0 = blockIdx.y * 32;
    const int tx = threadIdx.x, ty = threadIdx.y;
#pragma unroll
    for (int j = 0; j < 32; j += 8)
        tile[ty + j][tx] = in[(size_t)(k0 + ty + j) * N + n0 + tx];
    __syncthreads();
#pragma unroll
    for (int j = 0; j < 32; j += 8) {
        const float v = tile[tx][ty + j];
        const __nv_bfloat16 h = __float2bfloat16_rn(v);
        const __nv_bfloat16 l = __float2bfloat16_rn(v - __bfloat162float(h));
        const size_t o = (size_t)(n0 + ty + j) * K + k0 + tx;
        oh[o] = h; ol[o] = l;
    }
}

__global__ void __launch_bounds__(256) split_kernel(
    const float* __restrict__ in, __nv_bfloat16* __restrict__ oh,
    __nv_bfloat16* __restrict__ ol, int n)
{
    const int i = blockIdx.x * 256 + threadIdx.x;
    if (i < n) {
        const float v = in[i];
        const __nv_bfloat16 h = __float2bfloat16_rn(v);
        oh[i] = h;
        ol[i] = __float2bfloat16_rn(v - __bfloat162float(h));
    }
}

__global__ void concat3_kernel(const float* __restrict__ a, const float* __restrict__ b,
                               const float* __restrict__ c, float* __restrict__ o)
{
    const int i = blockIdx.x * 256 + threadIdx.x;
    if (i < HH) { o[i] = a[i]; o[HH + i] = b[i]; o[2 * HH + i] = c[i]; }
}

// ---------------------------------------------------------------------------
// GEMM: C[M,Ntot] = A[M,K] @ Wt[Ntot,K]^T, bf16 hi/lo 3-term, cp.async 3-stage
// ---------------------------------------------------------------------------
#define KC 32
#define ROWB 80
#define MATB (128 * ROWB)
#define STAGEB (4 * MATB)
#define NSTAGE 3
#define GSMEM_BYTES (NSTAGE * STAGEB)

template <int EPI>
__global__ void __launch_bounds__(256) tc_gemm(
    const __nv_bfloat16* __restrict__ Ahi, const __nv_bfloat16* __restrict__ Alo,
    const __nv_bfloat16* __restrict__ Whi, const __nv_bfloat16* __restrict__ Wlo,
    const float* __restrict__ bias, const float* __restrict__ resid,
    float* __restrict__ C,
    __nv_bfloat16* __restrict__ Chi, __nv_bfloat16* __restrict__ Clo,
    int K, int Ntot)
{
    extern __shared__ char sm[];
    const uint32_t sb = smem_u32(sm);

    const int t    = threadIdx.x;
    const int wid  = t >> 5, lane = t & 31;
    const int wm   = wid >> 2;
    const int wn   = wid & 3;
    const int bn   = blockIdx.x, bm = blockIdx.y;
    const int rbase = bm * 128, cbase = bn * 128;
    const int nch  = K / KC;

    const int r0 = t >> 2, c0 = (t & 3);
    const int r1 = r0 + 64;
    auto issue = [&](int ci) {
        const int s = ci % NSTAGE;
        const uint32_t st = sb + s * STAGEB;
        const int kt = ci * KC;
        const size_t ga0 = (size_t)(rbase + r0) * K + kt + c0 * 8;
        const size_t ga1 = (size_t)(rbase + r1) * K + kt + c0 * 8;
        const size_t gb0 = (size_t)(cbase + r0) * K + kt + c0 * 8;
        const size_t gb1 = (size_t)(cbase + r1) * K + kt + c0 * 8;
        const uint32_t so0 = r0 * ROWB + c0 * 16;
        const uint32_t so1 = r1 * ROWB + c0 * 16;
        CP16(st + so0,            Ahi + ga0);
        CP16(st + so1,            Ahi + ga1);
        CP16(st + MATB + so0,     Alo + ga0);
        CP16(st + MATB + so1,     Alo + ga1);
        CP16(st + 2 * MATB + so0, Whi + gb0);
        CP16(st + 2 * MATB + so1, Whi + gb1);
        CP16(st + 3 * MATB + so0, Wlo + gb0);
        CP16(st + 3 * MATB + so1, Wlo + gb1);
    };

    float acc[4][4][4];
#pragma unroll
    for (int i = 0; i < 4; i++)
#pragma unroll
        for (int j = 0; j < 4; j++)
#pragma unroll
            for (int q = 0; q < 4; q++) acc[i][j][q] = 0.f;

    const uint32_t a_off = (uint32_t)((wm * 64 + (lane & 15)) * ROWB + ((lane >> 4) << 4));
    const uint32_t b_off = (uint32_t)((wn * 32 + ((lane & 7) | ((lane & 16) >> 1))) * ROWB
                                      + (((lane >> 3) & 1) << 4));

    issue(0); CP_COMMIT();
    issue(1); CP_COMMIT();

    for (int ci = 0; ci < nch; ci++) {
        if (ci + 1 < nch) { CP_WAIT(1); } else { CP_WAIT(0); }
        __syncthreads();
        if (ci + 2 < nch) { issue(ci + 2); CP_COMMIT(); }

        const uint32_t sA  = sb + (ci % NSTAGE) * STAGEB;
        const uint32_t sAl = sA + MATB;
        const uint32_t sBh = sA + 2 * MATB;
        const uint32_t sBl = sA + 3 * MATB;
#pragma unroll
        for (int ks = 0; ks < 2; ks++) {
            const uint32_t ko = ks * 32;
            uint32_t AH[4][4], AL[4][4], BH[2][4], BL[2][4];
#pragma unroll
            for (int mt = 0; mt < 4; mt++) {
                LDM4(AH[mt], sA  + a_off + mt * (16 * ROWB) + ko);
                LDM4(AL[mt], sAl + a_off + mt * (16 * ROWB) + ko);
            }
#pragma unroll
            for (int n2 = 0; n2 < 2; n2++) {
                LDM4(BH[n2], sBh + b_off + n2 * (16 * ROWB) + ko);
                LDM4(BL[n2], sBl + b_off + n2 * (16 * ROWB) + ko);
            }
#pragma unroll
            for (int mt = 0; mt < 4; mt++) {
#pragma unroll
                for (int nt = 0; nt < 4; nt++) {
                    const uint32_t bh0 = BH[nt >> 1][(nt & 1) * 2];
                    const uint32_t bh1 = BH[nt >> 1][(nt & 1) * 2 + 1];
                    const uint32_t bl0 = BL[nt >> 1][(nt & 1) * 2];
                    const uint32_t bl1 = BL[nt >> 1][(nt & 1) * 2 + 1];
                    MMA16816(acc[mt][nt], AH[mt], bh0, bh1);
                    MMA16816(acc[mt][nt], AH[mt], bl0, bl1);
                    MMA16816(acc[mt][nt], AL[mt], bh0, bh1);
                }
            }
        }
        __syncthreads();
    }

    const int mrow0 = rbase + wm * 64 + (lane >> 2);
    const int ncol0 = cbase + wn * 32 + (lane & 3) * 2;
#pragma unroll
    for (int mt = 0; mt < 4; mt++) {
#pragma unroll
        for (int half = 0; half < 2; half++) {
            const int m = mrow0 + mt * 16 + half * 8;
            const size_t rowoff = (size_t)m * Ntot;
#pragma unroll
            for (int nt = 0; nt < 4; nt++) {
                const int n = ncol0 + nt * 8;
                float v0 = acc[mt][nt][half * 2 + 0];
                float v1 = acc[mt][nt][half * 2 + 1];
                const float2 bv = *(const float2*)(bias + n);
                v0 += bv.x; v1 += bv.y;
                if (EPI == 2) {
                    const float2 rv = *(const float2*)(resid + rowoff + n);
                    v0 += rv.x; v1 += rv.y;
                    *(float2*)(C + rowoff + n) = make_float2(v0, v1);
                } else {
                    if (EPI == 1) { v0 = gelu_f(v0); v1 = gelu_f(v1); }
                    uint32_t uh, ul;
                    split2(v0, v1, uh, ul);
                    *(uint32_t*)(Chi + rowoff + n) = uh;
                    *(uint32_t*)(Clo + rowoff + n) = ul;
                }
            }
        }
    }
}

// ---------------------------------------------------------------------------
// Tensor-core flash attention.
// grid (8, 96), 128 threads (4 warps). Warp w: q rows [w*16, w*16+16).
// ---------------------------------------------------------------------------
#define AROWB 144
#define AMATB (64 * AROWB)
#define ASM_QH   0
#define ASM_QL   AMATB
#define ASM_MASK (2 * AMATB)
#define ASM_KV   (2 * AMATB + 2048)
#define ASTAGEB  (4 * AMATB)
#define ATT_SMEM (ASM_KV + 2 * ASTAGEB)

__global__ void __launch_bounds__(128) attn_kernel(
    const __nv_bfloat16* __restrict__ QKVh, const __nv_bfloat16* __restrict__ QKVl,
    const int* __restrict__ mask,
    __nv_bfloat16* __restrict__ Ch, __nv_bfloat16* __restrict__ Cl)
{
    extern __shared__ char sm[];
    const uint32_t sb = smem_u32(sm);

    const int qt = blockIdx.x;
    const int bh = blockIdx.y;
    const int b  = bh / NHH;
    const int h  = bh % NHH;
    const int t  = threadIdx.x;
    const int w  = t >> 5, lane = t & 31;

    const int ST = 3 * HH;
    const size_t rowbase = (size_t)b * SS;
    const int qcol = h * DHH, kcol = HH + h * DHH, vcol = 2 * HH + h * DHH;

#pragma unroll
    for (int j = 0; j < 8; j++) {
        const int idx = t + j * 128;
        const int mat = idx >> 9;
        const int rem = idx & 511;
        const int r = rem >> 3, c = rem & 7;
        const size_t g = (rowbase + qt * 64 + r) * ST + qcol + c * 8;
        const uint32_t s = sb + mat * AMATB + r * AROWB + c * 16;
        CP16(s, (mat ? QKVl : QKVh) + g);
    }
    {
        float* am = (float*)(sm + ASM_MASK);
#pragma unroll
        for (int j = 0; j < 4; j++) {
            const int i = t + j * 128;
            am[i] = (1.0f - (float)mask[b * SS + i]) * -10000.0f;
        }
    }
    CP_COMMIT();

    auto issueKV = [&](int kt, int s) {
        const uint32_t st = sb + ASM_KV + s * ASTAGEB;
#pragma unroll
        for (int j = 0; j < 16; j++) {
            const int idx = t + j * 128;
            const int mat = idx >> 9;
            const int rem = idx & 511;
            const int r = rem >> 3, c = rem & 7;
            const int col = (mat < 2) ? kcol : vcol;
            const __nv_bfloat16* src = (mat & 1) ? QKVl : QKVh;
            const size_t g = (rowbase + kt * 64 + r) * ST + col + c * 8;
            CP16(st + mat * AMATB + r * AROWB + c * 16, src + g);
        }
    };
    issueKV(0, 0); CP_COMMIT();

    float m0 = -1e30f, m1 = -1e30f, l0 = 0.f, l1 = 0.f;
    float oacc[8][4];
#pragma unroll
    for (int i = 0; i < 8; i++)
#pragma unroll
        for (int j = 0; j < 4; j++) oacc[i][j] = 0.f;

    const uint32_t a_off = (uint32_t)((w * 16 + (lane & 15)) * AROWB + ((lane >> 4) << 4));
    const uint32_t b_row = (uint32_t)(((lane & 7) | ((lane & 16) >> 1)) * AROWB
                                      + (((lane >> 3) & 1) << 4));
    const uint32_t v_row = (uint32_t)((lane & 15) * AROWB + ((lane >> 4) << 4));
    const float* am = (const float*)(sm + ASM_MASK);

    for (int kt = 0; kt < SS / 64; kt++) {
        const int s = kt & 1;
        if (kt + 1 < SS / 64) { issueKV(kt + 1, s ^ 1); CP_COMMIT(); CP_WAIT(1); }
        else                  { CP_WAIT(0); }
        __syncthreads();

        const uint32_t sK = sb + ASM_KV + s * ASTAGEB;
        const uint32_t sV = sK + 2 * AMATB;

        float sacc[8][4];
#pragma unroll
        for (int i = 0; i < 8; i++)
#pragma unroll
            for (int j = 0; j < 4; j++) sacc[i][j] = 0.f;

#pragma unroll
        for (int ks = 0; ks < 4; ks++) {
            const uint32_t ko = ks * 32;
            uint32_t qh[4], ql[4];
            LDM4(qh, sb + ASM_QH + a_off + ko);
            LDM4(ql, sb + ASM_QL + a_off + ko);
#pragma unroll
            for (int n2 = 0; n2 < 4; n2++) {
                uint32_t kh[4], kl[4];
                const uint32_t ba = sK + b_row + n2 * (16 * AROWB) + ko;
                LDM4(kh, ba);
                LDM4(kl, ba + AMATB);
#pragma unroll
                for (int hf = 0; hf < 2; hf++) {
                    const int nt = n2 * 2 + hf;
                    MMA16816(sacc[nt], qh, kh[hf * 2], kh[hf * 2 + 1]);
                    MMA16816(sacc[nt], qh, kl[hf * 2], kl[hf * 2 + 1]);
                    MMA16816(sacc[nt], ql, kh[hf * 2], kh[hf * 2 + 1]);
                }
            }
        }

        const int colbase = kt * 64 + (lane & 3) * 2;
        float rmax0 = -1e30f, rmax1 = -1e30f;
#pragma unroll
        for (int nt = 0; nt < 8; nt++) {
            const float a0 = am[colbase + nt * 8];
            const float a1 = am[colbase + nt * 8 + 1];
            sacc[nt][0] = fmaf(sacc[nt][0], 0.125f, a0);
            sacc[nt][1] = fmaf(sacc[nt][1], 0.125f, a1);
            sacc[nt][2] = fmaf(sacc[nt][2], 0.125f, a0);
            sacc[nt][3] = fmaf(sacc[nt][3], 0.125f, a1);
            rmax0 = fmaxf(rmax0, fmaxf(sacc[nt][0], sacc[nt][1]));
            rmax1 = fmaxf(rmax1, fmaxf(sacc[nt][2], sacc[nt][3]));
        }
        rmax0 = fmaxf(rmax0, __shfl_xor_sync(0xffffffffu, rmax0, 1));
        rmax0 = fmaxf(rmax0, __shfl_xor_sync(0xffffffffu, rmax0, 2));
        rmax1 = fmaxf(rmax1, __shfl_xor_sync(0xffffffffu, rmax1, 1));
        rmax1 = fmaxf(rmax1, __shfl_xor_sync(0xffffffffu, rmax1, 2));
        const float nm0 = fmaxf(m0, rmax0), nm1 = fmaxf(m1, rmax1);
        const float sc0 = __expf(m0 - nm0), sc1 = __expf(m1 - nm1);
        m0 = nm0; m1 = nm1;
        l0 *= sc0; l1 *= sc1;
#pragma unroll
        for (int nt = 0; nt < 8; nt++) {
            oacc[nt][0] *= sc0; oacc[nt][1] *= sc0;
            oacc[nt][2] *= sc1; oacc[nt][3] *= sc1;
        }
        float ps0 = 0.f, ps1 = 0.f;
#pragma unroll
        for (int nt = 0; nt < 8; nt++) {
            sacc[nt][0] = __expf(sacc[nt][0] - nm0);
            sacc[nt][1] = __expf(sacc[nt][1] - nm0);
            sacc[nt][2] = __expf(sacc[nt][2] - nm1);
            sacc[nt][3] = __expf(sacc[nt][3] - nm1);
            ps0 += sacc[nt][0] + sacc[nt][1];
            ps1 += sacc[nt][2] + sacc[nt][3];
        }
        l0 += ps0; l1 += ps1;

#pragma unroll
        for (int ks = 0; ks < 4; ks++) {
            uint32_t ah[4], al[4];
#pragma unroll
            for (int pos = 0; pos < 4; pos++) {
                const int nt = 2 * ks + (pos >> 1);
                const int jb = (pos & 1) * 2;
                split2(sacc[nt][jb], sacc[nt][jb + 1], ah[pos], al[pos]);
            }
#pragma unroll
            for (int dp = 0; dp < 4; dp++) {
                uint32_t vh[4], vl[4];
                const uint32_t va = sV + ks * (16 * AROWB) + v_row + dp * 32;
                LDM4T(vh, va);
                LDM4T(vl, va + AMATB);
                MMA16816(oacc[dp * 2],     ah, vh[0], vh[1]);
                MMA16816(oacc[dp * 2],     ah, vl[0], vl[1]);
                MMA16816(oacc[dp * 2],     al, vh[0], vh[1]);
                MMA16816(oacc[dp * 2 + 1], ah, vh[2], vh[3]);
                MMA16816(oacc[dp * 2 + 1], ah, vl[2], vl[3]);
                MMA16816(oacc[dp * 2 + 1], al, vh[2], vh[3]);
            }
        }
        __syncthreads();
    }

    l0 += __shfl_xor_sync(0xffffffffu, l0, 1);
    l0 += __shfl_xor_sync(0xffffffffu, l0, 2);
    l1 += __shfl_xor_sync(0xffffffffu, l1, 1);
    l1 += __shfl_xor_sync(0xffffffffu, l1, 2);
    const float inv0 = 1.0f / l0, inv1 = 1.0f / l1;

    // FIX (R4 bug): row index was double-counting b*SS
    const size_t row0 = (size_t)(b * SS + qt * 64 + w * 16 + (lane >> 2));
    const size_t row1 = row0 + 8;
    const int ocol = h * DHH + (lane & 3) * 2;
#pragma unroll
    for (int nt = 0; nt < 8; nt++) {
        const int n = ocol + nt * 8;
        uint32_t uh, ul;
        split2(oacc[nt][0] * inv0, oacc[nt][1] * inv0, uh, ul);
        *(uint32_t*)(Ch + row0 * HH + n) = uh;
        *(uint32_t*)(Cl + row0 * HH + n) = ul;
        split2(oacc[nt][2] * inv1, oacc[nt][3] * inv1, uh, ul);
        *(uint32_t*)(Ch + row1 * HH + n) = uh;
        *(uint32_t*)(Cl + row1 * HH + n) = ul;
    }
}

// ---------------------------------------------------------------------------
// Row-wise LayerNorm; optional bf16 hi/lo side output
// ---------------------------------------------------------------------------
template <int SPLIT>
__global__ void __launch_bounds__(256) ln_kernel(
    const float* __restrict__ X, const float* __restrict__ gg,
    const float* __restrict__ bb, float* __restrict__ Y,
    __nv_bfloat16* __restrict__ Yh, __nv_bfloat16* __restrict__ Yl)
{
    const int row = blockIdx.x;
    const float* x = X + (size_t)row * HH;
    const int c = threadIdx.x;

    const float v0 = x[c];
    const float v1 = x[c + 256];
    const float v2 = x[c + 512];
    float s  = v0 + v1 + v2;
    float s2 = v0 * v0 + v1 * v1 + v2 * v2;

    __shared__ float sa[8], sb2[8];
    __shared__ float stats[2];
    const int lane = threadIdx.x & 31, w = threadIdx.x >> 5;
#pragma unroll
    for (int o = 16; o > 0; o >>= 1) {
        s  += __shfl_down_sync(0xffffffffu, s, o);
        s2 += __shfl_down_sync(0xffffffffu, s2, o);
    }
    if (lane == 0) { sa[w] = s; sb2[w] = s2; }
    __syncthreads();
    if (threadIdx.x == 0) {
        float ts = 0.f, ts2 = 0.f;
#pragma unroll
        for (int i = 0; i < 8; i++) { ts += sa[i]; ts2 += sb2[i]; }
        const float mu  = ts * (1.0f / HH);
        const float var = ts2 * (1.0f / HH) - mu * mu;
        stats[0] = mu;
        stats[1] = rsqrtf(var + LN_EPS);
    }
    __syncthreads();
    const float mu = stats[0], rstd = stats[1];
    const size_t ro = (size_t)row * HH;
#pragma unroll
    for (int j = 0; j < 3; j++) {
        const int cc = c + j * 256;
        const float vv = (j == 0 ? v0 : (j == 1 ? v1 : v2));
        const float y = (vv - mu) * rstd * gg[cc] + bb[cc];
        Y[ro + cc] = y;
        if (SPLIT) {
            const __nv_bfloat16 hh = __float2bfloat16_rn(y);
            Yh[ro + cc] = hh;
            Yl[ro + cc] = __float2bfloat16_rn(y - __bfloat162float(hh));
        }
    }
}

// ---------------------------------------------------------------------------
// Launch
// ---------------------------------------------------------------------------
extern "C" void kernel_launch(void* const* d_in, const int* in_sizes, int n_in,
                              void* d_out, int out_size)
{
    (void)in_sizes; (void)n_in; (void)out_size;
    const float* x    = (const float*)d_in[0];
    const int*   mask = (const int*)  d_in[1];
    const float* Wq   = (const float*)d_in[2];
    const float* bq   = (const float*)d_in[3];
    const float* Wk   = (const float*)d_in[4];
    const float* bk   = (const float*)d_in[5];
    const float* Wv   = (const float*)d_in[6];
    const float* bv   = (const float*)d_in[7];
    const float* Wo   = (const float*)d_in[8];
    const float* bo   = (const float*)d_in[9];
    const float* ln1g = (const float*)d_in[10];
    const float* ln1b = (const float*)d_in[11];
    const float* W1   = (const float*)d_in[12];
    const float* b1   = (const float*)d_in[13];
    const float* W2   = (const float*)d_in[14];
    const float* b2   = (const float*)d_in[15];
    const float* ln2g = (const float*)d_in[16];
    const float* ln2b = (const float*)d_in[17];
    float* out = (float*)d_out;

    __nv_bfloat16 *xh, *xl, *qkvh, *qkvl, *ctxh, *ctxl, *h1h, *h1l, *ffh, *ffl;
    __nv_bfloat16 *wqkvh, *wqkvl, *woh, *wol, *w1h, *w1l, *w2h, *w2l;
    float *t1, *h1, *t2, *bqkv;
    cudaGetSymbolAddress((void**)&xh, g_xh);     cudaGetSymbolAddress((void**)&xl, g_xl);
    cudaGetSymbolAddress((void**)&qkvh, g_qkvh); cudaGetSymbolAddress((void**)&qkvl, g_qkvl);
    cudaGetSymbolAddress((void**)&ctxh, g_ctxh); cudaGetSymbolAddress((void**)&ctxl, g_ctxl);
    cudaGetSymbolAddress((void**)&h1h, g_h1h);   cudaGetSymbolAddress((void**)&h1l, g_h1l);
    cudaGetSymbolAddress((void**)&ffh, g_ffh);   cudaGetSymbolAddress((void**)&ffl, g_ffl);
    cudaGetSymbolAddress((void**)&wqkvh, g_wqkvh); cudaGetSymbolAddress((void**)&wqkvl, g_wqkvl);
    cudaGetSymbolAddress((void**)&woh, g_woh);   cudaGetSymbolAddress((void**)&wol, g_wol);
    cudaGetSymbolAddress((void**)&w1h, g_w1h);   cudaGetSymbolAddress((void**)&w1l, g_w1l);
    cudaGetSymbolAddress((void**)&w2h, g_w2h);   cudaGetSymbolAddress((void**)&w2l, g_w2l);
    cudaGetSymbolAddress((void**)&t1, g_t1);
    cudaGetSymbolAddress((void**)&h1, g_h1);
    cudaGetSymbolAddress((void**)&t2, g_t2);
    cudaGetSymbolAddress((void**)&bqkv, g_bqkv);

    cudaFuncSetAttribute(attn_kernel,
                         cudaFuncAttributeMaxDynamicSharedMemorySize, ATT_SMEM);
    cudaFuncSetAttribute(tc_gemm<0>,
                         cudaFuncAttributeMaxDynamicSharedMemorySize, GSMEM_BYTES);
    cudaFuncSetAttribute(tc_gemm<1>,
                         cudaFuncAttributeMaxDynamicSharedMemorySize, GSMEM_BYTES);
    cudaFuncSetAttribute(tc_gemm<2>,
                         cudaFuncAttributeMaxDynamicSharedMemorySize, GSMEM_BYTES);

    const dim3 tb(32, 8);

    trans_split_kernel<<<dim3(HH / 32,  HH / 32),  tb>>>(Wq, wqkvh,              wqkvl,              HH, HH);
    trans_split_kernel<<<dim3(HH / 32,  HH / 32),  tb>>>(Wk, wqkvh + HH * HH,    wqkvl + HH * HH,    HH, HH);
    trans_split_kernel<<<dim3(HH / 32,  HH / 32),  tb>>>(Wv, wqkvh + 2 * HH * HH, wqkvl + 2 * HH * HH, HH, HH);
    trans_split_kernel<<<dim3(HH / 32,  HH / 32),  tb>>>(Wo, woh, wol, HH, HH);
    trans_split_kernel<<<dim3(FFF / 32, HH / 32),  tb>>>(W1, w1h, w1l, HH, FFF);
    trans_split_kernel<<<dim3(HH / 32,  FFF / 32), tb>>>(W2, w2h, w2l, FFF, HH);
    split_kernel<<<(MM * HH + 255) / 256, 256>>>(x, xh, xl, MM * HH);
    concat3_kernel<<<3, 256>>>(bq, bk, bv, bqkv);

    tc_gemm<0><<<dim3(3 * HH / 128, MM / 128), 256, GSMEM_BYTES>>>(
        xh, xl, wqkvh, wqkvl, bqkv, nullptr, nullptr, qkvh, qkvl, HH, 3 * HH);

    attn_kernel<<<dim3(SS / 64, BB * NHH), 128, ATT_SMEM>>>(
        qkvh, qkvl, mask, ctxh, ctxl);

    tc_gemm<2><<<dim3(HH / 128, MM / 128), 256, GSMEM_BYTES>>>(
        ctxh, ctxl, woh, wol, bo, x, t1, nullptr, nullptr, HH, HH);
    ln_kernel<1><<<MM, 256>>>(t1, ln1g, ln1b, h1, h1h, h1l);

    tc_gemm<1><<<dim3(FFF / 128, MM / 128), 256, GSMEM_BYTES>>>(
        h1h, h1l, w1h, w1l, b1, nullptr, nullptr, ffh, ffl, HH, FFF);

    tc_gemm<2><<<dim3(HH / 128, MM / 128), 256, GSMEM_BYTES>>>(
        ffh, ffl, w2h, w2l, b2, h1, t2, nullptr, nullptr, FFF, HH);
    ln_kernel<0><<<MM, 256>>>(t2, ln2g, ln2b, out, nullptr, nullptr);
}

// round 6
// speedup vs baseline: 3.8668x; 1.6141x over previous
#include <cuda_runtime.h>
#include <cuda_fp16.h>
#include <math.h>
#include <stdint.h>

#define BB   8
#define SS   512
#define HH   768
#define NHH  12
#define DHH  64
#define FFF  3072
#define MM   (BB * SS)
#define LN_EPS 1e-3f

// ---------------------------------------------------------------------------
// Scratch
// ---------------------------------------------------------------------------
__device__ __align__(16) __half g_xh  [MM * HH];
__device__ __align__(16) __half g_xl  [MM * HH];
__device__ __align__(16) __half g_qkvh[MM * 3 * HH];
__device__ __align__(16) __half g_qkvl[MM * 3 * HH];
__device__ __align__(16) __half g_ctxh[MM * HH];
__device__ __align__(16) __half g_ctxl[MM * HH];
__device__ __align__(16) float g_t1 [MM * HH];
__device__ __align__(16) float g_h1 [MM * HH];
__device__ __align__(16) __half g_h1h[MM * HH];
__device__ __align__(16) __half g_h1l[MM * HH];
__device__ __align__(16) __half g_ffh[MM * FFF];
__device__ __align__(16) __half g_ffl[MM * FFF];
__device__ __align__(16) float g_t2 [MM * HH];
__device__ __align__(16) __half g_wqkv[3 * HH * HH];   // fp16 hi only
__device__ __align__(16) float g_bqkv[3 * HH];
__device__ __align__(16) __half g_wo [HH * HH];
__device__ __align__(16) __half g_w1 [FFF * HH];
__device__ __align__(16) __half g_w2 [HH * FFF];

// ---------------------------------------------------------------------------
// PTX wrappers
// ---------------------------------------------------------------------------
__device__ __forceinline__ uint32_t smem_u32(const void* p) {
    uint32_t a;
    asm("{ .reg .u64 t; cvta.to.shared.u64 t, %1; cvt.u32.u64 %0, t; }"
        : "=r"(a) : "l"(p));
    return a;
}
#define LDM4(R, ADDR) \
    asm volatile("ldmatrix.sync.aligned.m8n8.x4.shared.b16 {%0,%1,%2,%3}, [%4];" \
        : "=r"((R)[0]), "=r"((R)[1]), "=r"((R)[2]), "=r"((R)[3]) : "r"(ADDR))
#define LDM4T(R, ADDR) \
    asm volatile("ldmatrix.sync.aligned.m8n8.x4.trans.shared.b16 {%0,%1,%2,%3}, [%4];" \
        : "=r"((R)[0]), "=r"((R)[1]), "=r"((R)[2]), "=r"((R)[3]) : "r"(ADDR))
#define MMAF16(D, A, B0, B1) \
    asm volatile("mma.sync.aligned.m16n8k16.row.col.f32.f16.f16.f32 " \
        "{%0,%1,%2,%3}, {%4,%5,%6,%7}, {%8,%9}, {%0,%1,%2,%3};" \
        : "+f"((D)[0]), "+f"((D)[1]), "+f"((D)[2]), "+f"((D)[3]) \
        : "r"((A)[0]), "r"((A)[1]), "r"((A)[2]), "r"((A)[3]), "r"(B0), "r"(B1))
#define CP16(SADDR, GPTR) \
    asm volatile("cp.async.cg.shared.global [%0], [%1], 16;" \
        :: "r"(SADDR), "l"(GPTR))
#define CP_COMMIT() asm volatile("cp.async.commit_group;" ::: "memory")
#define CP_WAIT(N)  asm volatile("cp.async.wait_group %0;" :: "n"(N) : "memory")

__device__ __forceinline__ float gelu_f(float x) {
    return 0.5f * x * (1.0f + erff(x * 0.70710678118654752f));
}
__device__ __forceinline__ void split2h(float v0, float v1, uint32_t& uh, uint32_t& ul) {
    __half2 h = __floats2half2_rn(v0, v1);
    float l0 = v0 - __half2float(__low2half(h));
    float l1 = v1 - __half2float(__high2half(h));
    __half2 l = __floats2half2_rn(l0, l1);
    uh = *(uint32_t*)&h; ul = *(uint32_t*)&l;
}

// ---------------------------------------------------------------------------
// Prep kernels
// ---------------------------------------------------------------------------
__global__ void __launch_bounds__(256) trans_half_kernel(
    const float* __restrict__ in, __half* __restrict__ oh, int K, int N)
{
    __shared__ float tile[32][33];
    const int n0 = blockIdx.x * 32, k0 = blockIdx.y * 32;
    const int tx = threadIdx.x, ty = threadIdx.y;
#pragma unroll
    for (int j = 0; j < 32; j += 8)
        tile[ty + j][tx] = in[(size_t)(k0 + ty + j) * N + n0 + tx];
    __syncthreads();
#pragma unroll
    for (int j = 0; j < 32; j += 8)
        oh[(size_t)(n0 + ty + j) * K + k0 + tx] = __float2half_rn(tile[tx][ty + j]);
}

__global__ void __launch_bounds__(256) split_kernel(
    const float* __restrict__ in, __half* __restrict__ oh,
    __half* __restrict__ ol, int n)
{
    const int i = blockIdx.x * 256 + threadIdx.x;
    if (i < n) {
        const float v = in[i];
        const __half h = __float2half_rn(v);
        oh[i] = h;
        ol[i] = __float2half_rn(v - __half2float(h));
    }
}

__global__ void concat3_kernel(const float* __restrict__ a, const float* __restrict__ b,
                               const float* __restrict__ c, float* __restrict__ o)
{
    const int i = blockIdx.x * 256 + threadIdx.x;
    if (i < HH) { o[i] = a[i]; o[HH + i] = b[i]; o[2 * HH + i] = c[i]; }
}

// ---------------------------------------------------------------------------
// GEMM: C[M,Ntot] = A[M,K] @ W[Ntot,K]^T; fp16 2-term (A hi+lo, W hi).
//   MT: warp M-tiles (4 -> BM=128, 2 -> BM=64). BN fixed 128.
//   EPI 0: bias -> fp16 hi/lo; 1: bias+GELU -> fp16 hi/lo; 2: bias+resid -> fp32
// ---------------------------------------------------------------------------
#define KC 32
#define ROWB 80
#define NSTAGE 3

template <int EPI, int MT>
__global__ void __launch_bounds__(256) tc_gemm(
    const __half* __restrict__ Ahi, const __half* __restrict__ Alo,
    const __half* __restrict__ Whi,
    const float* __restrict__ bias, const float* __restrict__ resid,
    float* __restrict__ C,
    __half* __restrict__ Chi, __half* __restrict__ Clo,
    int K, int Ntot)
{
    constexpr int BM = MT * 32;
    constexpr int AMATB = BM * ROWB;
    constexpr int BMATB = 128 * ROWB;
    constexpr int STAGEB = 2 * AMATB + BMATB;
    constexpr int ACH = BM * 4;            // 16B chunks per A matrix
    constexpr int NCHK = (2 * ACH + 512) / 256;

    extern __shared__ char sm[];
    const uint32_t sb = smem_u32(sm);

    const int t    = threadIdx.x;
    const int wid  = t >> 5, lane = t & 31;
    const int wm   = wid >> 2;
    const int wn   = wid & 3;
    const int bn   = blockIdx.x, bm = blockIdx.y;
    const int rbase = bm * BM, cbase = bn * 128;
    const int nch  = K / KC;

    auto issue = [&](int ci) {
        const int s = ci % NSTAGE;
        const uint32_t st = sb + s * STAGEB;
        const int kt = ci * KC;
#pragma unroll
        for (int j = 0; j < NCHK; j++) {
            int id = t + j * 256;
            if (id < ACH) {
                const int r = id >> 2, c = id & 3;
                CP16(st + r * ROWB + c * 16,
                     Ahi + (size_t)(rbase + r) * K + kt + c * 8);
            } else if (id < 2 * ACH) {
                id -= ACH;
                const int r = id >> 2, c = id & 3;
                CP16(st + AMATB + r * ROWB + c * 16,
                     Alo + (size_t)(rbase + r) * K + kt + c * 8);
            } else {
                id -= 2 * ACH;
                const int r = id >> 2, c = id & 3;
                CP16(st + 2 * AMATB + r * ROWB + c * 16,
                     Whi + (size_t)(cbase + r) * K + kt + c * 8);
            }
        }
    };

    float acc[MT][4][4];
#pragma unroll
    for (int i = 0; i < MT; i++)
#pragma unroll
        for (int j = 0; j < 4; j++)
#pragma unroll
            for (int q = 0; q < 4; q++) acc[i][j][q] = 0.f;

    const uint32_t a_off = (uint32_t)((wm * (MT * 16) + (lane & 15)) * ROWB
                                      + ((lane >> 4) << 4));
    const uint32_t b_off = (uint32_t)((wn * 32 + ((lane & 7) | ((lane & 16) >> 1))) * ROWB
                                      + (((lane >> 3) & 1) << 4));

    issue(0); CP_COMMIT();
    issue(1); CP_COMMIT();

    for (int ci = 0; ci < nch; ci++) {
        if (ci + 1 < nch) { CP_WAIT(1); } else { CP_WAIT(0); }
        __syncthreads();
        if (ci + 2 < nch) { issue(ci + 2); CP_COMMIT(); }

        const uint32_t sA  = sb + (ci % NSTAGE) * STAGEB;
        const uint32_t sAl = sA + AMATB;
        const uint32_t sBh = sA + 2 * AMATB;
#pragma unroll
        for (int ks = 0; ks < 2; ks++) {
            const uint32_t ko = ks * 32;
            uint32_t AH[MT][4], AL[MT][4], BH[2][4];
#pragma unroll
            for (int mt = 0; mt < MT; mt++) {
                LDM4(AH[mt], sA  + a_off + mt * (16 * ROWB) + ko);
                LDM4(AL[mt], sAl + a_off + mt * (16 * ROWB) + ko);
            }
#pragma unroll
            for (int n2 = 0; n2 < 2; n2++)
                LDM4(BH[n2], sBh + b_off + n2 * (16 * ROWB) + ko);
#pragma unroll
            for (int mt = 0; mt < MT; mt++) {
#pragma unroll
                for (int nt = 0; nt < 4; nt++) {
                    const uint32_t b0 = BH[nt >> 1][(nt & 1) * 2];
                    const uint32_t b1 = BH[nt >> 1][(nt & 1) * 2 + 1];
                    MMAF16(acc[mt][nt], AH[mt], b0, b1);
                    MMAF16(acc[mt][nt], AL[mt], b0, b1);
                }
            }
        }
        __syncthreads();
    }

    const int mrow0 = rbase + wm * (MT * 16) + (lane >> 2);
    const int ncol0 = cbase + wn * 32 + (lane & 3) * 2;
#pragma unroll
    for (int mt = 0; mt < MT; mt++) {
#pragma unroll
        for (int half = 0; half < 2; half++) {
            const int m = mrow0 + mt * 16 + half * 8;
            const size_t rowoff = (size_t)m * Ntot;
#pragma unroll
            for (int nt = 0; nt < 4; nt++) {
                const int n = ncol0 + nt * 8;
                float v0 = acc[mt][nt][half * 2 + 0];
                float v1 = acc[mt][nt][half * 2 + 1];
                const float2 bv = *(const float2*)(bias + n);
                v0 += bv.x; v1 += bv.y;
                if (EPI == 2) {
                    const float2 rv = *(const float2*)(resid + rowoff + n);
                    v0 += rv.x; v1 += rv.y;
                    *(float2*)(C + rowoff + n) = make_float2(v0, v1);
                } else {
                    if (EPI == 1) { v0 = gelu_f(v0); v1 = gelu_f(v1); }
                    uint32_t uh, ul;
                    split2h(v0, v1, uh, ul);
                    *(uint32_t*)(Chi + rowoff + n) = uh;
                    *(uint32_t*)(Clo + rowoff + n) = ul;
                }
            }
        }
    }
}

// ---------------------------------------------------------------------------
// Tensor-core flash attention, fp16 3-term.
// grid (8, 96), 128 threads (4 warps). Warp w: q rows [w*16, w*16+16).
// ---------------------------------------------------------------------------
#define AROWB 144
#define AMATB_A (64 * AROWB)
#define ASM_QH   0
#define ASM_QL   AMATB_A
#define ASM_MASK (2 * AMATB_A)
#define ASM_KV   (2 * AMATB_A + 2048)
#define ASTAGEB  (4 * AMATB_A)
#define ATT_SMEM (ASM_KV + 2 * ASTAGEB)

__global__ void __launch_bounds__(128) attn_kernel(
    const __half* __restrict__ QKVh, const __half* __restrict__ QKVl,
    const int* __restrict__ mask,
    __half* __restrict__ Ch, __half* __restrict__ Cl)
{
    extern __shared__ char sm[];
    const uint32_t sb = smem_u32(sm);

    const int qt = blockIdx.x;
    const int bh = blockIdx.y;
    const int b  = bh / NHH;
    const int h  = bh % NHH;
    const int t  = threadIdx.x;
    const int w  = t >> 5, lane = t & 31;

    const int ST = 3 * HH;
    const size_t rowbase = (size_t)b * SS;
    const int qcol = h * DHH, kcol = HH + h * DHH, vcol = 2 * HH + h * DHH;

#pragma unroll
    for (int j = 0; j < 8; j++) {
        const int idx = t + j * 128;
        const int mat = idx >> 9;
        const int rem = idx & 511;
        const int r = rem >> 3, c = rem & 7;
        const size_t g = (rowbase + qt * 64 + r) * ST + qcol + c * 8;
        const uint32_t s = sb + mat * AMATB_A + r * AROWB + c * 16;
        CP16(s, (mat ? QKVl : QKVh) + g);
    }
    {
        float* am = (float*)(sm + ASM_MASK);
#pragma unroll
        for (int j = 0; j < 4; j++) {
            const int i = t + j * 128;
            am[i] = (1.0f - (float)mask[b * SS + i]) * -10000.0f;
        }
    }
    CP_COMMIT();

    auto issueKV = [&](int kt, int s) {
        const uint32_t st = sb + ASM_KV + s * ASTAGEB;
#pragma unroll
        for (int j = 0; j < 16; j++) {
            const int idx = t + j * 128;
            const int mat = idx >> 9;
            const int rem = idx & 511;
            const int r = rem >> 3, c = rem & 7;
            const int col = (mat < 2) ? kcol : vcol;
            const __half* src = (mat & 1) ? QKVl : QKVh;
            const size_t g = (rowbase + kt * 64 + r) * ST + col + c * 8;
            CP16(st + mat * AMATB_A + r * AROWB + c * 16, src + g);
        }
    };
    issueKV(0, 0); CP_COMMIT();

    float m0 = -1e30f, m1 = -1e30f, l0 = 0.f, l1 = 0.f;
    float oacc[8][4];
#pragma unroll
    for (int i = 0; i < 8; i++)
#pragma unroll
        for (int j = 0; j < 4; j++) oacc[i][j] = 0.f;

    const uint32_t a_off = (uint32_t)((w * 16 + (lane & 15)) * AROWB + ((lane >> 4) << 4));
    const uint32_t b_row = (uint32_t)(((lane & 7) | ((lane & 16) >> 1)) * AROWB
                                      + (((lane >> 3) & 1) << 4));
    const uint32_t v_row = (uint32_t)((lane & 15) * AROWB + ((lane >> 4) << 4));
    const float* am = (const float*)(sm + ASM_MASK);

    for (int kt = 0; kt < SS / 64; kt++) {
        const int s = kt & 1;
        if (kt + 1 < SS / 64) { issueKV(kt + 1, s ^ 1); CP_COMMIT(); CP_WAIT(1); }
        else                  { CP_WAIT(0); }
        __syncthreads();

        const uint32_t sK = sb + ASM_KV + s * ASTAGEB;
        const uint32_t sV = sK + 2 * AMATB_A;

        float sacc[8][4];
#pragma unroll
        for (int i = 0; i < 8; i++)
#pragma unroll
            for (int j = 0; j < 4; j++) sacc[i][j] = 0.f;

#pragma unroll
        for (int ks = 0; ks < 4; ks++) {
            const uint32_t ko = ks * 32;
            uint32_t qh[4], ql[4];
            LDM4(qh, sb + ASM_QH + a_off + ko);
            LDM4(ql, sb + ASM_QL + a_off + ko);
#pragma unroll
            for (int n2 = 0; n2 < 4; n2++) {
                uint32_t kh[4], kl[4];
                const uint32_t ba = sK + b_row + n2 * (16 * AROWB) + ko;
                LDM4(kh, ba);
                LDM4(kl, ba + AMATB_A);
#pragma unroll
                for (int hf = 0; hf < 2; hf++) {
                    const int nt = n2 * 2 + hf;
                    MMAF16(sacc[nt], qh, kh[hf * 2], kh[hf * 2 + 1]);
                    MMAF16(sacc[nt], qh, kl[hf * 2], kl[hf * 2 + 1]);
                    MMAF16(sacc[nt], ql, kh[hf * 2], kh[hf * 2 + 1]);
                }
            }
        }

        const int colbase = kt * 64 + (lane & 3) * 2;
        float rmax0 = -1e30f, rmax1 = -1e30f;
#pragma unroll
        for (int nt = 0; nt < 8; nt++) {
            const float a0 = am[colbase + nt * 8];
            const float a1 = am[colbase + nt * 8 + 1];
            sacc[nt][0] = fmaf(sacc[nt][0], 0.125f, a0);
            sacc[nt][1] = fmaf(sacc[nt][1], 0.125f, a1);
            sacc[nt][2] = fmaf(sacc[nt][2], 0.125f, a0);
            sacc[nt][3] = fmaf(sacc[nt][3], 0.125f, a1);
            rmax0 = fmaxf(rmax0, fmaxf(sacc[nt][0], sacc[nt][1]));
            rmax1 = fmaxf(rmax1, fmaxf(sacc[nt][2], sacc[nt][3]));
        }
        rmax0 = fmaxf(rmax0, __shfl_xor_sync(0xffffffffu, rmax0, 1));
        rmax0 = fmaxf(rmax0, __shfl_xor_sync(0xffffffffu, rmax0, 2));
        rmax1 = fmaxf(rmax1, __shfl_xor_sync(0xffffffffu, rmax1, 1));
        rmax1 = fmaxf(rmax1, __shfl_xor_sync(0xffffffffu, rmax1, 2));
        const float nm0 = fmaxf(m0, rmax0), nm1 = fmaxf(m1, rmax1);
        const float sc0 = __expf(m0 - nm0), sc1 = __expf(m1 - nm1);
        m0 = nm0; m1 = nm1;
        l0 *= sc0; l1 *= sc1;
#pragma unroll
        for (int nt = 0; nt < 8; nt++) {
            oacc[nt][0] *= sc0; oacc[nt][1] *= sc0;
            oacc[nt][2] *= sc1; oacc[nt][3] *= sc1;
        }
        float ps0 = 0.f, ps1 = 0.f;
#pragma unroll
        for (int nt = 0; nt < 8; nt++) {
            sacc[nt][0] = __expf(sacc[nt][0] - nm0);
            sacc[nt][1] = __expf(sacc[nt][1] - nm0);
            sacc[nt][2] = __expf(sacc[nt][2] - nm1);
            sacc[nt][3] = __expf(sacc[nt][3] - nm1);
            ps0 += sacc[nt][0] + sacc[nt][1];
            ps1 += sacc[nt][2] + sacc[nt][3];
        }
        l0 += ps0; l1 += ps1;

#pragma unroll
        for (int ks = 0; ks < 4; ks++) {
            uint32_t ah[4], al[4];
#pragma unroll
            for (int pos = 0; pos < 4; pos++) {
                const int nt = 2 * ks + (pos >> 1);
                const int jb = (pos & 1) * 2;
                split2h(sacc[nt][jb], sacc[nt][jb + 1], ah[pos], al[pos]);
            }
#pragma unroll
            for (int dp = 0; dp < 4; dp++) {
                uint32_t vh[4], vl[4];
                const uint32_t va = sV + ks * (16 * AROWB) + v_row + dp * 32;
                LDM4T(vh, va);
                LDM4T(vl, va + AMATB_A);
                MMAF16(oacc[dp * 2],     ah, vh[0], vh[1]);
                MMAF16(oacc[dp * 2],     ah, vl[0], vl[1]);
                MMAF16(oacc[dp * 2],     al, vh[0], vh[1]);
                MMAF16(oacc[dp * 2 + 1], ah, vh[2], vh[3]);
                MMAF16(oacc[dp * 2 + 1], ah, vl[2], vl[3]);
                MMAF16(oacc[dp * 2 + 1], al, vh[2], vh[3]);
            }
        }
        __syncthreads();
    }

    l0 += __shfl_xor_sync(0xffffffffu, l0, 1);
    l0 += __shfl_xor_sync(0xffffffffu, l0, 2);
    l1 += __shfl_xor_sync(0xffffffffu, l1, 1);
    l1 += __shfl_xor_sync(0xffffffffu, l1, 2);
    const float inv0 = 1.0f / l0, inv1 = 1.0f / l1;

    const size_t row0 = (size_t)(b * SS + qt * 64 + w * 16 + (lane >> 2));
    const size_t row1 = row0 + 8;
    const int ocol = h * DHH + (lane & 3) * 2;
#pragma unroll
    for (int nt = 0; nt < 8; nt++) {
        const int n = ocol + nt * 8;
        uint32_t uh, ul;
        split2h(oacc[nt][0] * inv0, oacc[nt][1] * inv0, uh, ul);
        *(uint32_t*)(Ch + row0 * HH + n) = uh;
        *(uint32_t*)(Cl + row0 * HH + n) = ul;
        split2h(oacc[nt][2] * inv1, oacc[nt][3] * inv1, uh, ul);
        *(uint32_t*)(Ch + row1 * HH + n) = uh;
        *(uint32_t*)(Cl + row1 * HH + n) = ul;
    }
}

// ---------------------------------------------------------------------------
// Row-wise LayerNorm; optional fp16 hi/lo side output
// ---------------------------------------------------------------------------
template <int SPLIT>
__global__ void __launch_bounds__(256) ln_kernel(
    const float* __restrict__ X, const float* __restrict__ gg,
    const float* __restrict__ bb, float* __restrict__ Y,
    __half* __restrict__ Yh, __half* __restrict__ Yl)
{
    const int row = blockIdx.x;
    const float* x = X + (size_t)row * HH;
    const int c = threadIdx.x;

    const float v0 = x[c];
    const float v1 = x[c + 256];
    const float v2 = x[c + 512];
    float s  = v0 + v1 + v2;
    float s2 = v0 * v0 + v1 * v1 + v2 * v2;

    __shared__ float sa[8], sb2[8];
    __shared__ float stats[2];
    const int lane = threadIdx.x & 31, w = threadIdx.x >> 5;
#pragma unroll
    for (int o = 16; o > 0; o >>= 1) {
        s  += __shfl_down_sync(0xffffffffu, s, o);
        s2 += __shfl_down_sync(0xffffffffu, s2, o);
    }
    if (lane == 0) { sa[w] = s; sb2[w] = s2; }
    __syncthreads();
    if (threadIdx.x == 0) {
        float ts = 0.f, ts2 = 0.f;
#pragma unroll
        for (int i = 0; i < 8; i++) { ts += sa[i]; ts2 += sb2[i]; }
        const float mu  = ts * (1.0f / HH);
        const float var = ts2 * (1.0f / HH) - mu * mu;
        stats[0] = mu;
        stats[1] = rsqrtf(var + LN_EPS);
    }
    __syncthreads();
    const float mu = stats[0], rstd = stats[1];
    const size_t ro = (size_t)row * HH;
#pragma unroll
    for (int j = 0; j < 3; j++) {
        const int cc = c + j * 256;
        const float vv = (j == 0 ? v0 : (j == 1 ? v1 : v2));
        const float y = (vv - mu) * rstd * gg[cc] + bb[cc];
        Y[ro + cc] = y;
        if (SPLIT) {
            const __half hh = __float2half_rn(y);
            Yh[ro + cc] = hh;
            Yl[ro + cc] = __float2half_rn(y - __half2float(hh));
        }
    }
}

// ---------------------------------------------------------------------------
// Launch
// ---------------------------------------------------------------------------
extern "C" void kernel_launch(void* const* d_in, const int* in_sizes, int n_in,
                              void* d_out, int out_size)
{
    (void)in_sizes; (void)n_in; (void)out_size;
    const float* x    = (const float*)d_in[0];
    const int*   mask = (const int*)  d_in[1];
    const float* Wq   = (const float*)d_in[2];
    const float* bq   = (const float*)d_in[3];
    const float* Wk   = (const float*)d_in[4];
    const float* bk   = (const float*)d_in[5];
    const float* Wv   = (const float*)d_in[6];
    const float* bv   = (const float*)d_in[7];
    const float* Wo   = (const float*)d_in[8];
    const float* bo   = (const float*)d_in[9];
    const float* ln1g = (const float*)d_in[10];
    const float* ln1b = (const float*)d_in[11];
    const float* W1   = (const float*)d_in[12];
    const float* b1   = (const float*)d_in[13];
    const float* W2   = (const float*)d_in[14];
    const float* b2   = (const float*)d_in[15];
    const float* ln2g = (const float*)d_in[16];
    const float* ln2b = (const float*)d_in[17];
    float* out = (float*)d_out;

    __half *xh, *xl, *qkvh, *qkvl, *ctxh, *ctxl, *h1h, *h1l, *ffh, *ffl;
    __half *wqkv, *wo, *w1, *w2;
    float *t1, *h1, *t2, *bqkv;
    cudaGetSymbolAddress((void**)&xh, g_xh);     cudaGetSymbolAddress((void**)&xl, g_xl);
    cudaGetSymbolAddress((void**)&qkvh, g_qkvh); cudaGetSymbolAddress((void**)&qkvl, g_qkvl);
    cudaGetSymbolAddress((void**)&ctxh, g_ctxh); cudaGetSymbolAddress((void**)&ctxl, g_ctxl);
    cudaGetSymbolAddress((void**)&h1h, g_h1h);   cudaGetSymbolAddress((void**)&h1l, g_h1l);
    cudaGetSymbolAddress((void**)&ffh, g_ffh);   cudaGetSymbolAddress((void**)&ffl, g_ffl);
    cudaGetSymbolAddress((void**)&wqkv, g_wqkv);
    cudaGetSymbolAddress((void**)&wo, g_wo);
    cudaGetSymbolAddress((void**)&w1, g_w1);
    cudaGetSymbolAddress((void**)&w2, g_w2);
    cudaGetSymbolAddress((void**)&t1, g_t1);
    cudaGetSymbolAddress((void**)&h1, g_h1);
    cudaGetSymbolAddress((void**)&t2, g_t2);
    cudaGetSymbolAddress((void**)&bqkv, g_bqkv);

    constexpr int SM128 = (2 * 128 + 128) * ROWB * NSTAGE;   // MT=4
    constexpr int SM64  = (2 * 64 + 128) * ROWB * NSTAGE;    // MT=2

    cudaFuncSetAttribute(attn_kernel,
                         cudaFuncAttributeMaxDynamicSharedMemorySize, ATT_SMEM);
    cudaFuncSetAttribute(tc_gemm<0, 4>,
                         cudaFuncAttributeMaxDynamicSharedMemorySize, SM128);
    cudaFuncSetAttribute(tc_gemm<1, 4>,
                         cudaFuncAttributeMaxDynamicSharedMemorySize, SM128);
    cudaFuncSetAttribute(tc_gemm<2, 2>,
                         cudaFuncAttributeMaxDynamicSharedMemorySize, SM64);

    const dim3 tb(32, 8);

    trans_half_kernel<<<dim3(HH / 32,  HH / 32),  tb>>>(Wq, wqkv,              HH, HH);
    trans_half_kernel<<<dim3(HH / 32,  HH / 32),  tb>>>(Wk, wqkv + HH * HH,    HH, HH);
    trans_half_kernel<<<dim3(HH / 32,  HH / 32),  tb>>>(Wv, wqkv + 2 * HH * HH, HH, HH);
    trans_half_kernel<<<dim3(HH / 32,  HH / 32),  tb>>>(Wo, wo, HH, HH);
    trans_half_kernel<<<dim3(FFF / 32, HH / 32),  tb>>>(W1, w1, HH, FFF);
    trans_half_kernel<<<dim3(HH / 32,  FFF / 32), tb>>>(W2, w2, FFF, HH);
    split_kernel<<<(MM * HH + 255) / 256, 256>>>(x, xh, xl, MM * HH);
    concat3_kernel<<<3, 256>>>(bq, bk, bv, bqkv);

    // fused QKV -> fp16 hi/lo   (grid 18x32 = 576 tiles)
    tc_gemm<0, 4><<<dim3(3 * HH / 128, MM / 128), 256, SM128>>>(
        xh, xl, wqkv, bqkv, nullptr, nullptr, qkvh, qkvl, HH, 3 * HH);

    // attention -> ctx fp16 hi/lo
    attn_kernel<<<dim3(SS / 64, BB * NHH), 128, ATT_SMEM>>>(
        qkvh, qkvl, mask, ctxh, ctxl);

    // t1 = ctx @ Wo + bo + x    (BM=64: grid 6x64 = 384 tiles)
    tc_gemm<2, 2><<<dim3(HH / 128, MM / 64), 256, SM64>>>(
        ctxh, ctxl, wo, bo, x, t1, nullptr, nullptr, HH, HH);
    ln_kernel<1><<<MM, 256>>>(t1, ln1g, ln1b, h1, h1h, h1l);

    // ff = gelu(h1 @ W1 + b1)   (grid 24x32 = 768 tiles)
    tc_gemm<1, 4><<<dim3(FFF / 128, MM / 128), 256, SM128>>>(
        h1h, h1l, w1, b1, nullptr, nullptr, ffh, ffl, HH, FFF);

    // t2 = ff @ W2 + b2 + h1    (BM=64: grid 6x64 = 384 tiles)
    tc_gemm<2, 2><<<dim3(HH / 128, MM / 64), 256, SM64>>>(
        ffh, ffl, w2, b2, h1, t2, nullptr, nullptr, FFF, HH);
    ln_kernel<0><<<MM, 256>>>(t2, ln2g, ln2b, out, nullptr, nullptr);
}

// round 7
// speedup vs baseline: 5.4223x; 1.4023x over previous
#include <cuda_runtime.h>
#include <cuda_fp16.h>
#include <math.h>
#include <stdint.h>

#define BB   8
#define SS   512
#define HH   768
#define NHH  12
#define DHH  64
#define FFF  3072
#define MM   (BB * SS)
#define LN_EPS 1e-3f

// ---------------------------------------------------------------------------
// Scratch
// ---------------------------------------------------------------------------
__device__ __align__(16) __half g_xh  [MM * HH];
__device__ __align__(16) __half g_qkvh[MM * 3 * HH];
__device__ __align__(16) __half g_qkvl[MM * 3 * HH];
__device__ __align__(16) __half g_ctxh[MM * HH];
__device__ __align__(16) __half g_ctxl[MM * HH];
__device__ __align__(16) float g_t1 [MM * HH];
__device__ __align__(16) float g_h1 [MM * HH];
__device__ __align__(16) __half g_h1h[MM * HH];
__device__ __align__(16) __half g_ffh[MM * FFF];
__device__ __align__(16) float g_t2 [MM * HH];
__device__ __align__(16) __half g_wqkv[3 * HH * HH];
__device__ __align__(16) float g_bqkv[3 * HH];
__device__ __align__(16) __half g_wo [HH * HH];
__device__ __align__(16) __half g_w1 [FFF * HH];
__device__ __align__(16) __half g_w2 [HH * FFF];

// ---------------------------------------------------------------------------
// PTX wrappers
// ---------------------------------------------------------------------------
__device__ __forceinline__ uint32_t smem_u32(const void* p) {
    uint32_t a;
    asm("{ .reg .u64 t; cvta.to.shared.u64 t, %1; cvt.u32.u64 %0, t; }"
        : "=r"(a) : "l"(p));
    return a;
}
#define LDM4(R, ADDR) \
    asm volatile("ldmatrix.sync.aligned.m8n8.x4.shared.b16 {%0,%1,%2,%3}, [%4];" \
        : "=r"((R)[0]), "=r"((R)[1]), "=r"((R)[2]), "=r"((R)[3]) : "r"(ADDR))
#define LDM4T(R, ADDR) \
    asm volatile("ldmatrix.sync.aligned.m8n8.x4.trans.shared.b16 {%0,%1,%2,%3}, [%4];" \
        : "=r"((R)[0]), "=r"((R)[1]), "=r"((R)[2]), "=r"((R)[3]) : "r"(ADDR))
#define MMAF16(D, A, B0, B1) \
    asm volatile("mma.sync.aligned.m16n8k16.row.col.f32.f16.f16.f32 " \
        "{%0,%1,%2,%3}, {%4,%5,%6,%7}, {%8,%9}, {%0,%1,%2,%3};" \
        : "+f"((D)[0]), "+f"((D)[1]), "+f"((D)[2]), "+f"((D)[3]) \
        : "r"((A)[0]), "r"((A)[1]), "r"((A)[2]), "r"((A)[3]), "r"(B0), "r"(B1))
#define CP16(SADDR, GPTR) \
    asm volatile("cp.async.cg.shared.global [%0], [%1], 16;" \
        :: "r"(SADDR), "l"(GPTR))
#define CP_COMMIT() asm volatile("cp.async.commit_group;" ::: "memory")
#define CP_WAIT(N)  asm volatile("cp.async.wait_group %0;" :: "n"(N) : "memory")

__device__ __forceinline__ float gelu_f(float x) {
    return 0.5f * x * (1.0f + erff(x * 0.70710678118654752f));
}
__device__ __forceinline__ void split2h(float v0, float v1, uint32_t& uh, uint32_t& ul) {
    __half2 h = __floats2half2_rn(v0, v1);
    float l0 = v0 - __half2float(__low2half(h));
    float l1 = v1 - __half2float(__high2half(h));
    __half2 l = __floats2half2_rn(l0, l1);
    uh = *(uint32_t*)&h; ul = *(uint32_t*)&l;
}

// ---------------------------------------------------------------------------
// Prep kernels
// ---------------------------------------------------------------------------
__global__ void __launch_bounds__(256) trans_half4_kernel(
    const float* __restrict__ s0, const float* __restrict__ s1,
    const float* __restrict__ s2, const float* __restrict__ s3,
    __half* __restrict__ d0, __half* __restrict__ d1,
    __half* __restrict__ d2, __half* __restrict__ d3)
{
    const int z = blockIdx.z;
    const float* in = (z == 0) ? s0 : (z == 1) ? s1 : (z == 2) ? s2 : s3;
    __half* out     = (z == 0) ? d0 : (z == 1) ? d1 : (z == 2) ? d2 : d3;
    __shared__ float tile[32][33];
    const int n0 = blockIdx.x * 32, k0 = blockIdx.y * 32;
    const int tx = threadIdx.x, ty = threadIdx.y;
#pragma unroll
    for (int j = 0; j < 32; j += 8)
        tile[ty + j][tx] = in[(size_t)(k0 + ty + j) * HH + n0 + tx];
    __syncthreads();
#pragma unroll
    for (int j = 0; j < 32; j += 8)
        out[(size_t)(n0 + ty + j) * HH + k0 + tx] = __float2half_rn(tile[tx][ty + j]);
}

__global__ void __launch_bounds__(256) trans_half_kernel(
    const float* __restrict__ in, __half* __restrict__ oh, int K, int N)
{
    __shared__ float tile[32][33];
    const int n0 = blockIdx.x * 32, k0 = blockIdx.y * 32;
    const int tx = threadIdx.x, ty = threadIdx.y;
#pragma unroll
    for (int j = 0; j < 32; j += 8)
        tile[ty + j][tx] = in[(size_t)(k0 + ty + j) * N + n0 + tx];
    __syncthreads();
#pragma unroll
    for (int j = 0; j < 32; j += 8)
        oh[(size_t)(n0 + ty + j) * K + k0 + tx] = __float2half_rn(tile[tx][ty + j]);
}

__global__ void __launch_bounds__(256) half_kernel(
    const float* __restrict__ in, __half* __restrict__ oh, int n)
{
    const int i = blockIdx.x * 256 + threadIdx.x;
    if (i < n) oh[i] = __float2half_rn(in[i]);
}

__global__ void concat3_kernel(const float* __restrict__ a, const float* __restrict__ b,
                               const float* __restrict__ c, float* __restrict__ o)
{
    const int i = blockIdx.x * 256 + threadIdx.x;
    if (i < HH) { o[i] = a[i]; o[HH + i] = b[i]; o[2 * HH + i] = c[i]; }
}

// ---------------------------------------------------------------------------
// GEMM: C[M,Ntot] = A[M,K] @ W[Ntot,K]^T; pure fp16 1-term.
//   MT: warp M-tiles (4 -> BM=128, 2 -> BM=64). BN fixed 128.
//   EPI 0: bias -> fp16 hi/lo; 1: bias+GELU -> fp16 hi only; 2: bias+resid -> fp32
// ---------------------------------------------------------------------------
#define KC 32
#define ROWB 80
#define NSTAGE 3

template <int EPI, int MT>
__global__ void __launch_bounds__(256) tc_gemm(
    const __half* __restrict__ Ahi,
    const __half* __restrict__ Whi,
    const float* __restrict__ bias, const float* __restrict__ resid,
    float* __restrict__ C,
    __half* __restrict__ Chi, __half* __restrict__ Clo,
    int K, int Ntot)
{
    constexpr int BM = MT * 32;
    constexpr int AMATB = BM * ROWB;
    constexpr int BMATB = 128 * ROWB;
    constexpr int STAGEB = AMATB + BMATB;
    constexpr int ACH = BM * 4;
    constexpr int NCHK = (ACH + 512) / 256;

    extern __shared__ char sm[];
    const uint32_t sb = smem_u32(sm);

    const int t    = threadIdx.x;
    const int wid  = t >> 5, lane = t & 31;
    const int wm   = wid >> 2;
    const int wn   = wid & 3;
    const int bn   = blockIdx.x, bm = blockIdx.y;
    const int rbase = bm * BM, cbase = bn * 128;
    const int nch  = K / KC;

    auto issue = [&](int ci) {
        const int s = ci % NSTAGE;
        const uint32_t st = sb + s * STAGEB;
        const int kt = ci * KC;
#pragma unroll
        for (int j = 0; j < NCHK; j++) {
            int id = t + j * 256;
            if (id < ACH) {
                const int r = id >> 2, c = id & 3;
                CP16(st + r * ROWB + c * 16,
                     Ahi + (size_t)(rbase + r) * K + kt + c * 8);
            } else {
                id -= ACH;
                const int r = id >> 2, c = id & 3;
                CP16(st + AMATB + r * ROWB + c * 16,
                     Whi + (size_t)(cbase + r) * K + kt + c * 8);
            }
        }
    };

    float acc[MT][4][4];
#pragma unroll
    for (int i = 0; i < MT; i++)
#pragma unroll
        for (int j = 0; j < 4; j++)
#pragma unroll
            for (int q = 0; q < 4; q++) acc[i][j][q] = 0.f;

    const uint32_t a_off = (uint32_t)((wm * (MT * 16) + (lane & 15)) * ROWB
                                      + ((lane >> 4) << 4));
    const uint32_t b_off = (uint32_t)((wn * 32 + ((lane & 7) | ((lane & 16) >> 1))) * ROWB
                                      + (((lane >> 3) & 1) << 4));

    issue(0); CP_COMMIT();
    issue(1); CP_COMMIT();

    for (int ci = 0; ci < nch; ci++) {
        if (ci + 1 < nch) { CP_WAIT(1); } else { CP_WAIT(0); }
        __syncthreads();
        if (ci + 2 < nch) { issue(ci + 2); CP_COMMIT(); }

        const uint32_t sA  = sb + (ci % NSTAGE) * STAGEB;
        const uint32_t sBh = sA + AMATB;
#pragma unroll
        for (int ks = 0; ks < 2; ks++) {
            const uint32_t ko = ks * 32;
            uint32_t AH[MT][4], BH[2][4];
#pragma unroll
            for (int mt = 0; mt < MT; mt++)
                LDM4(AH[mt], sA + a_off + mt * (16 * ROWB) + ko);
#pragma unroll
            for (int n2 = 0; n2 < 2; n2++)
                LDM4(BH[n2], sBh + b_off + n2 * (16 * ROWB) + ko);
#pragma unroll
            for (int mt = 0; mt < MT; mt++) {
#pragma unroll
                for (int nt = 0; nt < 4; nt++) {
                    const uint32_t b0 = BH[nt >> 1][(nt & 1) * 2];
                    const uint32_t b1 = BH[nt >> 1][(nt & 1) * 2 + 1];
                    MMAF16(acc[mt][nt], AH[mt], b0, b1);
                }
            }
        }
        __syncthreads();
    }

    const int mrow0 = rbase + wm * (MT * 16) + (lane >> 2);
    const int ncol0 = cbase + wn * 32 + (lane & 3) * 2;
#pragma unroll
    for (int mt = 0; mt < MT; mt++) {
#pragma unroll
        for (int half = 0; half < 2; half++) {
            const int m = mrow0 + mt * 16 + half * 8;
            const size_t rowoff = (size_t)m * Ntot;
#pragma unroll
            for (int nt = 0; nt < 4; nt++) {
                const int n = ncol0 + nt * 8;
                float v0 = acc[mt][nt][half * 2 + 0];
                float v1 = acc[mt][nt][half * 2 + 1];
                const float2 bv = *(const float2*)(bias + n);
                v0 += bv.x; v1 += bv.y;
                if (EPI == 2) {
                    const float2 rv = *(const float2*)(resid + rowoff + n);
                    v0 += rv.x; v1 += rv.y;
                    *(float2*)(C + rowoff + n) = make_float2(v0, v1);
                } else if (EPI == 1) {
                    v0 = gelu_f(v0); v1 = gelu_f(v1);
                    __half2 hh = __floats2half2_rn(v0, v1);
                    *(__half2*)(Chi + rowoff + n) = hh;
                } else {
                    uint32_t uh, ul;
                    split2h(v0, v1, uh, ul);
                    *(uint32_t*)(Chi + rowoff + n) = uh;
                    *(uint32_t*)(Clo + rowoff + n) = ul;
                }
            }
        }
    }
}

// ---------------------------------------------------------------------------
// Tensor-core flash attention, fp16 3-term (unchanged from R6).
// ---------------------------------------------------------------------------
#define AROWB 144
#define AMATB_A (64 * AROWB)
#define ASM_QH   0
#define ASM_QL   AMATB_A
#define ASM_MASK (2 * AMATB_A)
#define ASM_KV   (2 * AMATB_A + 2048)
#define ASTAGEB  (4 * AMATB_A)
#define ATT_SMEM (ASM_KV + 2 * ASTAGEB)

__global__ void __launch_bounds__(128) attn_kernel(
    const __half* __restrict__ QKVh, const __half* __restrict__ QKVl,
    const int* __restrict__ mask,
    __half* __restrict__ Ch, __half* __restrict__ Cl)
{
    extern __shared__ char sm[];
    const uint32_t sb = smem_u32(sm);

    const int qt = blockIdx.x;
    const int bh = blockIdx.y;
    const int b  = bh / NHH;
    const int h  = bh % NHH;
    const int t  = threadIdx.x;
    const int w  = t >> 5, lane = t & 31;

    const int ST = 3 * HH;
    const size_t rowbase = (size_t)b * SS;
    const int qcol = h * DHH, kcol = HH + h * DHH, vcol = 2 * HH + h * DHH;

#pragma unroll
    for (int j = 0; j < 8; j++) {
        const int idx = t + j * 128;
        const int mat = idx >> 9;
        const int rem = idx & 511;
        const int r = rem >> 3, c = rem & 7;
        const size_t g = (rowbase + qt * 64 + r) * ST + qcol + c * 8;
        const uint32_t s = sb + mat * AMATB_A + r * AROWB + c * 16;
        CP16(s, (mat ? QKVl : QKVh) + g);
    }
    {
        float* am = (float*)(sm + ASM_MASK);
#pragma unroll
        for (int j = 0; j < 4; j++) {
            const int i = t + j * 128;
            am[i] = (1.0f - (float)mask[b * SS + i]) * -10000.0f;
        }
    }
    CP_COMMIT();

    auto issueKV = [&](int kt, int s) {
        const uint32_t st = sb + ASM_KV + s * ASTAGEB;
#pragma unroll
        for (int j = 0; j < 16; j++) {
            const int idx = t + j * 128;
            const int mat = idx >> 9;
            const int rem = idx & 511;
            const int r = rem >> 3, c = rem & 7;
            const int col = (mat < 2) ? kcol : vcol;
            const __half* src = (mat & 1) ? QKVl : QKVh;
            const size_t g = (rowbase + kt * 64 + r) * ST + col + c * 8;
            CP16(st + mat * AMATB_A + r * AROWB + c * 16, src + g);
        }
    };
    issueKV(0, 0); CP_COMMIT();

    float m0 = -1e30f, m1 = -1e30f, l0 = 0.f, l1 = 0.f;
    float oacc[8][4];
#pragma unroll
    for (int i = 0; i < 8; i++)
#pragma unroll
        for (int j = 0; j < 4; j++) oacc[i][j] = 0.f;

    const uint32_t a_off = (uint32_t)((w * 16 + (lane & 15)) * AROWB + ((lane >> 4) << 4));
    const uint32_t b_row = (uint32_t)(((lane & 7) | ((lane & 16) >> 1)) * AROWB
                                      + (((lane >> 3) & 1) << 4));
    const uint32_t v_row = (uint32_t)((lane & 15) * AROWB + ((lane >> 4) << 4));
    const float* am = (const float*)(sm + ASM_MASK);

    for (int kt = 0; kt < SS / 64; kt++) {
        const int s = kt & 1;
        if (kt + 1 < SS / 64) { issueKV(kt + 1, s ^ 1); CP_COMMIT(); CP_WAIT(1); }
        else                  { CP_WAIT(0); }
        __syncthreads();

        const uint32_t sK = sb + ASM_KV + s * ASTAGEB;
        const uint32_t sV = sK + 2 * AMATB_A;

        float sacc[8][4];
#pragma unroll
        for (int i = 0; i < 8; i++)
#pragma unroll
            for (int j = 0; j < 4; j++) sacc[i][j] = 0.f;

#pragma unroll
        for (int ks = 0; ks < 4; ks++) {
            const uint32_t ko = ks * 32;
            uint32_t qh[4], ql[4];
            LDM4(qh, sb + ASM_QH + a_off + ko);
            LDM4(ql, sb + ASM_QL + a_off + ko);
#pragma unroll
            for (int n2 = 0; n2 < 4; n2++) {
                uint32_t kh[4], kl[4];
                const uint32_t ba = sK + b_row + n2 * (16 * AROWB) + ko;
                LDM4(kh, ba);
                LDM4(kl, ba + AMATB_A);
#pragma unroll
                for (int hf = 0; hf < 2; hf++) {
                    const int nt = n2 * 2 + hf;
                    MMAF16(sacc[nt], qh, kh[hf * 2], kh[hf * 2 + 1]);
                    MMAF16(sacc[nt], qh, kl[hf * 2], kl[hf * 2 + 1]);
                    MMAF16(sacc[nt], ql, kh[hf * 2], kh[hf * 2 + 1]);
                }
            }
        }

        const int colbase = kt * 64 + (lane & 3) * 2;
        float rmax0 = -1e30f, rmax1 = -1e30f;
#pragma unroll
        for (int nt = 0; nt < 8; nt++) {
            const float a0 = am[colbase + nt * 8];
            const float a1 = am[colbase + nt * 8 + 1];
            sacc[nt][0] = fmaf(sacc[nt][0], 0.125f, a0);
            sacc[nt][1] = fmaf(sacc[nt][1], 0.125f, a1);
            sacc[nt][2] = fmaf(sacc[nt][2], 0.125f, a0);
            sacc[nt][3] = fmaf(sacc[nt][3], 0.125f, a1);
            rmax0 = fmaxf(rmax0, fmaxf(sacc[nt][0], sacc[nt][1]));
            rmax1 = fmaxf(rmax1, fmaxf(sacc[nt][2], sacc[nt][3]));
        }
        rmax0 = fmaxf(rmax0, __shfl_xor_sync(0xffffffffu, rmax0, 1));
        rmax0 = fmaxf(rmax0, __shfl_xor_sync(0xffffffffu, rmax0, 2));
        rmax1 = fmaxf(rmax1, __shfl_xor_sync(0xffffffffu, rmax1, 1));
        rmax1 = fmaxf(rmax1, __shfl_xor_sync(0xffffffffu, rmax1, 2));
        const float nm0 = fmaxf(m0, rmax0), nm1 = fmaxf(m1, rmax1);
        const float sc0 = __expf(m0 - nm0), sc1 = __expf(m1 - nm1);
        m0 = nm0; m1 = nm1;
        l0 *= sc0; l1 *= sc1;
#pragma unroll
        for (int nt = 0; nt < 8; nt++) {
            oacc[nt][0] *= sc0; oacc[nt][1] *= sc0;
            oacc[nt][2] *= sc1; oacc[nt][3] *= sc1;
        }
        float ps0 = 0.f, ps1 = 0.f;
#pragma unroll
        for (int nt = 0; nt < 8; nt++) {
            sacc[nt][0] = __expf(sacc[nt][0] - nm0);
            sacc[nt][1] = __expf(sacc[nt][1] - nm0);
            sacc[nt][2] = __expf(sacc[nt][2] - nm1);
            sacc[nt][3] = __expf(sacc[nt][3] - nm1);
            ps0 += sacc[nt][0] + sacc[nt][1];
            ps1 += sacc[nt][2] + sacc[nt][3];
        }
        l0 += ps0; l1 += ps1;

#pragma unroll
        for (int ks = 0; ks < 4; ks++) {
            uint32_t ah[4], al[4];
#pragma unroll
            for (int pos = 0; pos < 4; pos++) {
                const int nt = 2 * ks + (pos >> 1);
                const int jb = (pos & 1) * 2;
                split2h(sacc[nt][jb], sacc[nt][jb + 1], ah[pos], al[pos]);
            }
#pragma unroll
            for (int dp = 0; dp < 4; dp++) {
                uint32_t vh[4], vl[4];
                const uint32_t va = sV + ks * (16 * AROWB) + v_row + dp * 32;
                LDM4T(vh, va);
                LDM4T(vl, va + AMATB_A);
                MMAF16(oacc[dp * 2],     ah, vh[0], vh[1]);
                MMAF16(oacc[dp * 2],     ah, vl[0], vl[1]);
                MMAF16(oacc[dp * 2],     al, vh[0], vh[1]);
                MMAF16(oacc[dp * 2 + 1], ah, vh[2], vh[3]);
                MMAF16(oacc[dp * 2 + 1], ah, vl[2], vl[3]);
                MMAF16(oacc[dp * 2 + 1], al, vh[2], vh[3]);
            }
        }
        __syncthreads();
    }

    l0 += __shfl_xor_sync(0xffffffffu, l0, 1);
    l0 += __shfl_xor_sync(0xffffffffu, l0, 2);
    l1 += __shfl_xor_sync(0xffffffffu, l1, 1);
    l1 += __shfl_xor_sync(0xffffffffu, l1, 2);
    const float inv0 = 1.0f / l0, inv1 = 1.0f / l1;

    const size_t row0 = (size_t)(b * SS + qt * 64 + w * 16 + (lane >> 2));
    const size_t row1 = row0 + 8;
    const int ocol = h * DHH + (lane & 3) * 2;
#pragma unroll
    for (int nt = 0; nt < 8; nt++) {
        const int n = ocol + nt * 8;
        uint32_t uh, ul;
        split2h(oacc[nt][0] * inv0, oacc[nt][1] * inv0, uh, ul);
        *(uint32_t*)(Ch + row0 * HH + n) = uh;
        *(uint32_t*)(Cl + row0 * HH + n) = ul;
        split2h(oacc[nt][2] * inv1, oacc[nt][3] * inv1, uh, ul);
        *(uint32_t*)(Ch + row1 * HH + n) = uh;
        *(uint32_t*)(Cl + row1 * HH + n) = ul;
    }
}

// ---------------------------------------------------------------------------
// Row-wise LayerNorm; optional fp16 hi side output
// ---------------------------------------------------------------------------
template <int SPLIT>
__global__ void __launch_bounds__(256) ln_kernel(
    const float* __restrict__ X, const float* __restrict__ gg,
    const float* __restrict__ bb, float* __restrict__ Y,
    __half* __restrict__ Yh)
{
    const int row = blockIdx.x;
    const float* x = X + (size_t)row * HH;
    const int c = threadIdx.x;

    const float v0 = x[c];
    const float v1 = x[c + 256];
    const float v2 = x[c + 512];
    float s  = v0 + v1 + v2;
    float s2 = v0 * v0 + v1 * v1 + v2 * v2;

    __shared__ float sa[8], sb2[8];
    __shared__ float stats[2];
    const int lane = threadIdx.x & 31, w = threadIdx.x >> 5;
#pragma unroll
    for (int o = 16; o > 0; o >>= 1) {
        s  += __shfl_down_sync(0xffffffffu, s, o);
        s2 += __shfl_down_sync(0xffffffffu, s2, o);
    }
    if (lane == 0) { sa[w] = s; sb2[w] = s2; }
    __syncthreads();
    if (threadIdx.x == 0) {
        float ts = 0.f, ts2 = 0.f;
#pragma unroll
        for (int i = 0; i < 8; i++) { ts += sa[i]; ts2 += sb2[i]; }
        const float mu  = ts * (1.0f / HH);
        const float var = ts2 * (1.0f / HH) - mu * mu;
        stats[0] = mu;
        stats[1] = rsqrtf(var + LN_EPS);
    }
    __syncthreads();
    const float mu = stats[0], rstd = stats[1];
    const size_t ro = (size_t)row * HH;
#pragma unroll
    for (int j = 0; j < 3; j++) {
        const int cc = c + j * 256;
        const float vv = (j == 0 ? v0 : (j == 1 ? v1 : v2));
        const float y = (vv - mu) * rstd * gg[cc] + bb[cc];
        Y[ro + cc] = y;
        if (SPLIT) Yh[ro + cc] = __float2half_rn(y);
    }
}

// ---------------------------------------------------------------------------
// Launch
// ---------------------------------------------------------------------------
extern "C" void kernel_launch(void* const* d_in, const int* in_sizes, int n_in,
                              void* d_out, int out_size)
{
    (void)in_sizes; (void)n_in; (void)out_size;
    const float* x    = (const float*)d_in[0];
    const int*   mask = (const int*)  d_in[1];
    const float* Wq   = (const float*)d_in[2];
    const float* bq   = (const float*)d_in[3];
    const float* Wk   = (const float*)d_in[4];
    const float* bk   = (const float*)d_in[5];
    const float* Wv   = (const float*)d_in[6];
    const float* bv   = (const float*)d_in[7];
    const float* Wo   = (const float*)d_in[8];
    const float* bo   = (const float*)d_in[9];
    const float* ln1g = (const float*)d_in[10];
    const float* ln1b = (const float*)d_in[11];
    const float* W1   = (const float*)d_in[12];
    const float* b1   = (const float*)d_in[13];
    const float* W2   = (const float*)d_in[14];
    const float* b2   = (const float*)d_in[15];
    const float* ln2g = (const float*)d_in[16];
    const float* ln2b = (const float*)d_in[17];
    float* out = (float*)d_out;

    __half *xh, *qkvh, *qkvl, *ctxh, *ctxl, *h1h, *ffh;
    __half *wqkv, *wo, *w1, *w2;
    float *t1, *h1, *t2, *bqkv;
    cudaGetSymbolAddress((void**)&xh, g_xh);
    cudaGetSymbolAddress((void**)&qkvh, g_qkvh); cudaGetSymbolAddress((void**)&qkvl, g_qkvl);
    cudaGetSymbolAddress((void**)&ctxh, g_ctxh); cudaGetSymbolAddress((void**)&ctxl, g_ctxl);
    cudaGetSymbolAddress((void**)&h1h, g_h1h);
    cudaGetSymbolAddress((void**)&ffh, g_ffh);
    cudaGetSymbolAddress((void**)&wqkv, g_wqkv);
    cudaGetSymbolAddress((void**)&wo, g_wo);
    cudaGetSymbolAddress((void**)&w1, g_w1);
    cudaGetSymbolAddress((void**)&w2, g_w2);
    cudaGetSymbolAddress((void**)&t1, g_t1);
    cudaGetSymbolAddress((void**)&h1, g_h1);
    cudaGetSymbolAddress((void**)&t2, g_t2);
    cudaGetSymbolAddress((void**)&bqkv, g_bqkv);

    constexpr int SM128 = (128 + 128) * ROWB * NSTAGE;   // MT=4
    constexpr int SM64  = (64 + 128) * ROWB * NSTAGE;    // MT=2

    cudaFuncSetAttribute(attn_kernel,
                         cudaFuncAttributeMaxDynamicSharedMemorySize, ATT_SMEM);
    cudaFuncSetAttribute(tc_gemm<0, 4>,
                         cudaFuncAttributeMaxDynamicSharedMemorySize, SM128);
    cudaFuncSetAttribute(tc_gemm<1, 4>,
                         cudaFuncAttributeMaxDynamicSharedMemorySize, SM128);
    cudaFuncSetAttribute(tc_gemm<2, 2>,
                         cudaFuncAttributeMaxDynamicSharedMemorySize, SM64);

    const dim3 tb(32, 8);

    // weight prep: four HxH transposes fused into one launch; W1/W2 separate
    trans_half4_kernel<<<dim3(HH / 32, HH / 32, 4), tb>>>(
        Wq, Wk, Wv, Wo,
        wqkv, wqkv + HH * HH, wqkv + 2 * HH * HH, wo);
    trans_half_kernel<<<dim3(FFF / 32, HH / 32),  tb>>>(W1, w1, HH, FFF);
    trans_half_kernel<<<dim3(HH / 32,  FFF / 32), tb>>>(W2, w2, FFF, HH);
    half_kernel<<<(MM * HH + 255) / 256, 256>>>(x, xh, MM * HH);
    concat3_kernel<<<3, 256>>>(bq, bk, bv, bqkv);

    // fused QKV -> fp16 hi/lo (hi/lo needed by 3-term attention)
    tc_gemm<0, 4><<<dim3(3 * HH / 128, MM / 128), 256, SM128>>>(
        xh, wqkv, bqkv, nullptr, nullptr, qkvh, qkvl, HH, 3 * HH);

    // attention -> ctx fp16 hi/lo
    attn_kernel<<<dim3(SS / 64, BB * NHH), 128, ATT_SMEM>>>(
        qkvh, qkvl, mask, ctxh, ctxl);

    // t1 = ctx @ Wo + bo + x    (BM=64: 6x64 = 384 tiles)
    tc_gemm<2, 2><<<dim3(HH / 128, MM / 64), 256, SM64>>>(
        ctxh, wo, bo, x, t1, nullptr, nullptr, HH, HH);
    ln_kernel<1><<<MM, 256>>>(t1, ln1g, ln1b, h1, h1h);

    // ff = gelu(h1 @ W1 + b1) -> fp16 hi only
    tc_gemm<1, 4><<<dim3(FFF / 128, MM / 128), 256, SM128>>>(
        h1h, w1, b1, nullptr, nullptr, ffh, nullptr, HH, FFF);

    // t2 = ff @ W2 + b2 + h1    (BM=64)
    tc_gemm<2, 2><<<dim3(HH / 128, MM / 64), 256, SM64>>>(
        ffh, w2, b2, h1, t2, nullptr, nullptr, FFF, HH);
    ln_kernel<0><<<MM, 256>>>(t2, ln2g, ln2b, out, nullptr);
}

// round 8
// speedup vs baseline: 5.9374x; 1.0950x over previous
#include <cuda_runtime.h>
#include <cuda_fp16.h>
#include <math.h>
#include <stdint.h>

#define BB   8
#define SS   512
#define HH   768
#define NHH  12
#define DHH  64
#define FFF  3072
#define MM   (BB * SS)
#define LN_EPS 1e-3f

// ---------------------------------------------------------------------------
// Scratch
// ---------------------------------------------------------------------------
__device__ __align__(16) __half g_xh  [MM * HH];
__device__ __align__(16) __half g_qkvh[MM * 3 * HH];
__device__ __align__(16) __half g_qkvl[MM * 3 * HH];
__device__ __align__(16) __half g_ctxh[MM * HH];
__device__ __align__(16) float g_t1 [MM * HH];
__device__ __align__(16) float g_h1 [MM * HH];
__device__ __align__(16) __half g_h1h[MM * HH];
__device__ __align__(16) __half g_ffh[MM * FFF];
__device__ __align__(16) float g_t2 [MM * HH];
__device__ __align__(16) __half g_wqkv[3 * HH * HH];
__device__ __align__(16) float g_bqkv[3 * HH];
__device__ __align__(16) __half g_wo [HH * HH];
__device__ __align__(16) __half g_w1 [FFF * HH];
__device__ __align__(16) __half g_w2 [HH * FFF];

// ---------------------------------------------------------------------------
// PTX wrappers
// ---------------------------------------------------------------------------
__device__ __forceinline__ uint32_t smem_u32(const void* p) {
    uint32_t a;
    asm("{ .reg .u64 t; cvta.to.shared.u64 t, %1; cvt.u32.u64 %0, t; }"
        : "=r"(a) : "l"(p));
    return a;
}
#define LDM4(R, ADDR) \
    asm volatile("ldmatrix.sync.aligned.m8n8.x4.shared.b16 {%0,%1,%2,%3}, [%4];" \
        : "=r"((R)[0]), "=r"((R)[1]), "=r"((R)[2]), "=r"((R)[3]) : "r"(ADDR))
#define LDM4T(R, ADDR) \
    asm volatile("ldmatrix.sync.aligned.m8n8.x4.trans.shared.b16 {%0,%1,%2,%3}, [%4];" \
        : "=r"((R)[0]), "=r"((R)[1]), "=r"((R)[2]), "=r"((R)[3]) : "r"(ADDR))
#define MMAF16(D, A, B0, B1) \
    asm volatile("mma.sync.aligned.m16n8k16.row.col.f32.f16.f16.f32 " \
        "{%0,%1,%2,%3}, {%4,%5,%6,%7}, {%8,%9}, {%0,%1,%2,%3};" \
        : "+f"((D)[0]), "+f"((D)[1]), "+f"((D)[2]), "+f"((D)[3]) \
        : "r"((A)[0]), "r"((A)[1]), "r"((A)[2]), "r"((A)[3]), "r"(B0), "r"(B1))
#define CP16(SADDR, GPTR) \
    asm volatile("cp.async.cg.shared.global [%0], [%1], 16;" \
        :: "r"(SADDR), "l"(GPTR))
#define CP_COMMIT() asm volatile("cp.async.commit_group;" ::: "memory")
#define CP_WAIT(N)  asm volatile("cp.async.wait_group %0;" :: "n"(N) : "memory")

__device__ __forceinline__ float gelu_f(float x) {
    return 0.5f * x * (1.0f + erff(x * 0.70710678118654752f));
}
__device__ __forceinline__ void split2h(float v0, float v1, uint32_t& uh, uint32_t& ul) {
    __half2 h = __floats2half2_rn(v0, v1);
    float l0 = v0 - __half2float(__low2half(h));
    float l1 = v1 - __half2float(__high2half(h));
    __half2 l = __floats2half2_rn(l0, l1);
    uh = *(uint32_t*)&h; ul = *(uint32_t*)&l;
}

// ---------------------------------------------------------------------------
// Prep kernels
// ---------------------------------------------------------------------------
__global__ void __launch_bounds__(256) trans_half4_kernel(
    const float* __restrict__ s0, const float* __restrict__ s1,
    const float* __restrict__ s2, const float* __restrict__ s3,
    __half* __restrict__ d0, __half* __restrict__ d1,
    __half* __restrict__ d2, __half* __restrict__ d3)
{
    const int z = blockIdx.z;
    const float* in = (z == 0) ? s0 : (z == 1) ? s1 : (z == 2) ? s2 : s3;
    __half* out     = (z == 0) ? d0 : (z == 1) ? d1 : (z == 2) ? d2 : d3;
    __shared__ float tile[32][33];
    const int n0 = blockIdx.x * 32, k0 = blockIdx.y * 32;
    const int tx = threadIdx.x, ty = threadIdx.y;
#pragma unroll
    for (int j = 0; j < 32; j += 8)
        tile[ty + j][tx] = in[(size_t)(k0 + ty + j) * HH + n0 + tx];
    __syncthreads();
#pragma unroll
    for (int j = 0; j < 32; j += 8)
        out[(size_t)(n0 + ty + j) * HH + k0 + tx] = __float2half_rn(tile[tx][ty + j]);
}

__global__ void __launch_bounds__(256) trans_half_kernel(
    const float* __restrict__ in, __half* __restrict__ oh, int K, int N)
{
    __shared__ float tile[32][33];
    const int n0 = blockIdx.x * 32, k0 = blockIdx.y * 32;
    const int tx = threadIdx.x, ty = threadIdx.y;
#pragma unroll
    for (int j = 0; j < 32; j += 8)
        tile[ty + j][tx] = in[(size_t)(k0 + ty + j) * N + n0 + tx];
    __syncthreads();
#pragma unroll
    for (int j = 0; j < 32; j += 8)
        oh[(size_t)(n0 + ty + j) * K + k0 + tx] = __float2half_rn(tile[tx][ty + j]);
}

__global__ void __launch_bounds__(256) half4_kernel(
    const float* __restrict__ in, __half* __restrict__ oh, int n4)
{
    const int i = blockIdx.x * 256 + threadIdx.x;
    if (i < n4) {
        const float4 v = *(const float4*)(in + i * 4);
        __half2 h0 = __floats2half2_rn(v.x, v.y);
        __half2 h1 = __floats2half2_rn(v.z, v.w);
        uint2 u; u.x = *(uint32_t*)&h0; u.y = *(uint32_t*)&h1;
        *(uint2*)(oh + i * 4) = u;
    }
}

__global__ void concat3_kernel(const float* __restrict__ a, const float* __restrict__ b,
                               const float* __restrict__ c, float* __restrict__ o)
{
    const int i = blockIdx.x * 256 + threadIdx.x;
    if (i < HH) { o[i] = a[i]; o[HH + i] = b[i]; o[2 * HH + i] = c[i]; }
}

// ---------------------------------------------------------------------------
// GEMM: C[M,Ntot] = A[M,K] @ W[Ntot,K]^T; pure fp16 1-term.
// ---------------------------------------------------------------------------
#define KC 32
#define ROWB 80
#define NSTAGE 3

template <int EPI, int MT>
__global__ void __launch_bounds__(256) tc_gemm(
    const __half* __restrict__ Ahi,
    const __half* __restrict__ Whi,
    const float* __restrict__ bias, const float* __restrict__ resid,
    float* __restrict__ C,
    __half* __restrict__ Chi, __half* __restrict__ Clo,
    int K, int Ntot)
{
    constexpr int BM = MT * 32;
    constexpr int AMATB = BM * ROWB;
    constexpr int BMATB = 128 * ROWB;
    constexpr int STAGEB = AMATB + BMATB;
    constexpr int ACH = BM * 4;
    constexpr int NCHK = (ACH + 512) / 256;

    extern __shared__ char sm[];
    const uint32_t sb = smem_u32(sm);

    const int t    = threadIdx.x;
    const int wid  = t >> 5, lane = t & 31;
    const int wm   = wid >> 2;
    const int wn   = wid & 3;
    const int bn   = blockIdx.x, bm = blockIdx.y;
    const int rbase = bm * BM, cbase = bn * 128;
    const int nch  = K / KC;

    auto issue = [&](int ci) {
        const int s = ci % NSTAGE;
        const uint32_t st = sb + s * STAGEB;
        const int kt = ci * KC;
#pragma unroll
        for (int j = 0; j < NCHK; j++) {
            int id = t + j * 256;
            if (id < ACH) {
                const int r = id >> 2, c = id & 3;
                CP16(st + r * ROWB + c * 16,
                     Ahi + (size_t)(rbase + r) * K + kt + c * 8);
            } else {
                id -= ACH;
                const int r = id >> 2, c = id & 3;
                CP16(st + AMATB + r * ROWB + c * 16,
                     Whi + (size_t)(cbase + r) * K + kt + c * 8);
            }
        }
    };

    float acc[MT][4][4];
#pragma unroll
    for (int i = 0; i < MT; i++)
#pragma unroll
        for (int j = 0; j < 4; j++)
#pragma unroll
            for (int q = 0; q < 4; q++) acc[i][j][q] = 0.f;

    const uint32_t a_off = (uint32_t)((wm * (MT * 16) + (lane & 15)) * ROWB
                                      + ((lane >> 4) << 4));
    const uint32_t b_off = (uint32_t)((wn * 32 + ((lane & 7) | ((lane & 16) >> 1))) * ROWB
                                      + (((lane >> 3) & 1) << 4));

    issue(0); CP_COMMIT();
    issue(1); CP_COMMIT();

    for (int ci = 0; ci < nch; ci++) {
        if (ci + 1 < nch) { CP_WAIT(1); } else { CP_WAIT(0); }
        __syncthreads();
        if (ci + 2 < nch) { issue(ci + 2); CP_COMMIT(); }

        const uint32_t sA  = sb + (ci % NSTAGE) * STAGEB;
        const uint32_t sBh = sA + AMATB;
#pragma unroll
        for (int ks = 0; ks < 2; ks++) {
            const uint32_t ko = ks * 32;
            uint32_t AH[MT][4], BH[2][4];
#pragma unroll
            for (int mt = 0; mt < MT; mt++)
                LDM4(AH[mt], sA + a_off + mt * (16 * ROWB) + ko);
#pragma unroll
            for (int n2 = 0; n2 < 2; n2++)
                LDM4(BH[n2], sBh + b_off + n2 * (16 * ROWB) + ko);
#pragma unroll
            for (int mt = 0; mt < MT; mt++) {
#pragma unroll
                for (int nt = 0; nt < 4; nt++) {
                    const uint32_t b0 = BH[nt >> 1][(nt & 1) * 2];
                    const uint32_t b1 = BH[nt >> 1][(nt & 1) * 2 + 1];
                    MMAF16(acc[mt][nt], AH[mt], b0, b1);
                }
            }
        }
        __syncthreads();
    }

    const int mrow0 = rbase + wm * (MT * 16) + (lane >> 2);
    const int ncol0 = cbase + wn * 32 + (lane & 3) * 2;
#pragma unroll
    for (int mt = 0; mt < MT; mt++) {
#pragma unroll
        for (int half = 0; half < 2; half++) {
            const int m = mrow0 + mt * 16 + half * 8;
            const size_t rowoff = (size_t)m * Ntot;
#pragma unroll
            for (int nt = 0; nt < 4; nt++) {
                const int n = ncol0 + nt * 8;
                float v0 = acc[mt][nt][half * 2 + 0];
                float v1 = acc[mt][nt][half * 2 + 1];
                const float2 bv = *(const float2*)(bias + n);
                v0 += bv.x; v1 += bv.y;
                if (EPI == 2) {
                    const float2 rv = *(const float2*)(resid + rowoff + n);
                    v0 += rv.x; v1 += rv.y;
                    *(float2*)(C + rowoff + n) = make_float2(v0, v1);
                } else if (EPI == 1) {
                    v0 = gelu_f(v0); v1 = gelu_f(v1);
                    __half2 hh = __floats2half2_rn(v0, v1);
                    *(__half2*)(Chi + rowoff + n) = hh;
                } else {
                    uint32_t uh, ul;
                    split2h(v0, v1, uh, ul);
                    *(uint32_t*)(Chi + rowoff + n) = uh;
                    *(uint32_t*)(Clo + rowoff + n) = ul;
                }
            }
        }
    }
}

// ---------------------------------------------------------------------------
// Tensor-core flash attention, fp16 2-term:
//   S = (Qh+Ql) Kh^T ;  O = (Ph+Pl) Vh    (K-lo / V-lo terms dropped)
// grid (8, 96), 128 threads (4 warps). Warp w: q rows [w*16, w*16+16).
// ---------------------------------------------------------------------------
#define AROWB 144
#define AMATB_A (64 * AROWB)
#define ASM_QH   0
#define ASM_QL   AMATB_A
#define ASM_MASK (2 * AMATB_A)
#define ASM_KV   (2 * AMATB_A + 2048)
#define ASTAGEB  (2 * AMATB_A)
#define ATT_SMEM (ASM_KV + 2 * ASTAGEB)

__global__ void __launch_bounds__(128) attn_kernel(
    const __half* __restrict__ QKVh, const __half* __restrict__ QKVl,
    const int* __restrict__ mask,
    __half* __restrict__ Ch)
{
    extern __shared__ char sm[];
    const uint32_t sb = smem_u32(sm);

    const int qt = blockIdx.x;
    const int bh = blockIdx.y;
    const int b  = bh / NHH;
    const int h  = bh % NHH;
    const int t  = threadIdx.x;
    const int w  = t >> 5, lane = t & 31;

    const int ST = 3 * HH;
    const size_t rowbase = (size_t)b * SS;
    const int qcol = h * DHH, kcol = HH + h * DHH, vcol = 2 * HH + h * DHH;

    // Q hi+lo load
#pragma unroll
    for (int j = 0; j < 8; j++) {
        const int idx = t + j * 128;
        const int mat = idx >> 9;
        const int rem = idx & 511;
        const int r = rem >> 3, c = rem & 7;
        const size_t g = (rowbase + qt * 64 + r) * ST + qcol + c * 8;
        const uint32_t s = sb + mat * AMATB_A + r * AROWB + c * 16;
        CP16(s, (mat ? QKVl : QKVh) + g);
    }
    {
        float* am = (float*)(sm + ASM_MASK);
#pragma unroll
        for (int j = 0; j < 4; j++) {
            const int i = t + j * 128;
            am[i] = (1.0f - (float)mask[b * SS + i]) * -10000.0f;
        }
    }
    CP_COMMIT();

    // K-hi + V-hi only
    auto issueKV = [&](int kt, int s) {
        const uint32_t st = sb + ASM_KV + s * ASTAGEB;
#pragma unroll
        for (int j = 0; j < 8; j++) {
            const int idx = t + j * 128;
            const int mat = idx >> 9;            // 0 Kh, 1 Vh
            const int rem = idx & 511;
            const int r = rem >> 3, c = rem & 7;
            const int col = mat ? vcol : kcol;
            const size_t g = (rowbase + kt * 64 + r) * ST + col + c * 8;
            CP16(st + mat * AMATB_A + r * AROWB + c * 16, QKVh + g);
        }
    };
    issueKV(0, 0); CP_COMMIT();

    float m0 = -1e30f, m1 = -1e30f, l0 = 0.f, l1 = 0.f;
    float oacc[8][4];
#pragma unroll
    for (int i = 0; i < 8; i++)
#pragma unroll
        for (int j = 0; j < 4; j++) oacc[i][j] = 0.f;

    const uint32_t a_off = (uint32_t)((w * 16 + (lane & 15)) * AROWB + ((lane >> 4) << 4));
    const uint32_t b_row = (uint32_t)(((lane & 7) | ((lane & 16) >> 1)) * AROWB
                                      + (((lane >> 3) & 1) << 4));
    const uint32_t v_row = (uint32_t)((lane & 15) * AROWB + ((lane >> 4) << 4));
    const float* am = (const float*)(sm + ASM_MASK);

    for (int kt = 0; kt < SS / 64; kt++) {
        const int s = kt & 1;
        if (kt + 1 < SS / 64) { issueKV(kt + 1, s ^ 1); CP_COMMIT(); CP_WAIT(1); }
        else                  { CP_WAIT(0); }
        __syncthreads();

        const uint32_t sK = sb + ASM_KV + s * ASTAGEB;
        const uint32_t sV = sK + AMATB_A;

        float sacc[8][4];
#pragma unroll
        for (int i = 0; i < 8; i++)
#pragma unroll
            for (int j = 0; j < 4; j++) sacc[i][j] = 0.f;

#pragma unroll
        for (int ks = 0; ks < 4; ks++) {
            const uint32_t ko = ks * 32;
            uint32_t qh[4], ql[4];
            LDM4(qh, sb + ASM_QH + a_off + ko);
            LDM4(ql, sb + ASM_QL + a_off + ko);
#pragma unroll
            for (int n2 = 0; n2 < 4; n2++) {
                uint32_t kh[4];
                LDM4(kh, sK + b_row + n2 * (16 * AROWB) + ko);
#pragma unroll
                for (int hf = 0; hf < 2; hf++) {
                    const int nt = n2 * 2 + hf;
                    MMAF16(sacc[nt], qh, kh[hf * 2], kh[hf * 2 + 1]);
                    MMAF16(sacc[nt], ql, kh[hf * 2], kh[hf * 2 + 1]);
                }
            }
        }

        const int colbase = kt * 64 + (lane & 3) * 2;
        float rmax0 = -1e30f, rmax1 = -1e30f;
#pragma unroll
        for (int nt = 0; nt < 8; nt++) {
            const float a0 = am[colbase + nt * 8];
            const float a1 = am[colbase + nt * 8 + 1];
            sacc[nt][0] = fmaf(sacc[nt][0], 0.125f, a0);
            sacc[nt][1] = fmaf(sacc[nt][1], 0.125f, a1);
            sacc[nt][2] = fmaf(sacc[nt][2], 0.125f, a0);
            sacc[nt][3] = fmaf(sacc[nt][3], 0.125f, a1);
            rmax0 = fmaxf(rmax0, fmaxf(sacc[nt][0], sacc[nt][1]));
            rmax1 = fmaxf(rmax1, fmaxf(sacc[nt][2], sacc[nt][3]));
        }
        rmax0 = fmaxf(rmax0, __shfl_xor_sync(0xffffffffu, rmax0, 1));
        rmax0 = fmaxf(rmax0, __shfl_xor_sync(0xffffffffu, rmax0, 2));
        rmax1 = fmaxf(rmax1, __shfl_xor_sync(0xffffffffu, rmax1, 1));
        rmax1 = fmaxf(rmax1, __shfl_xor_sync(0xffffffffu, rmax1, 2));
        const float nm0 = fmaxf(m0, rmax0), nm1 = fmaxf(m1, rmax1);
        const float sc0 = __expf(m0 - nm0), sc1 = __expf(m1 - nm1);
        m0 = nm0; m1 = nm1;
        l0 *= sc0; l1 *= sc1;
#pragma unroll
        for (int nt = 0; nt < 8; nt++) {
            oacc[nt][0] *= sc0; oacc[nt][1] *= sc0;
            oacc[nt][2] *= sc1; oacc[nt][3] *= sc1;
        }
        float ps0 = 0.f, ps1 = 0.f;
#pragma unroll
        for (int nt = 0; nt < 8; nt++) {
            sacc[nt][0] = __expf(sacc[nt][0] - nm0);
            sacc[nt][1] = __expf(sacc[nt][1] - nm0);
            sacc[nt][2] = __expf(sacc[nt][2] - nm1);
            sacc[nt][3] = __expf(sacc[nt][3] - nm1);
            ps0 += sacc[nt][0] + sacc[nt][1];
            ps1 += sacc[nt][2] + sacc[nt][3];
        }
        l0 += ps0; l1 += ps1;

#pragma unroll
        for (int ks = 0; ks < 4; ks++) {
            uint32_t ah[4], al[4];
#pragma unroll
            for (int pos = 0; pos < 4; pos++) {
                const int nt = 2 * ks + (pos >> 1);
                const int jb = (pos & 1) * 2;
                split2h(sacc[nt][jb], sacc[nt][jb + 1], ah[pos], al[pos]);
            }
#pragma unroll
            for (int dp = 0; dp < 4; dp++) {
                uint32_t vh[4];
                LDM4T(vh, sV + ks * (16 * AROWB) + v_row + dp * 32);
                MMAF16(oacc[dp * 2],     ah, vh[0], vh[1]);
                MMAF16(oacc[dp * 2],     al, vh[0], vh[1]);
                MMAF16(oacc[dp * 2 + 1], ah, vh[2], vh[3]);
                MMAF16(oacc[dp * 2 + 1], al, vh[2], vh[3]);
            }
        }
        __syncthreads();
    }

    l0 += __shfl_xor_sync(0xffffffffu, l0, 1);
    l0 += __shfl_xor_sync(0xffffffffu, l0, 2);
    l1 += __shfl_xor_sync(0xffffffffu, l1, 1);
    l1 += __shfl_xor_sync(0xffffffffu, l1, 2);
    const float inv0 = 1.0f / l0, inv1 = 1.0f / l1;

    const size_t row0 = (size_t)(b * SS + qt * 64 + w * 16 + (lane >> 2));
    const size_t row1 = row0 + 8;
    const int ocol = h * DHH + (lane & 3) * 2;
#pragma unroll
    for (int nt = 0; nt < 8; nt++) {
        const int n = ocol + nt * 8;
        __half2 h0 = __floats2half2_rn(oacc[nt][0] * inv0, oacc[nt][1] * inv0);
        __half2 h1 = __floats2half2_rn(oacc[nt][2] * inv1, oacc[nt][3] * inv1);
        *(__half2*)(Ch + row0 * HH + n) = h0;
        *(__half2*)(Ch + row1 * HH + n) = h1;
    }
}

// ---------------------------------------------------------------------------
// Row-wise LayerNorm; optional fp16 hi side output
// ---------------------------------------------------------------------------
template <int SPLIT>
__global__ void __launch_bounds__(256) ln_kernel(
    const float* __restrict__ X, const float* __restrict__ gg,
    const float* __restrict__ bb, float* __restrict__ Y,
    __half* __restrict__ Yh)
{
    const int row = blockIdx.x;
    const float* x = X + (size_t)row * HH;
    const int c = threadIdx.x;

    const float v0 = x[c];
    const float v1 = x[c + 256];
    const float v2 = x[c + 512];
    float s  = v0 + v1 + v2;
    float s2 = v0 * v0 + v1 * v1 + v2 * v2;

    __shared__ float sa[8], sb2[8];
    __shared__ float stats[2];
    const int lane = threadIdx.x & 31, w = threadIdx.x >> 5;
#pragma unroll
    for (int o = 16; o > 0; o >>= 1) {
        s  += __shfl_down_sync(0xffffffffu, s, o);
        s2 += __shfl_down_sync(0xffffffffu, s2, o);
    }
    if (lane == 0) { sa[w] = s; sb2[w] = s2; }
    __syncthreads();
    if (threadIdx.x == 0) {
        float ts = 0.f, ts2 = 0.f;
#pragma unroll
        for (int i = 0; i < 8; i++) { ts += sa[i]; ts2 += sb2[i]; }
        const float mu  = ts * (1.0f / HH);
        const float var = ts2 * (1.0f / HH) - mu * mu;
        stats[0] = mu;
        stats[1] = rsqrtf(var + LN_EPS);
    }
    __syncthreads();
    const float mu = stats[0], rstd = stats[1];
    const size_t ro = (size_t)row * HH;
#pragma unroll
    for (int j = 0; j < 3; j++) {
        const int cc = c + j * 256;
        const float vv = (j == 0 ? v0 : (j == 1 ? v1 : v2));
        const float y = (vv - mu) * rstd * gg[cc] + bb[cc];
        Y[ro + cc] = y;
        if (SPLIT) Yh[ro + cc] = __float2half_rn(y);
    }
}

// ---------------------------------------------------------------------------
// Launch
// ---------------------------------------------------------------------------
extern "C" void kernel_launch(void* const* d_in, const int* in_sizes, int n_in,
                              void* d_out, int out_size)
{
    (void)in_sizes; (void)n_in; (void)out_size;
    const float* x    = (const float*)d_in[0];
    const int*   mask = (const int*)  d_in[1];
    const float* Wq   = (const float*)d_in[2];
    const float* bq   = (const float*)d_in[3];
    const float* Wk   = (const float*)d_in[4];
    const float* bk   = (const float*)d_in[5];
    const float* Wv   = (const float*)d_in[6];
    const float* bv   = (const float*)d_in[7];
    const float* Wo   = (const float*)d_in[8];
    const float* bo   = (const float*)d_in[9];
    const float* ln1g = (const float*)d_in[10];
    const float* ln1b = (const float*)d_in[11];
    const float* W1   = (const float*)d_in[12];
    const float* b1   = (const float*)d_in[13];
    const float* W2   = (const float*)d_in[14];
    const float* b2   = (const float*)d_in[15];
    const float* ln2g = (const float*)d_in[16];
    const float* ln2b = (const float*)d_in[17];
    float* out = (float*)d_out;

    __half *xh, *qkvh, *qkvl, *ctxh, *h1h, *ffh;
    __half *wqkv, *wo, *w1, *w2;
    float *t1, *h1, *t2, *bqkv;
    cudaGetSymbolAddress((void**)&xh, g_xh);
    cudaGetSymbolAddress((void**)&qkvh, g_qkvh); cudaGetSymbolAddress((void**)&qkvl, g_qkvl);
    cudaGetSymbolAddress((void**)&ctxh, g_ctxh);
    cudaGetSymbolAddress((void**)&h1h, g_h1h);
    cudaGetSymbolAddress((void**)&ffh, g_ffh);
    cudaGetSymbolAddress((void**)&wqkv, g_wqkv);
    cudaGetSymbolAddress((void**)&wo, g_wo);
    cudaGetSymbolAddress((void**)&w1, g_w1);
    cudaGetSymbolAddress((void**)&w2, g_w2);
    cudaGetSymbolAddress((void**)&t1, g_t1);
    cudaGetSymbolAddress((void**)&h1, g_h1);
    cudaGetSymbolAddress((void**)&t2, g_t2);
    cudaGetSymbolAddress((void**)&bqkv, g_bqkv);

    constexpr int SM128 = (128 + 128) * ROWB * NSTAGE;   // MT=4
    constexpr int SM64  = (64 + 128) * ROWB * NSTAGE;    // MT=2

    cudaFuncSetAttribute(attn_kernel,
                         cudaFuncAttributeMaxDynamicSharedMemorySize, ATT_SMEM);
    cudaFuncSetAttribute(tc_gemm<0, 4>,
                         cudaFuncAttributeMaxDynamicSharedMemorySize, SM128);
    cudaFuncSetAttribute(tc_gemm<1, 4>,
                         cudaFuncAttributeMaxDynamicSharedMemorySize, SM128);
    cudaFuncSetAttribute(tc_gemm<2, 2>,
                         cudaFuncAttributeMaxDynamicSharedMemorySize, SM64);

    const dim3 tb(32, 8);

    trans_half4_kernel<<<dim3(HH / 32, HH / 32, 4), tb>>>(
        Wq, Wk, Wv, Wo,
        wqkv, wqkv + HH * HH, wqkv + 2 * HH * HH, wo);
    trans_half_kernel<<<dim3(FFF / 32, HH / 32),  tb>>>(W1, w1, HH, FFF);
    trans_half_kernel<<<dim3(HH / 32,  FFF / 32), tb>>>(W2, w2, FFF, HH);
    half4_kernel<<<(MM * HH / 4 + 255) / 256, 256>>>(x, xh, MM * HH / 4);
    concat3_kernel<<<3, 256>>>(bq, bk, bv, bqkv);

    // fused QKV -> fp16 hi/lo (lo needed for Q term of attention)
    tc_gemm<0, 4><<<dim3(3 * HH / 128, MM / 128), 256, SM128>>>(
        xh, wqkv, bqkv, nullptr, nullptr, qkvh, qkvl, HH, 3 * HH);

    // attention -> ctx fp16 (hi only; Wo GEMM is 1-term)
    attn_kernel<<<dim3(SS / 64, BB * NHH), 128, ATT_SMEM>>>(
        qkvh, qkvl, mask, ctxh);

    // t1 = ctx @ Wo + bo + x
    tc_gemm<2, 2><<<dim3(HH / 128, MM / 64), 256, SM64>>>(
        ctxh, wo, bo, x, t1, nullptr, nullptr, HH, HH);
    ln_kernel<1><<<MM, 256>>>(t1, ln1g, ln1b, h1, h1h);

    // ff = gelu(h1 @ W1 + b1) -> fp16 hi
    tc_gemm<1, 4><<<dim3(FFF / 128, MM / 128), 256, SM128>>>(
        h1h, w1, b1, nullptr, nullptr, ffh, nullptr, HH, FFF);

    // t2 = ff @ W2 + b2 + h1
    tc_gemm<2, 2><<<dim3(HH / 128, MM / 64), 256, SM64>>>(
        ffh, w2, b2, h1, t2, nullptr, nullptr, FFF, HH);
    ln_kernel<0><<<MM, 256>>>(t2, ln2g, ln2b, out, nullptr);
}

// round 9
// speedup vs baseline: 6.2326x; 1.0497x over previous
#include <cuda_runtime.h>
#include <cuda_fp16.h>
#include <math.h>
#include <stdint.h>

#define BB   8
#define SS   512
#define HH   768
#define NHH  12
#define DHH  64
#define FFF  3072
#define MM   (BB * SS)
#define LN_EPS 1e-3f

// ---------------------------------------------------------------------------
// Scratch
// ---------------------------------------------------------------------------
__device__ __align__(16) __half g_xh  [MM * HH];
__device__ __align__(16) __half g_qkvh[MM * 3 * HH];
__device__ __align__(16) __half g_ctxh[MM * HH];
__device__ __align__(16) float g_t1 [MM * HH];
__device__ __align__(16) float g_h1 [MM * HH];
__device__ __align__(16) __half g_h1h[MM * HH];
__device__ __align__(16) __half g_ffh[MM * FFF];
__device__ __align__(16) float g_t2 [MM * HH];
__device__ __align__(16) __half g_wqkv[3 * HH * HH];
__device__ __align__(16) float g_bqkv[3 * HH];
__device__ __align__(16) __half g_wo [HH * HH];
__device__ __align__(16) __half g_w1 [FFF * HH];
__device__ __align__(16) __half g_w2 [HH * FFF];

// ---------------------------------------------------------------------------
// PTX wrappers
// ---------------------------------------------------------------------------
__device__ __forceinline__ uint32_t smem_u32(const void* p) {
    uint32_t a;
    asm("{ .reg .u64 t; cvta.to.shared.u64 t, %1; cvt.u32.u64 %0, t; }"
        : "=r"(a) : "l"(p));
    return a;
}
#define LDM4(R, ADDR) \
    asm volatile("ldmatrix.sync.aligned.m8n8.x4.shared.b16 {%0,%1,%2,%3}, [%4];" \
        : "=r"((R)[0]), "=r"((R)[1]), "=r"((R)[2]), "=r"((R)[3]) : "r"(ADDR))
#define LDM4T(R, ADDR) \
    asm volatile("ldmatrix.sync.aligned.m8n8.x4.trans.shared.b16 {%0,%1,%2,%3}, [%4];" \
        : "=r"((R)[0]), "=r"((R)[1]), "=r"((R)[2]), "=r"((R)[3]) : "r"(ADDR))
#define MMAF16(D, A, B0, B1) \
    asm volatile("mma.sync.aligned.m16n8k16.row.col.f32.f16.f16.f32 " \
        "{%0,%1,%2,%3}, {%4,%5,%6,%7}, {%8,%9}, {%0,%1,%2,%3};" \
        : "+f"((D)[0]), "+f"((D)[1]), "+f"((D)[2]), "+f"((D)[3]) \
        : "r"((A)[0]), "r"((A)[1]), "r"((A)[2]), "r"((A)[3]), "r"(B0), "r"(B1))
#define CP16(SADDR, GPTR) \
    asm volatile("cp.async.cg.shared.global [%0], [%1], 16;" \
        :: "r"(SADDR), "l"(GPTR))
#define CP_COMMIT() asm volatile("cp.async.commit_group;" ::: "memory")
#define CP_WAIT(N)  asm volatile("cp.async.wait_group %0;" :: "n"(N) : "memory")

__device__ __forceinline__ float gelu_f(float x) {
    return 0.5f * x * (1.0f + erff(x * 0.70710678118654752f));
}

// ---------------------------------------------------------------------------
// Prep kernels
// ---------------------------------------------------------------------------
__global__ void __launch_bounds__(256) trans_half4_kernel(
    const float* __restrict__ s0, const float* __restrict__ s1,
    const float* __restrict__ s2, const float* __restrict__ s3,
    __half* __restrict__ d0, __half* __restrict__ d1,
    __half* __restrict__ d2, __half* __restrict__ d3)
{
    const int z = blockIdx.z;
    const float* in = (z == 0) ? s0 : (z == 1) ? s1 : (z == 2) ? s2 : s3;
    __half* out     = (z == 0) ? d0 : (z == 1) ? d1 : (z == 2) ? d2 : d3;
    __shared__ float tile[32][33];
    const int n0 = blockIdx.x * 32, k0 = blockIdx.y * 32;
    const int tx = threadIdx.x, ty = threadIdx.y;
#pragma unroll
    for (int j = 0; j < 32; j += 8)
        tile[ty + j][tx] = in[(size_t)(k0 + ty + j) * HH + n0 + tx];
    __syncthreads();
#pragma unroll
    for (int j = 0; j < 32; j += 8)
        out[(size_t)(n0 + ty + j) * HH + k0 + tx] = __float2half_rn(tile[tx][ty + j]);
}

__global__ void __launch_bounds__(256) trans_half_kernel(
    const float* __restrict__ in, __half* __restrict__ oh, int K, int N)
{
    __shared__ float tile[32][33];
    const int n0 = blockIdx.x * 32, k0 = blockIdx.y * 32;
    const int tx = threadIdx.x, ty = threadIdx.y;
#pragma unroll
    for (int j = 0; j < 32; j += 8)
        tile[ty + j][tx] = in[(size_t)(k0 + ty + j) * N + n0 + tx];
    __syncthreads();
#pragma unroll
    for (int j = 0; j < 32; j += 8)
        oh[(size_t)(n0 + ty + j) * K + k0 + tx] = __float2half_rn(tile[tx][ty + j]);
}

__global__ void __launch_bounds__(256) half4_kernel(
    const float* __restrict__ in, __half* __restrict__ oh, int n4)
{
    const int i = blockIdx.x * 256 + threadIdx.x;
    if (i < n4) {
        const float4 v = *(const float4*)(in + i * 4);
        __half2 h0 = __floats2half2_rn(v.x, v.y);
        __half2 h1 = __floats2half2_rn(v.z, v.w);
        uint2 u; u.x = *(uint32_t*)&h0; u.y = *(uint32_t*)&h1;
        *(uint2*)(oh + i * 4) = u;
    }
}

__global__ void concat3_kernel(const float* __restrict__ a, const float* __restrict__ b,
                               const float* __restrict__ c, float* __restrict__ o)
{
    const int i = blockIdx.x * 256 + threadIdx.x;
    if (i < HH) { o[i] = a[i]; o[HH + i] = b[i]; o[2 * HH + i] = c[i]; }
}

// ---------------------------------------------------------------------------
// GEMM: C[M,Ntot] = A[M,K] @ W[Ntot,K]^T; pure fp16 1-term.
//   EPI 0: bias -> fp16; 1: bias+GELU -> fp16; 2: bias+resid -> fp32
// ---------------------------------------------------------------------------
#define KC 32
#define ROWB 80
#define NSTAGE 3

template <int EPI, int MT>
__global__ void __launch_bounds__(256) tc_gemm(
    const __half* __restrict__ Ahi,
    const __half* __restrict__ Whi,
    const float* __restrict__ bias, const float* __restrict__ resid,
    float* __restrict__ C, __half* __restrict__ Chi,
    int K, int Ntot)
{
    constexpr int BM = MT * 32;
    constexpr int AMATB = BM * ROWB;
    constexpr int BMATB = 128 * ROWB;
    constexpr int STAGEB = AMATB + BMATB;
    constexpr int ACH = BM * 4;
    constexpr int NCHK = (ACH + 512) / 256;

    extern __shared__ char sm[];
    const uint32_t sb = smem_u32(sm);

    const int t    = threadIdx.x;
    const int wid  = t >> 5, lane = t & 31;
    const int wm   = wid >> 2;
    const int wn   = wid & 3;
    const int bn   = blockIdx.x, bm = blockIdx.y;
    const int rbase = bm * BM, cbase = bn * 128;
    const int nch  = K / KC;

    auto issue = [&](int ci) {
        const int s = ci % NSTAGE;
        const uint32_t st = sb + s * STAGEB;
        const int kt = ci * KC;
#pragma unroll
        for (int j = 0; j < NCHK; j++) {
            int id = t + j * 256;
            if (id < ACH) {
                const int r = id >> 2, c = id & 3;
                CP16(st + r * ROWB + c * 16,
                     Ahi + (size_t)(rbase + r) * K + kt + c * 8);
            } else {
                id -= ACH;
                const int r = id >> 2, c = id & 3;
                CP16(st + AMATB + r * ROWB + c * 16,
                     Whi + (size_t)(cbase + r) * K + kt + c * 8);
            }
        }
    };

    float acc[MT][4][4];
#pragma unroll
    for (int i = 0; i < MT; i++)
#pragma unroll
        for (int j = 0; j < 4; j++)
#pragma unroll
            for (int q = 0; q < 4; q++) acc[i][j][q] = 0.f;

    const uint32_t a_off = (uint32_t)((wm * (MT * 16) + (lane & 15)) * ROWB
                                      + ((lane >> 4) << 4));
    const uint32_t b_off = (uint32_t)((wn * 32 + ((lane & 7) | ((lane & 16) >> 1))) * ROWB
                                      + (((lane >> 3) & 1) << 4));

    issue(0); CP_COMMIT();
    issue(1); CP_COMMIT();

    for (int ci = 0; ci < nch; ci++) {
        if (ci + 1 < nch) { CP_WAIT(1); } else { CP_WAIT(0); }
        __syncthreads();
        if (ci + 2 < nch) { issue(ci + 2); CP_COMMIT(); }

        const uint32_t sA  = sb + (ci % NSTAGE) * STAGEB;
        const uint32_t sBh = sA + AMATB;
#pragma unroll
        for (int ks = 0; ks < 2; ks++) {
            const uint32_t ko = ks * 32;
            uint32_t AH[MT][4], BH[2][4];
#pragma unroll
            for (int mt = 0; mt < MT; mt++)
                LDM4(AH[mt], sA + a_off + mt * (16 * ROWB) + ko);
#pragma unroll
            for (int n2 = 0; n2 < 2; n2++)
                LDM4(BH[n2], sBh + b_off + n2 * (16 * ROWB) + ko);
#pragma unroll
            for (int mt = 0; mt < MT; mt++) {
#pragma unroll
                for (int nt = 0; nt < 4; nt++) {
                    const uint32_t b0 = BH[nt >> 1][(nt & 1) * 2];
                    const uint32_t b1 = BH[nt >> 1][(nt & 1) * 2 + 1];
                    MMAF16(acc[mt][nt], AH[mt], b0, b1);
                }
            }
        }
        __syncthreads();
    }

    const int mrow0 = rbase + wm * (MT * 16) + (lane >> 2);
    const int ncol0 = cbase + wn * 32 + (lane & 3) * 2;
#pragma unroll
    for (int mt = 0; mt < MT; mt++) {
#pragma unroll
        for (int half = 0; half < 2; half++) {
            const int m = mrow0 + mt * 16 + half * 8;
            const size_t rowoff = (size_t)m * Ntot;
#pragma unroll
            for (int nt = 0; nt < 4; nt++) {
                const int n = ncol0 + nt * 8;
                float v0 = acc[mt][nt][half * 2 + 0];
                float v1 = acc[mt][nt][half * 2 + 1];
                const float2 bv = *(const float2*)(bias + n);
                v0 += bv.x; v1 += bv.y;
                if (EPI == 2) {
                    const float2 rv = *(const float2*)(resid + rowoff + n);
                    v0 += rv.x; v1 += rv.y;
                    *(float2*)(C + rowoff + n) = make_float2(v0, v1);
                } else {
                    if (EPI == 1) { v0 = gelu_f(v0); v1 = gelu_f(v1); }
                    __half2 hh = __floats2half2_rn(v0, v1);
                    *(__half2*)(Chi + rowoff + n) = hh;
                }
            }
        }
    }
}

// ---------------------------------------------------------------------------
// Tensor-core flash attention, pure fp16 1-term.
// grid (8, 96), 128 threads (4 warps). Warp w: q rows [w*16, w*16+16).
// ---------------------------------------------------------------------------
#define AROWB 144
#define AMATB_A (64 * AROWB)
#define ASM_QH   0
#define ASM_MASK AMATB_A
#define ASM_KV   (AMATB_A + 2048)
#define ASTAGEB  (2 * AMATB_A)
#define ATT_SMEM (ASM_KV + 2 * ASTAGEB)

__global__ void __launch_bounds__(128) attn_kernel(
    const __half* __restrict__ QKVh,
    const int* __restrict__ mask,
    __half* __restrict__ Ch)
{
    extern __shared__ char sm[];
    const uint32_t sb = smem_u32(sm);

    const int qt = blockIdx.x;
    const int bh = blockIdx.y;
    const int b  = bh / NHH;
    const int h  = bh % NHH;
    const int t  = threadIdx.x;
    const int w  = t >> 5, lane = t & 31;

    const int ST = 3 * HH;
    const size_t rowbase = (size_t)b * SS;
    const int qcol = h * DHH, kcol = HH + h * DHH, vcol = 2 * HH + h * DHH;

    // Q hi load: 512 chunks, 4 per thread
#pragma unroll
    for (int j = 0; j < 4; j++) {
        const int idx = t + j * 128;
        const int r = idx >> 3, c = idx & 7;
        const size_t g = (rowbase + qt * 64 + r) * ST + qcol + c * 8;
        CP16(sb + r * AROWB + c * 16, QKVh + g);
    }
    {
        float* am = (float*)(sm + ASM_MASK);
#pragma unroll
        for (int j = 0; j < 4; j++) {
            const int i = t + j * 128;
            am[i] = (1.0f - (float)mask[b * SS + i]) * -10000.0f;
        }
    }
    CP_COMMIT();

    auto issueKV = [&](int kt, int s) {
        const uint32_t st = sb + ASM_KV + s * ASTAGEB;
#pragma unroll
        for (int j = 0; j < 8; j++) {
            const int idx = t + j * 128;
            const int mat = idx >> 9;            // 0 Kh, 1 Vh
            const int rem = idx & 511;
            const int r = rem >> 3, c = rem & 7;
            const int col = mat ? vcol : kcol;
            const size_t g = (rowbase + kt * 64 + r) * ST + col + c * 8;
            CP16(st + mat * AMATB_A + r * AROWB + c * 16, QKVh + g);
        }
    };
    issueKV(0, 0); CP_COMMIT();

    float m0 = -1e30f, m1 = -1e30f, l0 = 0.f, l1 = 0.f;
    float oacc[8][4];
#pragma unroll
    for (int i = 0; i < 8; i++)
#pragma unroll
        for (int j = 0; j < 4; j++) oacc[i][j] = 0.f;

    const uint32_t a_off = (uint32_t)((w * 16 + (lane & 15)) * AROWB + ((lane >> 4) << 4));
    const uint32_t b_row = (uint32_t)(((lane & 7) | ((lane & 16) >> 1)) * AROWB
                                      + (((lane >> 3) & 1) << 4));
    const uint32_t v_row = (uint32_t)((lane & 15) * AROWB + ((lane >> 4) << 4));
    const float* am = (const float*)(sm + ASM_MASK);

    for (int kt = 0; kt < SS / 64; kt++) {
        const int s = kt & 1;
        if (kt + 1 < SS / 64) { issueKV(kt + 1, s ^ 1); CP_COMMIT(); CP_WAIT(1); }
        else                  { CP_WAIT(0); }
        __syncthreads();

        const uint32_t sK = sb + ASM_KV + s * ASTAGEB;
        const uint32_t sV = sK + AMATB_A;

        float sacc[8][4];
#pragma unroll
        for (int i = 0; i < 8; i++)
#pragma unroll
            for (int j = 0; j < 4; j++) sacc[i][j] = 0.f;

#pragma unroll
        for (int ks = 0; ks < 4; ks++) {
            const uint32_t ko = ks * 32;
            uint32_t qh[4];
            LDM4(qh, sb + ASM_QH + a_off + ko);
#pragma unroll
            for (int n2 = 0; n2 < 4; n2++) {
                uint32_t kh[4];
                LDM4(kh, sK + b_row + n2 * (16 * AROWB) + ko);
                MMAF16(sacc[n2 * 2],     qh, kh[0], kh[1]);
                MMAF16(sacc[n2 * 2 + 1], qh, kh[2], kh[3]);
            }
        }

        const int colbase = kt * 64 + (lane & 3) * 2;
        float rmax0 = -1e30f, rmax1 = -1e30f;
#pragma unroll
        for (int nt = 0; nt < 8; nt++) {
            const float a0 = am[colbase + nt * 8];
            const float a1 = am[colbase + nt * 8 + 1];
            sacc[nt][0] = fmaf(sacc[nt][0], 0.125f, a0);
            sacc[nt][1] = fmaf(sacc[nt][1], 0.125f, a1);
            sacc[nt][2] = fmaf(sacc[nt][2], 0.125f, a0);
            sacc[nt][3] = fmaf(sacc[nt][3], 0.125f, a1);
            rmax0 = fmaxf(rmax0, fmaxf(sacc[nt][0], sacc[nt][1]));
            rmax1 = fmaxf(rmax1, fmaxf(sacc[nt][2], sacc[nt][3]));
        }
        rmax0 = fmaxf(rmax0, __shfl_xor_sync(0xffffffffu, rmax0, 1));
        rmax0 = fmaxf(rmax0, __shfl_xor_sync(0xffffffffu, rmax0, 2));
        rmax1 = fmaxf(rmax1, __shfl_xor_sync(0xffffffffu, rmax1, 1));
        rmax1 = fmaxf(rmax1, __shfl_xor_sync(0xffffffffu, rmax1, 2));
        const float nm0 = fmaxf(m0, rmax0), nm1 = fmaxf(m1, rmax1);
        const float sc0 = __expf(m0 - nm0), sc1 = __expf(m1 - nm1);
        m0 = nm0; m1 = nm1;
        l0 *= sc0; l1 *= sc1;
#pragma unroll
        for (int nt = 0; nt < 8; nt++) {
            oacc[nt][0] *= sc0; oacc[nt][1] *= sc0;
            oacc[nt][2] *= sc1; oacc[nt][3] *= sc1;
        }
        float ps0 = 0.f, ps1 = 0.f;
#pragma unroll
        for (int nt = 0; nt < 8; nt++) {
            sacc[nt][0] = __expf(sacc[nt][0] - nm0);
            sacc[nt][1] = __expf(sacc[nt][1] - nm0);
            sacc[nt][2] = __expf(sacc[nt][2] - nm1);
            sacc[nt][3] = __expf(sacc[nt][3] - nm1);
            ps0 += sacc[nt][0] + sacc[nt][1];
            ps1 += sacc[nt][2] + sacc[nt][3];
        }
        l0 += ps0; l1 += ps1;

#pragma unroll
        for (int ks = 0; ks < 4; ks++) {
            uint32_t ah[4];
#pragma unroll
            for (int pos = 0; pos < 4; pos++) {
                const int nt = 2 * ks + (pos >> 1);
                const int jb = (pos & 1) * 2;
                __half2 hh = __floats2half2_rn(sacc[nt][jb], sacc[nt][jb + 1]);
                ah[pos] = *(uint32_t*)&hh;
            }
#pragma unroll
            for (int dp = 0; dp < 4; dp++) {
                uint32_t vh[4];
                LDM4T(vh, sV + ks * (16 * AROWB) + v_row + dp * 32);
                MMAF16(oacc[dp * 2],     ah, vh[0], vh[1]);
                MMAF16(oacc[dp * 2 + 1], ah, vh[2], vh[3]);
            }
        }
        __syncthreads();
    }

    l0 += __shfl_xor_sync(0xffffffffu, l0, 1);
    l0 += __shfl_xor_sync(0xffffffffu, l0, 2);
    l1 += __shfl_xor_sync(0xffffffffu, l1, 1);
    l1 += __shfl_xor_sync(0xffffffffu, l1, 2);
    const float inv0 = 1.0f / l0, inv1 = 1.0f / l1;

    const size_t row0 = (size_t)(b * SS + qt * 64 + w * 16 + (lane >> 2));
    const size_t row1 = row0 + 8;
    const int ocol = h * DHH + (lane & 3) * 2;
#pragma unroll
    for (int nt = 0; nt < 8; nt++) {
        const int n = ocol + nt * 8;
        __half2 h0 = __floats2half2_rn(oacc[nt][0] * inv0, oacc[nt][1] * inv0);
        __half2 h1 = __floats2half2_rn(oacc[nt][2] * inv1, oacc[nt][3] * inv1);
        *(__half2*)(Ch + row0 * HH + n) = h0;
        *(__half2*)(Ch + row1 * HH + n) = h1;
    }
}

// ---------------------------------------------------------------------------
// Row-wise LayerNorm; optional fp16 hi side output
// ---------------------------------------------------------------------------
template <int SPLIT>
__global__ void __launch_bounds__(256) ln_kernel(
    const float* __restrict__ X, const float* __restrict__ gg,
    const float* __restrict__ bb, float* __restrict__ Y,
    __half* __restrict__ Yh)
{
    const int row = blockIdx.x;
    const float* x = X + (size_t)row * HH;
    const int c = threadIdx.x;

    const float v0 = x[c];
    const float v1 = x[c + 256];
    const float v2 = x[c + 512];
    float s  = v0 + v1 + v2;
    float s2 = v0 * v0 + v1 * v1 + v2 * v2;

    __shared__ float sa[8], sb2[8];
    __shared__ float stats[2];
    const int lane = threadIdx.x & 31, w = threadIdx.x >> 5;
#pragma unroll
    for (int o = 16; o > 0; o >>= 1) {
        s  += __shfl_down_sync(0xffffffffu, s, o);
        s2 += __shfl_down_sync(0xffffffffu, s2, o);
    }
    if (lane == 0) { sa[w] = s; sb2[w] = s2; }
    __syncthreads();
    if (threadIdx.x == 0) {
        float ts = 0.f, ts2 = 0.f;
#pragma unroll
        for (int i = 0; i < 8; i++) { ts += sa[i]; ts2 += sb2[i]; }
        const float mu  = ts * (1.0f / HH);
        const float var = ts2 * (1.0f / HH) - mu * mu;
        stats[0] = mu;
        stats[1] = rsqrtf(var + LN_EPS);
    }
    __syncthreads();
    const float mu = stats[0], rstd = stats[1];
    const size_t ro = (size_t)row * HH;
#pragma unroll
    for (int j = 0; j < 3; j++) {
        const int cc = c + j * 256;
        const float vv = (j == 0 ? v0 : (j == 1 ? v1 : v2));
        const float y = (vv - mu) * rstd * gg[cc] + bb[cc];
        Y[ro + cc] = y;
        if (SPLIT) Yh[ro + cc] = __float2half_rn(y);
    }
}

// ---------------------------------------------------------------------------
// Launch
// ---------------------------------------------------------------------------
extern "C" void kernel_launch(void* const* d_in, const int* in_sizes, int n_in,
                              void* d_out, int out_size)
{
    (void)in_sizes; (void)n_in; (void)out_size;
    const float* x    = (const float*)d_in[0];
    const int*   mask = (const int*)  d_in[1];
    const float* Wq   = (const float*)d_in[2];
    const float* bq   = (const float*)d_in[3];
    const float* Wk   = (const float*)d_in[4];
    const float* bk   = (const float*)d_in[5];
    const float* Wv   = (const float*)d_in[6];
    const float* bv   = (const float*)d_in[7];
    const float* Wo   = (const float*)d_in[8];
    const float* bo   = (const float*)d_in[9];
    const float* ln1g = (const float*)d_in[10];
    const float* ln1b = (const float*)d_in[11];
    const float* W1   = (const float*)d_in[12];
    const float* b1   = (const float*)d_in[13];
    const float* W2   = (const float*)d_in[14];
    const float* b2   = (const float*)d_in[15];
    const float* ln2g = (const float*)d_in[16];
    const float* ln2b = (const float*)d_in[17];
    float* out = (float*)d_out;

    __half *xh, *qkvh, *ctxh, *h1h, *ffh;
    __half *wqkv, *wo, *w1, *w2;
    float *t1, *h1, *t2, *bqkv;
    cudaGetSymbolAddress((void**)&xh, g_xh);
    cudaGetSymbolAddress((void**)&qkvh, g_qkvh);
    cudaGetSymbolAddress((void**)&ctxh, g_ctxh);
    cudaGetSymbolAddress((void**)&h1h, g_h1h);
    cudaGetSymbolAddress((void**)&ffh, g_ffh);
    cudaGetSymbolAddress((void**)&wqkv, g_wqkv);
    cudaGetSymbolAddress((void**)&wo, g_wo);
    cudaGetSymbolAddress((void**)&w1, g_w1);
    cudaGetSymbolAddress((void**)&w2, g_w2);
    cudaGetSymbolAddress((void**)&t1, g_t1);
    cudaGetSymbolAddress((void**)&h1, g_h1);
    cudaGetSymbolAddress((void**)&t2, g_t2);
    cudaGetSymbolAddress((void**)&bqkv, g_bqkv);

    constexpr int SM128 = (128 + 128) * ROWB * NSTAGE;   // MT=4
    constexpr int SM64  = (64 + 128) * ROWB * NSTAGE;    // MT=2

    cudaFuncSetAttribute(attn_kernel,
                         cudaFuncAttributeMaxDynamicSharedMemorySize, ATT_SMEM);
    cudaFuncSetAttribute(tc_gemm<0, 4>,
                         cudaFuncAttributeMaxDynamicSharedMemorySize, SM128);
    cudaFuncSetAttribute(tc_gemm<1, 4>,
                         cudaFuncAttributeMaxDynamicSharedMemorySize, SM128);
    cudaFuncSetAttribute(tc_gemm<2, 2>,
                         cudaFuncAttributeMaxDynamicSharedMemorySize, SM64);

    const dim3 tb(32, 8);

    trans_half4_kernel<<<dim3(HH / 32, HH / 32, 4), tb>>>(
        Wq, Wk, Wv, Wo,
        wqkv, wqkv + HH * HH, wqkv + 2 * HH * HH, wo);
    trans_half_kernel<<<dim3(FFF / 32, HH / 32),  tb>>>(W1, w1, HH, FFF);
    trans_half_kernel<<<dim3(HH / 32,  FFF / 32), tb>>>(W2, w2, FFF, HH);
    half4_kernel<<<(MM * HH / 4 + 255) / 256, 256>>>(x, xh, MM * HH / 4);
    concat3_kernel<<<3, 256>>>(bq, bk, bv, bqkv);

    // fused QKV -> fp16
    tc_gemm<0, 4><<<dim3(3 * HH / 128, MM / 128), 256, SM128>>>(
        xh, wqkv, bqkv, nullptr, nullptr, qkvh, HH, 3 * HH);

    // attention -> ctx fp16
    attn_kernel<<<dim3(SS / 64, BB * NHH), 128, ATT_SMEM>>>(
        qkvh, mask, ctxh);

    // t1 = ctx @ Wo + bo + x
    tc_gemm<2, 2><<<dim3(HH / 128, MM / 64), 256, SM64>>>(
        ctxh, wo, bo, x, t1, nullptr, HH, HH);
    ln_kernel<1><<<MM, 256>>>(t1, ln1g, ln1b, h1, h1h);

    // ff = gelu(h1 @ W1 + b1) -> fp16
    tc_gemm<1, 4><<<dim3(FFF / 128, MM / 128), 256, SM128>>>(
        h1h, w1, b1, nullptr, nullptr, ffh, HH, FFF);

    // t2 = ff @ W2 + b2 + h1
    tc_gemm<2, 2><<<dim3(HH / 128, MM / 64), 256, SM64>>>(
        ffh, w2, b2, h1, t2, nullptr, FFF, HH);
    ln_kernel<0><<<MM, 256>>>(t2, ln2g, ln2b, out, nullptr);
}

// round 10
// speedup vs baseline: 7.1603x; 1.1488x over previous
#include <cuda_runtime.h>
#include <cuda_fp16.h>
#include <math.h>
#include <stdint.h>

#define BB   8
#define SS   512
#define HH   768
#define NHH  12
#define DHH  64
#define FFF  3072
#define MM   (BB * SS)
#define LN_EPS 1e-3f

// ---------------------------------------------------------------------------
// Scratch
// ---------------------------------------------------------------------------
__device__ __align__(16) __half g_xh  [MM * HH];
__device__ __align__(16) __half g_qkvh[MM * 3 * HH];
__device__ __align__(16) __half g_ctxh[MM * HH];
__device__ __align__(16) float g_t1 [MM * HH];
__device__ __align__(16) float g_h1 [MM * HH];
__device__ __align__(16) __half g_h1h[MM * HH];
__device__ __align__(16) __half g_ffh[MM * FFF];
__device__ __align__(16) float g_t2 [MM * HH];
__device__ __align__(16) __half g_wqkv[3 * HH * HH];
__device__ __align__(16) float g_bqkv[3 * HH];
__device__ __align__(16) __half g_wo [HH * HH];
__device__ __align__(16) __half g_w1 [FFF * HH];
__device__ __align__(16) __half g_w2 [HH * FFF];

// ---------------------------------------------------------------------------
// PTX wrappers
// ---------------------------------------------------------------------------
__device__ __forceinline__ uint32_t smem_u32(const void* p) {
    uint32_t a;
    asm("{ .reg .u64 t; cvta.to.shared.u64 t, %1; cvt.u32.u64 %0, t; }"
        : "=r"(a) : "l"(p));
    return a;
}
#define LDM4(R, ADDR) \
    asm volatile("ldmatrix.sync.aligned.m8n8.x4.shared.b16 {%0,%1,%2,%3}, [%4];" \
        : "=r"((R)[0]), "=r"((R)[1]), "=r"((R)[2]), "=r"((R)[3]) : "r"(ADDR))
#define LDM4T(R, ADDR) \
    asm volatile("ldmatrix.sync.aligned.m8n8.x4.trans.shared.b16 {%0,%1,%2,%3}, [%4];" \
        : "=r"((R)[0]), "=r"((R)[1]), "=r"((R)[2]), "=r"((R)[3]) : "r"(ADDR))
#define MMAF16(D, A, B0, B1) \
    asm volatile("mma.sync.aligned.m16n8k16.row.col.f32.f16.f16.f32 " \
        "{%0,%1,%2,%3}, {%4,%5,%6,%7}, {%8,%9}, {%0,%1,%2,%3};" \
        : "+f"((D)[0]), "+f"((D)[1]), "+f"((D)[2]), "+f"((D)[3]) \
        : "r"((A)[0]), "r"((A)[1]), "r"((A)[2]), "r"((A)[3]), "r"(B0), "r"(B1))
#define CP16(SADDR, GPTR) \
    asm volatile("cp.async.cg.shared.global [%0], [%1], 16;" \
        :: "r"(SADDR), "l"(GPTR))
#define CP_COMMIT() asm volatile("cp.async.commit_group;" ::: "memory")
#define CP_WAIT(N)  asm volatile("cp.async.wait_group %0;" :: "n"(N) : "memory")

__device__ __forceinline__ float gelu_f(float x) {
    return 0.5f * x * (1.0f + erff(x * 0.70710678118654752f));
}

// ---------------------------------------------------------------------------
// Fused prep kernel: 4x HxH transpose, W1^T, W2^T, x->fp16, bias concat.
// One launch, flat blockIdx dispatch.
//   [0,2304)      : Wq/Wk/Wv/Wo transpose+convert (576 tiles each)
//   [2304,4608)   : W1 [768,3072] -> w1 [3072][768]  (96 x 24 tiles)
//   [4608,6912)   : W2 [3072,768] -> w2 [768][3072]  (24 x 96 tiles)
//   [6912,9984)   : x -> fp16 (3072 blocks, float4)
//   [9984]        : bias concat
// ---------------------------------------------------------------------------
#define PREP_BLOCKS 9985

__global__ void __launch_bounds__(256) prep_kernel(
    const float* __restrict__ Wq, const float* __restrict__ Wk,
    const float* __restrict__ Wv, const float* __restrict__ Wo,
    const float* __restrict__ W1, const float* __restrict__ W2,
    const float* __restrict__ x,
    const float* __restrict__ bq, const float* __restrict__ bk,
    const float* __restrict__ bv,
    __half* __restrict__ wqkv, __half* __restrict__ wo,
    __half* __restrict__ w1, __half* __restrict__ w2,
    __half* __restrict__ xh, float* __restrict__ bqkv)
{
    __shared__ float tile[32][33];
    const int id = blockIdx.x;
    const int t  = threadIdx.x;
    const int tx = t & 31, ty = t >> 5;

    const float* in = nullptr;
    __half* out = nullptr;
    int K = 0, N = 0, bx = 0, by = 0;

    if (id < 2304) {
        const int z = id / 576, within = id % 576;
        in  = (z == 0) ? Wq : (z == 1) ? Wk : (z == 2) ? Wv : Wo;
        out = (z < 3) ? (wqkv + z * HH * HH) : wo;
        K = HH; N = HH; bx = within % 24; by = within / 24;
    } else if (id < 4608) {
        const int within = id - 2304;
        in = W1; out = w1; K = HH; N = FFF;
        bx = within % 96; by = within / 96;
    } else if (id < 6912) {
        const int within = id - 4608;
        in = W2; out = w2; K = FFF; N = HH;
        bx = within % 24; by = within / 24;
    } else if (id < 9984) {
        const int i = (id - 6912) * 256 + t;
        const float4 v = *(const float4*)(x + (size_t)i * 4);
        __half2 h0 = __floats2half2_rn(v.x, v.y);
        __half2 h1 = __floats2half2_rn(v.z, v.w);
        uint2 u; u.x = *(uint32_t*)&h0; u.y = *(uint32_t*)&h1;
        *(uint2*)(xh + (size_t)i * 4) = u;
        return;
    } else {
        for (int i = t; i < HH; i += 256) {
            bqkv[i] = bq[i]; bqkv[HH + i] = bk[i]; bqkv[2 * HH + i] = bv[i];
        }
        return;
    }

    const int n0 = bx * 32, k0 = by * 32;
#pragma unroll
    for (int j = 0; j < 32; j += 8)
        tile[ty + j][tx] = in[(size_t)(k0 + ty + j) * N + n0 + tx];
    __syncthreads();
#pragma unroll
    for (int j = 0; j < 32; j += 8)
        out[(size_t)(n0 + ty + j) * K + k0 + tx] = __float2half_rn(tile[tx][ty + j]);
}

// ---------------------------------------------------------------------------
// GEMM: C[M,Ntot] = A[M,K] @ W[Ntot,K]^T; pure fp16, KC=64, 2-stage cp.async.
//   EPI 0: bias -> fp16; 1: bias+GELU -> fp16; 2: bias+resid -> fp32
// ---------------------------------------------------------------------------
#define KC 64
#define ROWB 144
#define NSTAGE 2

template <int EPI, int MT>
__global__ void __launch_bounds__(256) tc_gemm(
    const __half* __restrict__ Ahi,
    const __half* __restrict__ Whi,
    const float* __restrict__ bias, const float* __restrict__ resid,
    float* __restrict__ C, __half* __restrict__ Chi,
    int K, int Ntot)
{
    constexpr int BM = MT * 32;
    constexpr int AMATB = BM * ROWB;
    constexpr int BMATB = 128 * ROWB;
    constexpr int STAGEB = AMATB + BMATB;
    constexpr int ACH = BM * 8;                 // 16B chunks for A (128B rows)
    constexpr int NCHK = (ACH + 1024) / 256;

    extern __shared__ char sm[];
    const uint32_t sb = smem_u32(sm);

    const int t    = threadIdx.x;
    const int wid  = t >> 5, lane = t & 31;
    const int wm   = wid >> 2;
    const int wn   = wid & 3;
    const int bn   = blockIdx.x, bm = blockIdx.y;
    const int rbase = bm * BM, cbase = bn * 128;
    const int nch  = K / KC;

    auto issue = [&](int ci) {
        const int s = ci & 1;
        const uint32_t st = sb + s * STAGEB;
        const int kt = ci * KC;
#pragma unroll
        for (int j = 0; j < NCHK; j++) {
            int id = t + j * 256;
            if (id < ACH) {
                const int r = id >> 3, c = id & 7;
                CP16(st + r * ROWB + c * 16,
                     Ahi + (size_t)(rbase + r) * K + kt + c * 8);
            } else {
                id -= ACH;
                const int r = id >> 3, c = id & 7;
                CP16(st + AMATB + r * ROWB + c * 16,
                     Whi + (size_t)(cbase + r) * K + kt + c * 8);
            }
        }
    };

    float acc[MT][4][4];
#pragma unroll
    for (int i = 0; i < MT; i++)
#pragma unroll
        for (int j = 0; j < 4; j++)
#pragma unroll
            for (int q = 0; q < 4; q++) acc[i][j][q] = 0.f;

    const uint32_t a_off = (uint32_t)((wm * (MT * 16) + (lane & 15)) * ROWB
                                      + ((lane >> 4) << 4));
    const uint32_t b_off = (uint32_t)((wn * 32 + ((lane & 7) | ((lane & 16) >> 1))) * ROWB
                                      + (((lane >> 3) & 1) << 4));

    issue(0); CP_COMMIT();

    for (int ci = 0; ci < nch; ci++) {
        if (ci + 1 < nch) { issue(ci + 1); CP_COMMIT(); CP_WAIT(1); }
        else              { CP_WAIT(0); }
        __syncthreads();

        const uint32_t sA  = sb + (ci & 1) * STAGEB;
        const uint32_t sBh = sA + AMATB;
#pragma unroll
        for (int ks = 0; ks < 4; ks++) {
            const uint32_t ko = ks * 32;
            uint32_t AH[MT][4], BH[2][4];
#pragma unroll
            for (int mt = 0; mt < MT; mt++)
                LDM4(AH[mt], sA + a_off + mt * (16 * ROWB) + ko);
#pragma unroll
            for (int n2 = 0; n2 < 2; n2++)
                LDM4(BH[n2], sBh + b_off + n2 * (16 * ROWB) + ko);
#pragma unroll
            for (int mt = 0; mt < MT; mt++) {
#pragma unroll
                for (int nt = 0; nt < 4; nt++) {
                    const uint32_t b0 = BH[nt >> 1][(nt & 1) * 2];
                    const uint32_t b1 = BH[nt >> 1][(nt & 1) * 2 + 1];
                    MMAF16(acc[mt][nt], AH[mt], b0, b1);
                }
            }
        }
        __syncthreads();
    }

    const int mrow0 = rbase + wm * (MT * 16) + (lane >> 2);
    const int ncol0 = cbase + wn * 32 + (lane & 3) * 2;
#pragma unroll
    for (int mt = 0; mt < MT; mt++) {
#pragma unroll
        for (int half = 0; half < 2; half++) {
            const int m = mrow0 + mt * 16 + half * 8;
            const size_t rowoff = (size_t)m * Ntot;
#pragma unroll
            for (int nt = 0; nt < 4; nt++) {
                const int n = ncol0 + nt * 8;
                float v0 = acc[mt][nt][half * 2 + 0];
                float v1 = acc[mt][nt][half * 2 + 1];
                const float2 bv = *(const float2*)(bias + n);
                v0 += bv.x; v1 += bv.y;
                if (EPI == 2) {
                    const float2 rv = *(const float2*)(resid + rowoff + n);
                    v0 += rv.x; v1 += rv.y;
                    *(float2*)(C + rowoff + n) = make_float2(v0, v1);
                } else {
                    if (EPI == 1) { v0 = gelu_f(v0); v1 = gelu_f(v1); }
                    __half2 hh = __floats2half2_rn(v0, v1);
                    *(__half2*)(Chi + rowoff + n) = hh;
                }
            }
        }
    }
}

// ---------------------------------------------------------------------------
// Tensor-core flash attention, fp16, shift-free softmax (logits bounded).
// grid (8, 96), 128 threads (4 warps). Warp w: q rows [w*16, w*16+16).
// ---------------------------------------------------------------------------
#define AROWB 144
#define AMATB_A (64 * AROWB)
#define ASM_QH   0
#define ASM_MASK AMATB_A
#define ASM_KV   (AMATB_A + 2048)
#define ASTAGEB  (2 * AMATB_A)
#define ATT_SMEM (ASM_KV + 2 * ASTAGEB)

__global__ void __launch_bounds__(128) attn_kernel(
    const __half* __restrict__ QKVh,
    const int* __restrict__ mask,
    __half* __restrict__ Ch)
{
    extern __shared__ char sm[];
    const uint32_t sb = smem_u32(sm);

    const int qt = blockIdx.x;
    const int bh = blockIdx.y;
    const int b  = bh / NHH;
    const int h  = bh % NHH;
    const int t  = threadIdx.x;
    const int w  = t >> 5, lane = t & 31;

    const int ST = 3 * HH;
    const size_t rowbase = (size_t)b * SS;
    const int qcol = h * DHH, kcol = HH + h * DHH, vcol = 2 * HH + h * DHH;

#pragma unroll
    for (int j = 0; j < 4; j++) {
        const int idx = t + j * 128;
        const int r = idx >> 3, c = idx & 7;
        const size_t g = (rowbase + qt * 64 + r) * ST + qcol + c * 8;
        CP16(sb + r * AROWB + c * 16, QKVh + g);
    }
    {
        float* am = (float*)(sm + ASM_MASK);
#pragma unroll
        for (int j = 0; j < 4; j++) {
            const int i = t + j * 128;
            am[i] = (1.0f - (float)mask[b * SS + i]) * -10000.0f;
        }
    }
    CP_COMMIT();

    auto issueKV = [&](int kt, int s) {
        const uint32_t st = sb + ASM_KV + s * ASTAGEB;
#pragma unroll
        for (int j = 0; j < 8; j++) {
            const int idx = t + j * 128;
            const int mat = idx >> 9;            // 0 Kh, 1 Vh
            const int rem = idx & 511;
            const int r = rem >> 3, c = rem & 7;
            const int col = mat ? vcol : kcol;
            const size_t g = (rowbase + kt * 64 + r) * ST + col + c * 8;
            CP16(st + mat * AMATB_A + r * AROWB + c * 16, QKVh + g);
        }
    };
    issueKV(0, 0); CP_COMMIT();

    float l0 = 0.f, l1 = 0.f;
    float oacc[8][4];
#pragma unroll
    for (int i = 0; i < 8; i++)
#pragma unroll
        for (int j = 0; j < 4; j++) oacc[i][j] = 0.f;

    const uint32_t a_off = (uint32_t)((w * 16 + (lane & 15)) * AROWB + ((lane >> 4) << 4));
    const uint32_t b_row = (uint32_t)(((lane & 7) | ((lane & 16) >> 1)) * AROWB
                                      + (((lane >> 3) & 1) << 4));
    const uint32_t v_row = (uint32_t)((lane & 15) * AROWB + ((lane >> 4) << 4));
    const float* am = (const float*)(sm + ASM_MASK);

    for (int kt = 0; kt < SS / 64; kt++) {
        const int s = kt & 1;
        if (kt + 1 < SS / 64) { issueKV(kt + 1, s ^ 1); CP_COMMIT(); CP_WAIT(1); }
        else                  { CP_WAIT(0); }
        __syncthreads();

        const uint32_t sK = sb + ASM_KV + s * ASTAGEB;
        const uint32_t sV = sK + AMATB_A;

        float sacc[8][4];
#pragma unroll
        for (int i = 0; i < 8; i++)
#pragma unroll
            for (int j = 0; j < 4; j++) sacc[i][j] = 0.f;

#pragma unroll
        for (int ks = 0; ks < 4; ks++) {
            const uint32_t ko = ks * 32;
            uint32_t qh[4];
            LDM4(qh, sb + ASM_QH + a_off + ko);
#pragma unroll
            for (int n2 = 0; n2 < 4; n2++) {
                uint32_t kh[4];
                LDM4(kh, sK + b_row + n2 * (16 * AROWB) + ko);
                MMAF16(sacc[n2 * 2],     qh, kh[0], kh[1]);
                MMAF16(sacc[n2 * 2 + 1], qh, kh[2], kh[3]);
            }
        }

        // shift-free softmax accumulation (logits bounded; mask -> exp underflow 0)
        const int colbase = kt * 64 + (lane & 3) * 2;
        float ps0 = 0.f, ps1 = 0.f;
#pragma unroll
        for (int nt = 0; nt < 8; nt++) {
            const float a0 = am[colbase + nt * 8];
            const float a1 = am[colbase + nt * 8 + 1];
            sacc[nt][0] = __expf(fmaf(sacc[nt][0], 0.125f, a0));
            sacc[nt][1] = __expf(fmaf(sacc[nt][1], 0.125f, a1));
            sacc[nt][2] = __expf(fmaf(sacc[nt][2], 0.125f, a0));
            sacc[nt][3] = __expf(fmaf(sacc[nt][3], 0.125f, a1));
            ps0 += sacc[nt][0] + sacc[nt][1];
            ps1 += sacc[nt][2] + sacc[nt][3];
        }
        l0 += ps0; l1 += ps1;

#pragma unroll
        for (int ks = 0; ks < 4; ks++) {
            uint32_t ah[4];
#pragma unroll
            for (int pos = 0; pos < 4; pos++) {
                const int nt = 2 * ks + (pos >> 1);
                const int jb = (pos & 1) * 2;
                __half2 hh = __floats2half2_rn(sacc[nt][jb], sacc[nt][jb + 1]);
                ah[pos] = *(uint32_t*)&hh;
            }
#pragma unroll
            for (int dp = 0; dp < 4; dp++) {
                uint32_t vh[4];
                LDM4T(vh, sV + ks * (16 * AROWB) + v_row + dp * 32);
                MMAF16(oacc[dp * 2],     ah, vh[0], vh[1]);
                MMAF16(oacc[dp * 2 + 1], ah, vh[2], vh[3]);
            }
        }
        __syncthreads();
    }

    l0 += __shfl_xor_sync(0xffffffffu, l0, 1);
    l0 += __shfl_xor_sync(0xffffffffu, l0, 2);
    l1 += __shfl_xor_sync(0xffffffffu, l1, 1);
    l1 += __shfl_xor_sync(0xffffffffu, l1, 2);
    const float inv0 = 1.0f / l0, inv1 = 1.0f / l1;

    const size_t row0 = (size_t)(b * SS + qt * 64 + w * 16 + (lane >> 2));
    const size_t row1 = row0 + 8;
    const int ocol = h * DHH + (lane & 3) * 2;
#pragma unroll
    for (int nt = 0; nt < 8; nt++) {
        const int n = ocol + nt * 8;
        __half2 h0 = __floats2half2_rn(oacc[nt][0] * inv0, oacc[nt][1] * inv0);
        __half2 h1 = __floats2half2_rn(oacc[nt][2] * inv1, oacc[nt][3] * inv1);
        *(__half2*)(Ch + row0 * HH + n) = h0;
        *(__half2*)(Ch + row1 * HH + n) = h1;
    }
}

// ---------------------------------------------------------------------------
// Row-wise LayerNorm; optional fp16 side output
// ---------------------------------------------------------------------------
template <int SPLIT>
__global__ void __launch_bounds__(256) ln_kernel(
    const float* __restrict__ X, const float* __restrict__ gg,
    const float* __restrict__ bb, float* __restrict__ Y,
    __half* __restrict__ Yh)
{
    const int row = blockIdx.x;
    const float* x = X + (size_t)row * HH;
    const int c = threadIdx.x;

    const float v0 = x[c];
    const float v1 = x[c + 256];
    const float v2 = x[c + 512];
    float s  = v0 + v1 + v2;
    float s2 = v0 * v0 + v1 * v1 + v2 * v2;

    __shared__ float sa[8], sb2[8];
    __shared__ float stats[2];
    const int lane = threadIdx.x & 31, w = threadIdx.x >> 5;
#pragma unroll
    for (int o = 16; o > 0; o >>= 1) {
        s  += __shfl_down_sync(0xffffffffu, s, o);
        s2 += __shfl_down_sync(0xffffffffu, s2, o);
    }
    if (lane == 0) { sa[w] = s; sb2[w] = s2; }
    __syncthreads();
    if (threadIdx.x == 0) {
        float ts = 0.f, ts2 = 0.f;
#pragma unroll
        for (int i = 0; i < 8; i++) { ts += sa[i]; ts2 += sb2[i]; }
        const float mu  = ts * (1.0f / HH);
        const float var = ts2 * (1.0f / HH) - mu * mu;
        stats[0] = mu;
        stats[1] = rsqrtf(var + LN_EPS);
    }
    __syncthreads();
    const float mu = stats[0], rstd = stats[1];
    const size_t ro = (size_t)row * HH;
#pragma unroll
    for (int j = 0; j < 3; j++) {
        const int cc = c + j * 256;
        const float vv = (j == 0 ? v0 : (j == 1 ? v1 : v2));
        const float y = (vv - mu) * rstd * gg[cc] + bb[cc];
        Y[ro + cc] = y;
        if (SPLIT) Yh[ro + cc] = __float2half_rn(y);
    }
}

// ---------------------------------------------------------------------------
// Launch
// ---------------------------------------------------------------------------
extern "C" void kernel_launch(void* const* d_in, const int* in_sizes, int n_in,
                              void* d_out, int out_size)
{
    (void)in_sizes; (void)n_in; (void)out_size;
    const float* x    = (const float*)d_in[0];
    const int*   mask = (const int*)  d_in[1];
    const float* Wq   = (const float*)d_in[2];
    const float* bq   = (const float*)d_in[3];
    const float* Wk   = (const float*)d_in[4];
    const float* bk   = (const float*)d_in[5];
    const float* Wv   = (const float*)d_in[6];
    const float* bv   = (const float*)d_in[7];
    const float* Wo   = (const float*)d_in[8];
    const float* bo   = (const float*)d_in[9];
    const float* ln1g = (const float*)d_in[10];
    const float* ln1b = (const float*)d_in[11];
    const float* W1   = (const float*)d_in[12];
    const float* b1   = (const float*)d_in[13];
    const float* W2   = (const float*)d_in[14];
    const float* b2   = (const float*)d_in[15];
    const float* ln2g = (const float*)d_in[16];
    const float* ln2b = (const float*)d_in[17];
    float* out = (float*)d_out;

    __half *xh, *qkvh, *ctxh, *h1h, *ffh;
    __half *wqkv, *wo, *w1, *w2;
    float *t1, *h1, *t2, *bqkv;
    cudaGetSymbolAddress((void**)&xh, g_xh);
    cudaGetSymbolAddress((void**)&qkvh, g_qkvh);
    cudaGetSymbolAddress((void**)&ctxh, g_ctxh);
    cudaGetSymbolAddress((void**)&h1h, g_h1h);
    cudaGetSymbolAddress((void**)&ffh, g_ffh);
    cudaGetSymbolAddress((void**)&wqkv, g_wqkv);
    cudaGetSymbolAddress((void**)&wo, g_wo);
    cudaGetSymbolAddress((void**)&w1, g_w1);
    cudaGetSymbolAddress((void**)&w2, g_w2);
    cudaGetSymbolAddress((void**)&t1, g_t1);
    cudaGetSymbolAddress((void**)&h1, g_h1);
    cudaGetSymbolAddress((void**)&t2, g_t2);
    cudaGetSymbolAddress((void**)&bqkv, g_bqkv);

    constexpr int SM128 = (128 + 128) * ROWB * NSTAGE;   // MT=4: 73728
    constexpr int SM64  = (64 + 128) * ROWB * NSTAGE;    // MT=2: 55296

    cudaFuncSetAttribute(attn_kernel,
                         cudaFuncAttributeMaxDynamicSharedMemorySize, ATT_SMEM);
    cudaFuncSetAttribute(tc_gemm<0, 4>,
                         cudaFuncAttributeMaxDynamicSharedMemorySize, SM128);
    cudaFuncSetAttribute(tc_gemm<1, 4>,
                         cudaFuncAttributeMaxDynamicSharedMemorySize, SM128);
    cudaFuncSetAttribute(tc_gemm<2, 2>,
                         cudaFuncAttributeMaxDynamicSharedMemorySize, SM64);

    // single fused prep launch
    prep_kernel<<<PREP_BLOCKS, 256>>>(Wq, Wk, Wv, Wo, W1, W2, x, bq, bk, bv,
                                      wqkv, wo, w1, w2, xh, bqkv);

    // fused QKV -> fp16
    tc_gemm<0, 4><<<dim3(3 * HH / 128, MM / 128), 256, SM128>>>(
        xh, wqkv, bqkv, nullptr, nullptr, qkvh, HH, 3 * HH);

    // attention -> ctx fp16
    attn_kernel<<<dim3(SS / 64, BB * NHH), 128, ATT_SMEM>>>(
        qkvh, mask, ctxh);

    // t1 = ctx @ Wo + bo + x
    tc_gemm<2, 2><<<dim3(HH / 128, MM / 64), 256, SM64>>>(
        ctxh, wo, bo, x, t1, nullptr, HH, HH);
    ln_kernel<1><<<MM, 256>>>(t1, ln1g, ln1b, h1, h1h);

    // ff = gelu(h1 @ W1 + b1) -> fp16
    tc_gemm<1, 4><<<dim3(FFF / 128, MM / 128), 256, SM128>>>(
        h1h, w1, b1, nullptr, nullptr, ffh, HH, FFF);

    // t2 = ff @ W2 + b2 + h1
    tc_gemm<2, 2><<<dim3(HH / 128, MM / 64), 256, SM64>>>(
        ffh, w2, b2, h1, t2, nullptr, FFF, HH);
    ln_kernel<0><<<MM, 256>>>(t2, ln2g, ln2b, out, nullptr);
}